// round 5
// baseline (speedup 1.0000x reference)
#include <cuda_runtime.h>
#include <math.h>

#define NTOK   512          // B*T = 8*64
#define NE     768          // n_embd
#define NH     8            // heads
#define HD     96           // head dim
#define DFF    3072
#define NEXP   8
#define NLAYER 12
#define NVOCAB 99
#define TT     64           // seq len

// ---------------- scratch (static device globals; no allocation) -------------
__device__ float g_x[NTOK * NE];
__device__ float g_q[NTOK * NE];
__device__ float g_k[NTOK * NE];
__device__ float g_v[NTOK * NE];
__device__ float g_o[NTOK * NE];
__device__ float g_y[NTOK * NE];
__device__ float g_h[(size_t)NEXP * NTOK * DFF];   // ~50 MB expert hidden
__device__ float g_yslot[2 * NTOK * NE];           // per-slot MoE outputs
__device__ float g_logits[NTOK * NEXP];
__device__ int   g_cnt[NEXP];
__device__ int   g_tok[NEXP * NTOK];
__device__ int   g_slot[NEXP * NTOK];
__device__ float g_pw[NEXP * NTOK];

// ---------------- embed ------------------------------------------------------
__global__ void embed_kernel(const int* __restrict__ idx,
                             const float* __restrict__ te,
                             const float* __restrict__ pe) {
    int t = blockIdx.x;
    int id = idx[t];
    int pp = t & (TT - 1);
    for (int c = threadIdx.x; c < NE; c += blockDim.x)
        g_x[t * NE + c] = te[id * NE + c] + pe[pp * NE + c];
}

// ---------------- generic 64x64 fp32 GEMM tile (C = A @ W^T) -----------------
// A: [mrows, lda] row-major (optionally row-gathered), W: [N, K] row-major.
// 256 threads, BK=16, 4x4 microtile per thread, float4 smem reads.
__device__ __forceinline__ void gemm_tile(
    const float* __restrict__ Abase, int lda,
    const int* __restrict__ rowmap, int mrows, int rowTile,
    const float* __restrict__ W, int nTile, int K,
    float (&acc)[16])
{
    __shared__ alignas(16) float As[16][68];
    __shared__ alignas(16) float Bs[16][68];

    const int tx = threadIdx.x;
    const int lr = tx >> 2;            // load row 0..63
    const int lk = (tx & 3) << 2;      // k offset {0,4,8,12}

    const int gr = rowTile * 64 + lr;
    const float* arow = nullptr;
    if (gr < mrows) {
        int src = rowmap ? rowmap[gr] : gr;
        arow = Abase + (size_t)src * lda;
    }
    const float* wrow = W + (size_t)(nTile * 64 + lr) * K;

    const int m0 = (tx >> 4) << 2;
    const int n0 = (tx & 15) << 2;

    float4 av = arow ? *(const float4*)(arow + lk) : make_float4(0.f, 0.f, 0.f, 0.f);
    float4 bv = *(const float4*)(wrow + lk);

    for (int kt = 0; kt < K; kt += 16) {
        __syncthreads();
        As[lk + 0][lr] = av.x; As[lk + 1][lr] = av.y;
        As[lk + 2][lr] = av.z; As[lk + 3][lr] = av.w;
        Bs[lk + 0][lr] = bv.x; Bs[lk + 1][lr] = bv.y;
        Bs[lk + 2][lr] = bv.z; Bs[lk + 3][lr] = bv.w;
        __syncthreads();
        if (kt + 16 < K) {   // prefetch next tile (hides LDG under FMA)
            av = arow ? *(const float4*)(arow + kt + 16 + lk)
                      : make_float4(0.f, 0.f, 0.f, 0.f);
            bv = *(const float4*)(wrow + kt + 16 + lk);
        }
#pragma unroll
        for (int k = 0; k < 16; k++) {
            const float4 a = *(const float4*)(&As[k][m0]);
            const float4 b = *(const float4*)(&Bs[k][n0]);
            acc[0]  += a.x * b.x; acc[1]  += a.x * b.y; acc[2]  += a.x * b.z; acc[3]  += a.x * b.w;
            acc[4]  += a.y * b.x; acc[5]  += a.y * b.y; acc[6]  += a.y * b.z; acc[7]  += a.y * b.w;
            acc[8]  += a.z * b.x; acc[9]  += a.z * b.y; acc[10] += a.z * b.z; acc[11] += a.z * b.w;
            acc[12] += a.w * b.x; acc[13] += a.w * b.y; acc[14] += a.w * b.z; acc[15] += a.w * b.w;
        }
    }
}

// ---------------- fused QKV: grid (12, 8, 3) ---------------------------------
__global__ __launch_bounds__(256) void qkv_kernel(
    const float* __restrict__ wq, const float* __restrict__ wk,
    const float* __restrict__ wv)
{
    const float* W = (blockIdx.z == 0) ? wq : (blockIdx.z == 1) ? wk : wv;
    float* out = (blockIdx.z == 0) ? g_q : (blockIdx.z == 1) ? g_k : g_v;
    float acc[16] = {0.f};
    gemm_tile(g_x, NE, nullptr, NTOK, blockIdx.y, W, blockIdx.x, NE, acc);
    const int m0 = blockIdx.y * 64 + ((threadIdx.x >> 4) << 2);
    const int n0 = blockIdx.x * 64 + ((threadIdx.x & 15) << 2);
#pragma unroll
    for (int i = 0; i < 4; i++)
#pragma unroll
        for (int j = 0; j < 4; j++)
            out[(m0 + i) * NE + n0 + j] = acc[i * 4 + j];
}

// ---------------- attention core: grid (B*H=64, 2), 256 thr, dyn smem --------
__global__ __launch_bounds__(256) void attn_kernel() {
    extern __shared__ float sm[];
    float* sq = sm;                 // 32*96
    float* sk = sq + 32 * HD;       // 64*96
    float* sv = sk + 64 * HD;       // 64*96
    float* ss = sv + 64 * HD;       // 32*64
    const int b = blockIdx.x >> 3, h = blockIdx.x & 7;
    const int t0 = blockIdx.y * 32;
    const int base = b * TT;
    const int tid = threadIdx.x;
    const int col0 = h * HD;

    for (int i = tid; i < 64 * HD; i += 256) {
        int t = i / HD, d = i - t * HD;
        sk[i] = g_k[(base + t) * NE + col0 + d];
        sv[i] = g_v[(base + t) * NE + col0 + d];
    }
    for (int i = tid; i < 32 * HD; i += 256) {
        int t = i / HD, d = i - t * HD;
        sq[i] = g_q[(base + t0 + t) * NE + col0 + d];
    }
    __syncthreads();

    const float scale = 0.10206207261596575f;  // 96^-0.5
    for (int e = tid; e < 32 * 64; e += 256) {
        int t = e >> 6, s = e & 63;
        float a = 0.f;
        if (s <= t0 + t) {
            const float* qp = sq + t * HD;
            const float* kp = sk + s * HD;
#pragma unroll 8
            for (int d = 0; d < HD; d++) a += qp[d] * kp[d];
            a *= scale;
        }
        ss[e] = a;
    }
    __syncthreads();

    if (tid < 32) {
        int lim = t0 + tid;
        float m = -1e30f;
        for (int s = 0; s <= lim; s++) m = fmaxf(m, ss[tid * 64 + s]);
        float sum = 0.f;
        for (int s = 0; s < 64; s++) {
            float v = (s <= lim) ? expf(ss[tid * 64 + s] - m) : 0.f;
            ss[tid * 64 + s] = v;
            sum += v;
        }
        float inv = 1.f / sum;
        for (int s = 0; s < 64; s++) ss[tid * 64 + s] *= inv;
    }
    __syncthreads();

    for (int i = tid; i < 32 * HD; i += 256) {
        int t = i / HD, d = i - t * HD;
        const float* ps = ss + t * 64;
        float a = 0.f;
#pragma unroll 8
        for (int s = 0; s < 64; s++) a += ps[s] * sv[s * HD + d];
        g_o[(base + t0 + t) * NE + col0 + d] = a;
    }
}

// ---------------- output projection: grid (12, 8) ----------------------------
__global__ __launch_bounds__(256) void proj_kernel(
    const float* __restrict__ wp, const float* __restrict__ bp)
{
    float acc[16] = {0.f};
    gemm_tile(g_o, NE, nullptr, NTOK, blockIdx.y, wp, blockIdx.x, NE, acc);
    const int m0 = blockIdx.y * 64 + ((threadIdx.x >> 4) << 2);
    const int n0 = blockIdx.x * 64 + ((threadIdx.x & 15) << 2);
#pragma unroll
    for (int i = 0; i < 4; i++)
#pragma unroll
        for (int j = 0; j < 4; j++)
            g_y[(m0 + i) * NE + n0 + j] = acc[i * 4 + j] + bp[n0 + j];
}

// ---------------- residual add + layernorm; mode: 0 none, 1 +g_y, 2 +yslots --
__global__ __launch_bounds__(256) void addln_kernel(
    const float* __restrict__ w, const float* __restrict__ bb, int mode)
{
    const int t = blockIdx.x, tid = threadIdx.x;
    float v[3];
    float s = 0.f, s2 = 0.f;
#pragma unroll
    for (int j = 0; j < 3; j++) {
        int c = tid + j * 256;
        float x = g_x[t * NE + c];
        if (mode == 1) x += g_y[t * NE + c];
        else if (mode == 2) x += g_yslot[t * NE + c] + g_yslot[NTOK * NE + t * NE + c];
        v[j] = x; s += x; s2 += x * x;
    }
#pragma unroll
    for (int o = 16; o; o >>= 1) {
        s  += __shfl_down_sync(0xffffffffu, s,  o);
        s2 += __shfl_down_sync(0xffffffffu, s2, o);
    }
    __shared__ float rs[8], rs2[8], smv[2];
    const int wp = tid >> 5, lane = tid & 31;
    if (lane == 0) { rs[wp] = s; rs2[wp] = s2; }
    __syncthreads();
    if (tid == 0) {
        float a = 0.f, b2 = 0.f;
#pragma unroll
        for (int i = 0; i < 8; i++) { a += rs[i]; b2 += rs2[i]; }
        float mean = a * (1.f / NE);
        float var = b2 * (1.f / NE) - mean * mean;
        smv[0] = mean;
        smv[1] = rsqrtf(var + 1e-5f);
    }
    __syncthreads();
    const float mean = smv[0], r = smv[1];
#pragma unroll
    for (int j = 0; j < 3; j++) {
        int c = tid + j * 256;
        g_x[t * NE + c] = (v[j] - mean) * r * w[c] + bb[c];
    }
}

// ---------------- MoE routing ------------------------------------------------
// A: gate logits. grid(512), block(256): warp w computes expert w for token blockIdx.x
__global__ __launch_bounds__(256) void route_a(
    const float* __restrict__ gw, const float* __restrict__ gb)
{
    const int tok = blockIdx.x;
    const int w = threadIdx.x >> 5, lane = threadIdx.x & 31;
    const float* xr = g_x + tok * NE;
    const float* gr = gw + w * NE;
    float a = 0.f;
    for (int c = lane; c < NE; c += 32) a += xr[c] * gr[c];
#pragma unroll
    for (int o = 16; o; o >>= 1) a += __shfl_down_sync(0xffffffffu, a, o);
    if (lane == 0) g_logits[tok * NEXP + w] = a + gb[w];
}

// B: top-2 + renorm + per-expert token lists. single block, 512 threads.
__global__ __launch_bounds__(512) void route_b() {
    __shared__ int scnt[NEXP];
    const int tid = threadIdx.x;
    if (tid < NEXP) scnt[tid] = 0;
    __syncthreads();

    float lg[NEXP];
    float m = -1e30f;
#pragma unroll
    for (int e = 0; e < NEXP; e++) { lg[e] = g_logits[tid * NEXP + e]; m = fmaxf(m, lg[e]); }
#pragma unroll
    for (int e = 0; e < NEXP; e++) lg[e] = expf(lg[e] - m);

    int i0 = 0;
#pragma unroll
    for (int e = 1; e < NEXP; e++) if (lg[e] > lg[i0]) i0 = e;
    int i1 = (i0 == 0) ? 1 : 0;
#pragma unroll
    for (int e = 0; e < NEXP; e++) if (e != i0 && lg[e] > lg[i1]) i1 = e;

    const float inv = 1.f / (lg[i0] + lg[i1]);
    const float p0 = lg[i0] * inv, p1 = lg[i1] * inv;

    int pos0 = atomicAdd(&scnt[i0], 1);
    g_tok[i0 * NTOK + pos0] = tid; g_slot[i0 * NTOK + pos0] = 0; g_pw[i0 * NTOK + pos0] = p0;
    int pos1 = atomicAdd(&scnt[i1], 1);
    g_tok[i1 * NTOK + pos1] = tid; g_slot[i1 * NTOK + pos1] = 1; g_pw[i1 * NTOK + pos1] = p1;

    __syncthreads();
    if (tid < NEXP) g_cnt[tid] = scnt[tid];
}

// ---------------- expert GEMM1: h = gelu(x_gather @ w1^T + b1) ----------------
// grid (48, 8, NEXP)
__global__ __launch_bounds__(256) void moe_g1(
    const float* __restrict__ w1l, const float* __restrict__ b1l)
{
    const int e = blockIdx.z;
    const int ne = g_cnt[e];
    if ((int)(blockIdx.y * 64) >= ne) return;
    float acc[16] = {0.f};
    gemm_tile(g_x, NE, g_tok + e * NTOK, ne, blockIdx.y,
              w1l + (size_t)e * DFF * NE, blockIdx.x, NE, acc);
    const int m0 = blockIdx.y * 64 + ((threadIdx.x >> 4) << 2);
    const int n0 = blockIdx.x * 64 + ((threadIdx.x & 15) << 2);
    float* hb = g_h + (size_t)e * NTOK * DFF;
    const float* bl = b1l + e * DFF;
#pragma unroll
    for (int i = 0; i < 4; i++) {
        int r = m0 + i;
        if (r < ne) {
#pragma unroll
            for (int j = 0; j < 4; j++) {
                int n = n0 + j;
                float v = acc[i * 4 + j] + bl[n];
                hb[(size_t)r * DFF + n] = 0.5f * v * (1.f + erff(v * 0.70710678118654752f));
            }
        }
    }
}

// ---------------- expert GEMM2: y_slot = p * (h @ w2^T + b2), scatter --------
// grid (12, 8, NEXP)
__global__ __launch_bounds__(256) void moe_g2(
    const float* __restrict__ w2l, const float* __restrict__ b2l)
{
    const int e = blockIdx.z;
    const int ne = g_cnt[e];
    if ((int)(blockIdx.y * 64) >= ne) return;
    float acc[16] = {0.f};
    gemm_tile(g_h + (size_t)e * NTOK * DFF, DFF, nullptr, ne, blockIdx.y,
              w2l + (size_t)e * NE * DFF, blockIdx.x, DFF, acc);
    const int m0 = blockIdx.y * 64 + ((threadIdx.x >> 4) << 2);
    const int n0 = blockIdx.x * 64 + ((threadIdx.x & 15) << 2);
    const float* bl = b2l + e * NE;
#pragma unroll
    for (int i = 0; i < 4; i++) {
        int r = m0 + i;
        if (r < ne) {
            int tok = g_tok[e * NTOK + r];
            int sl  = g_slot[e * NTOK + r];
            float p = g_pw[e * NTOK + r];
            float* dst = g_yslot + (size_t)sl * NTOK * NE + (size_t)tok * NE;
#pragma unroll
            for (int j = 0; j < 4; j++) {
                int n = n0 + j;
                dst[n] = p * (acc[i * 4 + j] + bl[n]);
            }
        }
    }
}

// ---------------- LM head: logits = x @ lm_w^T + lm_b ------------------------
__global__ __launch_bounds__(128) void lm_kernel(
    const float* __restrict__ lw, const float* __restrict__ lb,
    float* __restrict__ out)
{
    __shared__ float xr[NE];
    const int t = blockIdx.x, tid = threadIdx.x;
    for (int c = tid; c < NE; c += 128) xr[c] = g_x[t * NE + c];
    __syncthreads();
    if (tid < NVOCAB) {
        const float* wr = lw + (size_t)tid * NE;
        float a = lb[tid];
#pragma unroll 8
        for (int c = 0; c < NE; c++) a += xr[c] * wr[c];
        out[t * NVOCAB + tid] = a;
    }
}

// ---------------- launch -----------------------------------------------------
extern "C" void kernel_launch(void* const* d_in, const int* in_sizes, int n_in,
                              void* d_out, int out_size) {
    (void)in_sizes; (void)n_in; (void)out_size;
    const int*   idx     = (const int*)  d_in[0];
    const float* tok_emb = (const float*)d_in[1];
    const float* pos_emb = (const float*)d_in[2];
    const float* wq      = (const float*)d_in[3];
    const float* wk      = (const float*)d_in[4];
    const float* wv      = (const float*)d_in[5];
    const float* wproj   = (const float*)d_in[6];
    const float* bproj   = (const float*)d_in[7];
    const float* gate_w  = (const float*)d_in[8];
    const float* gate_b  = (const float*)d_in[9];
    const float* w1      = (const float*)d_in[10];
    const float* b1      = (const float*)d_in[11];
    const float* w2      = (const float*)d_in[12];
    const float* b2      = (const float*)d_in[13];
    const float* ln1_w   = (const float*)d_in[14];
    const float* ln1_b   = (const float*)d_in[15];
    const float* ln2_w   = (const float*)d_in[16];
    const float* ln2_b   = (const float*)d_in[17];
    const float* lnf_w   = (const float*)d_in[18];
    const float* lnf_b   = (const float*)d_in[19];
    const float* lm_w    = (const float*)d_in[20];
    const float* lm_b    = (const float*)d_in[21];
    float* out = (float*)d_out;

    const int ATTN_SMEM = (32 * HD + 64 * HD + 64 * HD + 32 * 64) * 4;  // 69632 B
    cudaFuncSetAttribute(attn_kernel, cudaFuncAttributeMaxDynamicSharedMemorySize, ATTN_SMEM);

    embed_kernel<<<NTOK, 256>>>(idx, tok_emb, pos_emb);

    for (int l = 0; l < NLAYER; l++) {
        const size_t offW  = (size_t)l * NH * HD * NE;      // 589824
        const size_t offM1 = (size_t)l * NEXP * DFF * NE;   // w1/w2 per layer
        qkv_kernel<<<dim3(12, 8, 3), 256>>>(wq + offW, wk + offW, wv + offW);
        attn_kernel<<<dim3(64, 2), 256, ATTN_SMEM>>>();
        proj_kernel<<<dim3(12, 8), 256>>>(wproj + offW, bproj + (size_t)l * NE);
        addln_kernel<<<NTOK, 256>>>(ln1_w + (size_t)l * NE, ln1_b + (size_t)l * NE, 1);

        route_a<<<NTOK, 256>>>(gate_w + (size_t)l * NEXP * NE, gate_b + (size_t)l * NEXP);
        route_b<<<1, 512>>>();
        moe_g1<<<dim3(48, 8, NEXP), 256>>>(w1 + offM1, b1 + (size_t)l * NEXP * DFF);
        moe_g2<<<dim3(12, 8, NEXP), 256>>>(w2 + offM1, b2 + (size_t)l * NEXP * NE);
        addln_kernel<<<NTOK, 256>>>(ln2_w + (size_t)l * NE, ln2_b + (size_t)l * NE, 2);
    }

    addln_kernel<<<NTOK, 256>>>(lnf_w, lnf_b, 0);
    lm_kernel<<<NTOK, 128>>>(lm_w, lm_b, out);
}

// round 6
// speedup vs baseline: 1.6218x; 1.6218x over previous
#include <cuda_runtime.h>
#include <cuda_bf16.h>
#include <math.h>

#define NTOK   512          // B*T = 8*64
#define NE     768          // n_embd
#define NH     8            // heads
#define HD     96           // head dim
#define DFF    3072
#define NEXP   8
#define NLAYER 12
#define NVOCAB 99
#define TT     64           // seq len

// ---------------- scratch (static device globals; no allocation) -------------
__device__ float g_x[NTOK * NE];
__device__ float g_q[NTOK * NE];
__device__ float g_k[NTOK * NE];
__device__ float g_v[NTOK * NE];
__device__ float g_o[NTOK * NE];
__device__ float g_y[NTOK * NE];
__device__ float g_h[(size_t)NEXP * NTOK * DFF];   // ~50 MB expert hidden
__device__ float g_yslot[2 * NTOK * NE];           // per-slot MoE outputs
__device__ float g_logits[NTOK * NEXP];
__device__ int   g_cnt[NEXP];
__device__ int   g_tok[NEXP * NTOK];
__device__ int   g_slot[NEXP * NTOK];
__device__ float g_pw[NEXP * NTOK];

// ---------------- small helpers ----------------------------------------------
__device__ __forceinline__ unsigned su32(const void* p) {
    return (unsigned)__cvta_generic_to_shared(p);
}

__device__ __forceinline__ void ldsm4(unsigned* r, unsigned addr) {
    asm volatile("ldmatrix.sync.aligned.m8n8.x4.shared.b16 {%0,%1,%2,%3}, [%4];"
        : "=r"(r[0]), "=r"(r[1]), "=r"(r[2]), "=r"(r[3]) : "r"(addr));
}

__device__ __forceinline__ void mma16816(float* c, const unsigned* a, const unsigned* b) {
    asm volatile(
        "mma.sync.aligned.m16n8k16.row.col.f32.bf16.bf16.f32 "
        "{%0,%1,%2,%3}, {%4,%5,%6,%7}, {%8,%9}, {%0,%1,%2,%3};\n"
        : "+f"(c[0]), "+f"(c[1]), "+f"(c[2]), "+f"(c[3])
        : "r"(a[0]), "r"(a[1]), "r"(a[2]), "r"(a[3]), "r"(b[0]), "r"(b[1]));
}

// split 2 fp32 into packed bf16 hi pair + bf16 lo pair (lo = x - float(hi))
__device__ __forceinline__ void split2(float x0, float x1, unsigned& hi, unsigned& lo) {
    __nv_bfloat162 h = __floats2bfloat162_rn(x0, x1);
    float2 hf = __bfloat1622float2(h);
    __nv_bfloat162 l = __floats2bfloat162_rn(x0 - hf.x, x1 - hf.y);
    hi = *reinterpret_cast<unsigned*>(&h);
    lo = *reinterpret_cast<unsigned*>(&l);
}

// ---------------- tensor-core GEMM core: C = A @ W^T (fp32-in/out, bf16x3) ----
// Block tile 64(M) x 128(N), BK=16, 256 threads = 8 warps (2M x 4N),
// warp tile 32x32. A: [mrows, lda] fp32 row-major (optional row gather).
// W: [N, K] fp32 row-major (so W rows are K-major = col-major B => "row.col" mma).
__device__ __forceinline__ void mma_gemm_core(
    const float* __restrict__ Abase, int lda,
    const int* __restrict__ rowmap, int mrows, int mTile,
    const float* __restrict__ W, int nTile, int K,
    float (&acc)[2][4][4])
{
    // padded row stride 24 bf16 = 48 B => conflict-free LDSM, 16B-aligned rows
    __shared__ __align__(16) __nv_bfloat16 As[2][64][24];
    __shared__ __align__(16) __nv_bfloat16 Bs[2][128][24];

    const int tx = threadIdx.x;
    const int warp = tx >> 5, lane = tx & 31;
    const int wm = (warp >> 2) * 32;   // warp M offset in block tile
    const int wn = (warp & 3) * 32;    // warp N offset

    // --- staging assignments ---
    const int ar = tx >> 2;            // A stage row 0..63
    const int ak = (tx & 3) * 4;       // A stage k offset {0,4,8,12}
    const int grow = mTile * 64 + ar;
    const float* aptr = nullptr;
    if (grow < mrows) {
        int src = rowmap ? rowmap[grow] : grow;
        aptr = Abase + (size_t)src * lda + ak;
    }
    const int br = tx >> 1;            // B stage row 0..127
    const int bk = (tx & 1) * 8;       // k offset {0,8}
    const float* bptr = W + (size_t)(nTile * 128 + br) * K + bk;

    // --- ldmatrix lane addresses (fixed across k loop; single-buffer smem) ---
    unsigned aAddrHi = su32(&As[0][wm + (lane & 15)][(lane >> 4) * 8]);
    unsigned aAddrLo = su32(&As[1][wm + (lane & 15)][(lane >> 4) * 8]);
    const int bn  = wn + (lane & 7) + ((lane >> 1) & 8);
    const int bko = lane & 8;
    unsigned bAddrHi = su32(&Bs[0][bn][bko]);
    unsigned bAddrLo = su32(&Bs[1][bn][bko]);

    // --- prefetch first k tile ---
    float4 av  = aptr ? *(const float4*)aptr : make_float4(0.f, 0.f, 0.f, 0.f);
    float4 bv0 = *(const float4*)bptr;
    float4 bv1 = *(const float4*)(bptr + 4);

    for (int kt = 0; kt < K; kt += 16) {
        __syncthreads();
        {   // stage A (hi/lo split)
            unsigned h0, l0, h1, l1;
            split2(av.x, av.y, h0, l0);
            split2(av.z, av.w, h1, l1);
            *(uint2*)&As[0][ar][ak] = make_uint2(h0, h1);
            *(uint2*)&As[1][ar][ak] = make_uint2(l0, l1);
        }
        {   // stage B
            unsigned h0, l0, h1, l1, h2, l2, h3, l3;
            split2(bv0.x, bv0.y, h0, l0);
            split2(bv0.z, bv0.w, h1, l1);
            split2(bv1.x, bv1.y, h2, l2);
            split2(bv1.z, bv1.w, h3, l3);
            *(uint4*)&Bs[0][br][bk] = make_uint4(h0, h1, h2, h3);
            *(uint4*)&Bs[1][br][bk] = make_uint4(l0, l1, l2, l3);
        }
        __syncthreads();
        if (kt + 16 < K) {   // prefetch next tile under the MMA section
            av  = aptr ? *(const float4*)(aptr + kt + 16) : make_float4(0.f, 0.f, 0.f, 0.f);
            bv0 = *(const float4*)(bptr + kt + 16);
            bv1 = *(const float4*)(bptr + kt + 20);
        }

        unsigned Ah[2][4], Al[2][4], Bh[2][4], Bl[2][4];
        ldsm4(Ah[0], aAddrHi);  ldsm4(Ah[1], aAddrHi + 16 * 48);
        ldsm4(Al[0], aAddrLo);  ldsm4(Al[1], aAddrLo + 16 * 48);
        ldsm4(Bh[0], bAddrHi);  ldsm4(Bh[1], bAddrHi + 16 * 48);
        ldsm4(Bl[0], bAddrLo);  ldsm4(Bl[1], bAddrLo + 16 * 48);

#pragma unroll
        for (int i = 0; i < 2; i++)
#pragma unroll
            for (int j = 0; j < 4; j++) {
                const unsigned* bh = &Bh[j >> 1][(j & 1) * 2];
                const unsigned* bl = &Bl[j >> 1][(j & 1) * 2];
                mma16816(acc[i][j], Ah[i], bh);   // hi*hi
                mma16816(acc[i][j], Ah[i], bl);   // hi*lo
                mma16816(acc[i][j], Al[i], bh);   // lo*hi
            }
    }
}

// ---------------- fused QKV: grid (6, 8, 3) -----------------------------------
__global__ __launch_bounds__(256) void qkv_mma(
    const float* __restrict__ wq, const float* __restrict__ wk,
    const float* __restrict__ wv)
{
    const float* W = (blockIdx.z == 0) ? wq : (blockIdx.z == 1) ? wk : wv;
    float* out = (blockIdx.z == 0) ? g_q : (blockIdx.z == 1) ? g_k : g_v;
    float acc[2][4][4] = {};
    mma_gemm_core(g_x, NE, nullptr, NTOK, blockIdx.y, W, blockIdx.x, NE, acc);
    const int lane = threadIdx.x & 31, warp = threadIdx.x >> 5;
    const int m0 = blockIdx.y * 64 + (warp >> 2) * 32 + (lane >> 2);
    const int n0 = blockIdx.x * 128 + (warp & 3) * 32 + (lane & 3) * 2;
#pragma unroll
    for (int i = 0; i < 2; i++)
#pragma unroll
        for (int j = 0; j < 4; j++) {
            int m = m0 + i * 16, n = n0 + j * 8;
            *(float2*)&out[m * NE + n]       = make_float2(acc[i][j][0], acc[i][j][1]);
            *(float2*)&out[(m + 8) * NE + n] = make_float2(acc[i][j][2], acc[i][j][3]);
        }
}

// ---------------- output projection: grid (6, 8) -----------------------------
__global__ __launch_bounds__(256) void proj_mma(
    const float* __restrict__ wp, const float* __restrict__ bp)
{
    float acc[2][4][4] = {};
    mma_gemm_core(g_o, NE, nullptr, NTOK, blockIdx.y, wp, blockIdx.x, NE, acc);
    const int lane = threadIdx.x & 31, warp = threadIdx.x >> 5;
    const int m0 = blockIdx.y * 64 + (warp >> 2) * 32 + (lane >> 2);
    const int n0 = blockIdx.x * 128 + (warp & 3) * 32 + (lane & 3) * 2;
#pragma unroll
    for (int i = 0; i < 2; i++)
#pragma unroll
        for (int j = 0; j < 4; j++) {
            int m = m0 + i * 16, n = n0 + j * 8;
            float b0 = bp[n], b1 = bp[n + 1];
            *(float2*)&g_y[m * NE + n]       = make_float2(acc[i][j][0] + b0, acc[i][j][1] + b1);
            *(float2*)&g_y[(m + 8) * NE + n] = make_float2(acc[i][j][2] + b0, acc[i][j][3] + b1);
        }
}

// ---------------- expert GEMM1: h = gelu(x_gather @ w1^T + b1); grid(24,8,8) --
__global__ __launch_bounds__(256) void moe_g1_mma(
    const float* __restrict__ w1l, const float* __restrict__ b1l)
{
    const int e = blockIdx.z;
    const int ne = g_cnt[e];
    if ((int)(blockIdx.y * 64) >= ne) return;
    float acc[2][4][4] = {};
    mma_gemm_core(g_x, NE, g_tok + e * NTOK, ne, blockIdx.y,
                  w1l + (size_t)e * DFF * NE, blockIdx.x, NE, acc);
    const int lane = threadIdx.x & 31, warp = threadIdx.x >> 5;
    const int m0 = blockIdx.y * 64 + (warp >> 2) * 32 + (lane >> 2);
    const int n0 = blockIdx.x * 128 + (warp & 3) * 32 + (lane & 3) * 2;
    float* hb = g_h + (size_t)e * NTOK * DFF;
#pragma unroll
    for (int i = 0; i < 2; i++)
#pragma unroll
        for (int j = 0; j < 4; j++) {
            int n = n0 + j * 8;
            float b0 = b1l[e * DFF + n], b1 = b1l[e * DFF + n + 1];
#pragma unroll
            for (int half = 0; half < 2; half++) {
                int m = m0 + i * 16 + half * 8;
                if (m < ne) {
                    float v0 = acc[i][j][half * 2 + 0] + b0;
                    float v1 = acc[i][j][half * 2 + 1] + b1;
                    v0 = 0.5f * v0 * (1.f + erff(v0 * 0.70710678118654752f));
                    v1 = 0.5f * v1 * (1.f + erff(v1 * 0.70710678118654752f));
                    *(float2*)&hb[(size_t)m * DFF + n] = make_float2(v0, v1);
                }
            }
        }
}

// ---------------- expert GEMM2: y_slot = p*(h @ w2^T + b2); grid(6,8,8) -------
__global__ __launch_bounds__(256) void moe_g2_mma(
    const float* __restrict__ w2l, const float* __restrict__ b2l)
{
    const int e = blockIdx.z;
    const int ne = g_cnt[e];
    if ((int)(blockIdx.y * 64) >= ne) return;
    float acc[2][4][4] = {};
    mma_gemm_core(g_h + (size_t)e * NTOK * DFF, DFF, nullptr, ne, blockIdx.y,
                  w2l + (size_t)e * NE * DFF, blockIdx.x, DFF, acc);
    const int lane = threadIdx.x & 31, warp = threadIdx.x >> 5;
    const int m0 = blockIdx.y * 64 + (warp >> 2) * 32 + (lane >> 2);
    const int n0 = blockIdx.x * 128 + (warp & 3) * 32 + (lane & 3) * 2;
#pragma unroll
    for (int i = 0; i < 2; i++)
#pragma unroll
        for (int j = 0; j < 4; j++) {
            int n = n0 + j * 8;
            float b0 = b2l[e * NE + n], b1 = b2l[e * NE + n + 1];
#pragma unroll
            for (int half = 0; half < 2; half++) {
                int m = m0 + i * 16 + half * 8;
                if (m < ne) {
                    int tok = g_tok[e * NTOK + m];
                    int sl  = g_slot[e * NTOK + m];
                    float p = g_pw[e * NTOK + m];
                    float* dst = g_yslot + (size_t)sl * NTOK * NE + (size_t)tok * NE;
                    *(float2*)&dst[n] = make_float2(p * (acc[i][j][half * 2 + 0] + b0),
                                                    p * (acc[i][j][half * 2 + 1] + b1));
                }
            }
        }
}

// ---------------- embed ------------------------------------------------------
__global__ void embed_kernel(const int* __restrict__ idx,
                             const float* __restrict__ te,
                             const float* __restrict__ pe) {
    int t = blockIdx.x;
    int id = idx[t];
    int pp = t & (TT - 1);
    for (int c = threadIdx.x; c < NE; c += blockDim.x)
        g_x[t * NE + c] = te[id * NE + c] + pe[pp * NE + c];
}

// ---------------- attention core: grid (B*H=64, 2), 256 thr, dyn smem --------
__global__ __launch_bounds__(256) void attn_kernel() {
    extern __shared__ float sm[];
    float* sq = sm;                 // 32*96
    float* sk = sq + 32 * HD;       // 64*96
    float* sv = sk + 64 * HD;       // 64*96
    float* ss = sv + 64 * HD;       // 32*64
    const int b = blockIdx.x >> 3, h = blockIdx.x & 7;
    const int t0 = blockIdx.y * 32;
    const int base = b * TT;
    const int tid = threadIdx.x;
    const int col0 = h * HD;

    for (int i = tid; i < 64 * HD; i += 256) {
        int t = i / HD, d = i - t * HD;
        sk[i] = g_k[(base + t) * NE + col0 + d];
        sv[i] = g_v[(base + t) * NE + col0 + d];
    }
    for (int i = tid; i < 32 * HD; i += 256) {
        int t = i / HD, d = i - t * HD;
        sq[i] = g_q[(base + t0 + t) * NE + col0 + d];
    }
    __syncthreads();

    const float scale = 0.10206207261596575f;  // 96^-0.5
    for (int e = tid; e < 32 * 64; e += 256) {
        int t = e >> 6, s = e & 63;
        float a = 0.f;
        if (s <= t0 + t) {
            const float* qp = sq + t * HD;
            const float* kp = sk + s * HD;
#pragma unroll 8
            for (int d = 0; d < HD; d++) a += qp[d] * kp[d];
            a *= scale;
        }
        ss[e] = a;
    }
    __syncthreads();

    if (tid < 32) {
        int lim = t0 + tid;
        float m = -1e30f;
        for (int s = 0; s <= lim; s++) m = fmaxf(m, ss[tid * 64 + s]);
        float sum = 0.f;
        for (int s = 0; s < 64; s++) {
            float v = (s <= lim) ? expf(ss[tid * 64 + s] - m) : 0.f;
            ss[tid * 64 + s] = v;
            sum += v;
        }
        float inv = 1.f / sum;
        for (int s = 0; s < 64; s++) ss[tid * 64 + s] *= inv;
    }
    __syncthreads();

    for (int i = tid; i < 32 * HD; i += 256) {
        int t = i / HD, d = i - t * HD;
        const float* ps = ss + t * 64;
        float a = 0.f;
#pragma unroll 8
        for (int s = 0; s < 64; s++) a += ps[s] * sv[s * HD + d];
        g_o[(base + t0 + t) * NE + col0 + d] = a;
    }
}

// ---------------- residual add + layernorm; mode: 0 none, 1 +g_y, 2 +yslots --
__global__ __launch_bounds__(256) void addln_kernel(
    const float* __restrict__ w, const float* __restrict__ bb, int mode)
{
    const int t = blockIdx.x, tid = threadIdx.x;
    float v[3];
    float s = 0.f, s2 = 0.f;
#pragma unroll
    for (int j = 0; j < 3; j++) {
        int c = tid + j * 256;
        float x = g_x[t * NE + c];
        if (mode == 1) x += g_y[t * NE + c];
        else if (mode == 2) x += g_yslot[t * NE + c] + g_yslot[NTOK * NE + t * NE + c];
        v[j] = x; s += x; s2 += x * x;
    }
#pragma unroll
    for (int o = 16; o; o >>= 1) {
        s  += __shfl_down_sync(0xffffffffu, s,  o);
        s2 += __shfl_down_sync(0xffffffffu, s2, o);
    }
    __shared__ float rs[8], rs2[8], smv[2];
    const int wp = tid >> 5, lane = tid & 31;
    if (lane == 0) { rs[wp] = s; rs2[wp] = s2; }
    __syncthreads();
    if (tid == 0) {
        float a = 0.f, b2 = 0.f;
#pragma unroll
        for (int i = 0; i < 8; i++) { a += rs[i]; b2 += rs2[i]; }
        float mean = a * (1.f / NE);
        float var = b2 * (1.f / NE) - mean * mean;
        smv[0] = mean;
        smv[1] = rsqrtf(var + 1e-5f);
    }
    __syncthreads();
    const float mean = smv[0], r = smv[1];
#pragma unroll
    for (int j = 0; j < 3; j++) {
        int c = tid + j * 256;
        g_x[t * NE + c] = (v[j] - mean) * r * w[c] + bb[c];
    }
}

// ---------------- MoE routing ------------------------------------------------
__global__ __launch_bounds__(256) void route_a(
    const float* __restrict__ gw, const float* __restrict__ gb)
{
    const int tok = blockIdx.x;
    const int w = threadIdx.x >> 5, lane = threadIdx.x & 31;
    const float* xr = g_x + tok * NE;
    const float* gr = gw + w * NE;
    float a = 0.f;
    for (int c = lane; c < NE; c += 32) a += xr[c] * gr[c];
#pragma unroll
    for (int o = 16; o; o >>= 1) a += __shfl_down_sync(0xffffffffu, a, o);
    if (lane == 0) g_logits[tok * NEXP + w] = a + gb[w];
}

__global__ __launch_bounds__(512) void route_b() {
    __shared__ int scnt[NEXP];
    const int tid = threadIdx.x;
    if (tid < NEXP) scnt[tid] = 0;
    __syncthreads();

    float lg[NEXP];
    float m = -1e30f;
#pragma unroll
    for (int e = 0; e < NEXP; e++) { lg[e] = g_logits[tid * NEXP + e]; m = fmaxf(m, lg[e]); }
#pragma unroll
    for (int e = 0; e < NEXP; e++) lg[e] = expf(lg[e] - m);

    int i0 = 0;
#pragma unroll
    for (int e = 1; e < NEXP; e++) if (lg[e] > lg[i0]) i0 = e;
    int i1 = (i0 == 0) ? 1 : 0;
#pragma unroll
    for (int e = 0; e < NEXP; e++) if (e != i0 && lg[e] > lg[i1]) i1 = e;

    const float inv = 1.f / (lg[i0] + lg[i1]);
    const float p0 = lg[i0] * inv, p1 = lg[i1] * inv;

    int pos0 = atomicAdd(&scnt[i0], 1);
    g_tok[i0 * NTOK + pos0] = tid; g_slot[i0 * NTOK + pos0] = 0; g_pw[i0 * NTOK + pos0] = p0;
    int pos1 = atomicAdd(&scnt[i1], 1);
    g_tok[i1 * NTOK + pos1] = tid; g_slot[i1 * NTOK + pos1] = 1; g_pw[i1 * NTOK + pos1] = p1;

    __syncthreads();
    if (tid < NEXP) g_cnt[tid] = scnt[tid];
}

// ---------------- LM head: logits = x @ lm_w^T + lm_b ------------------------
__global__ __launch_bounds__(128) void lm_kernel(
    const float* __restrict__ lw, const float* __restrict__ lb,
    float* __restrict__ out)
{
    __shared__ float xr[NE];
    const int t = blockIdx.x, tid = threadIdx.x;
    for (int c = tid; c < NE; c += 128) xr[c] = g_x[t * NE + c];
    __syncthreads();
    if (tid < NVOCAB) {
        const float* wr = lw + (size_t)tid * NE;
        float a = lb[tid];
#pragma unroll 8
        for (int c = 0; c < NE; c++) a += xr[c] * wr[c];
        out[t * NVOCAB + tid] = a;
    }
}

// ---------------- launch -----------------------------------------------------
extern "C" void kernel_launch(void* const* d_in, const int* in_sizes, int n_in,
                              void* d_out, int out_size) {
    (void)in_sizes; (void)n_in; (void)out_size;
    const int*   idx     = (const int*)  d_in[0];
    const float* tok_emb = (const float*)d_in[1];
    const float* pos_emb = (const float*)d_in[2];
    const float* wq      = (const float*)d_in[3];
    const float* wk      = (const float*)d_in[4];
    const float* wv      = (const float*)d_in[5];
    const float* wproj   = (const float*)d_in[6];
    const float* bproj   = (const float*)d_in[7];
    const float* gate_w  = (const float*)d_in[8];
    const float* gate_b  = (const float*)d_in[9];
    const float* w1      = (const float*)d_in[10];
    const float* b1      = (const float*)d_in[11];
    const float* w2      = (const float*)d_in[12];
    const float* b2      = (const float*)d_in[13];
    const float* ln1_w   = (const float*)d_in[14];
    const float* ln1_b   = (const float*)d_in[15];
    const float* ln2_w   = (const float*)d_in[16];
    const float* ln2_b   = (const float*)d_in[17];
    const float* lnf_w   = (const float*)d_in[18];
    const float* lnf_b   = (const float*)d_in[19];
    const float* lm_w    = (const float*)d_in[20];
    const float* lm_b    = (const float*)d_in[21];
    float* out = (float*)d_out;

    const int ATTN_SMEM = (32 * HD + 64 * HD + 64 * HD + 32 * 64) * 4;  // 69632 B
    cudaFuncSetAttribute(attn_kernel, cudaFuncAttributeMaxDynamicSharedMemorySize, ATTN_SMEM);

    embed_kernel<<<NTOK, 256>>>(idx, tok_emb, pos_emb);

    for (int l = 0; l < NLAYER; l++) {
        const size_t offW  = (size_t)l * NH * HD * NE;      // 589824
        const size_t offM1 = (size_t)l * NEXP * DFF * NE;   // w1/w2 per layer
        qkv_mma<<<dim3(6, 8, 3), 256>>>(wq + offW, wk + offW, wv + offW);
        attn_kernel<<<dim3(64, 2), 256, ATTN_SMEM>>>();
        proj_mma<<<dim3(6, 8), 256>>>(wproj + offW, bproj + (size_t)l * NE);
        addln_kernel<<<NTOK, 256>>>(ln1_w + (size_t)l * NE, ln1_b + (size_t)l * NE, 1);

        route_a<<<NTOK, 256>>>(gate_w + (size_t)l * NEXP * NE, gate_b + (size_t)l * NEXP);
        route_b<<<1, 512>>>();
        moe_g1_mma<<<dim3(24, 8, NEXP), 256>>>(w1 + offM1, b1 + (size_t)l * NEXP * DFF);
        moe_g2_mma<<<dim3(6, 8, NEXP), 256>>>(w2 + offM1, b2 + (size_t)l * NEXP * NE);
        addln_kernel<<<NTOK, 256>>>(ln2_w + (size_t)l * NE, ln2_b + (size_t)l * NE, 2);
    }

    addln_kernel<<<NTOK, 256>>>(lnf_w, lnf_b, 0);
    lm_kernel<<<NTOK, 128>>>(lm_w, lm_b, out);
}

// round 7
// speedup vs baseline: 2.0473x; 1.2623x over previous
#include <cuda_runtime.h>
#include <cuda_bf16.h>
#include <math.h>

#define NTOK   512          // B*T = 8*64
#define NE     768          // n_embd
#define NH     8            // heads
#define HD     96           // head dim
#define DFF    3072
#define NEXP   8
#define NLAYER 12
#define NVOCAB 99
#define TT     64           // seq len

// ---------------- scratch (static device globals; no allocation) -------------
__device__ float g_x[NTOK * NE];
__device__ float g_q[NTOK * NE];
__device__ float g_k[NTOK * NE];
__device__ float g_v[NTOK * NE];
__device__ float g_o[NTOK * NE];
__device__ float g_y[NTOK * NE];
__device__ float g_h[(size_t)NEXP * NTOK * DFF];   // ~50 MB expert hidden
__device__ float g_yslot[2 * NTOK * NE];           // per-slot MoE outputs
__device__ float g_logits[NTOK * NEXP];
__device__ int   g_cnt[NEXP];
__device__ int   g_tok[NEXP * NTOK];
__device__ int   g_slot[NEXP * NTOK];
__device__ float g_pw[NEXP * NTOK];

// ---------------- small helpers ----------------------------------------------
__device__ __forceinline__ unsigned su32(const void* p) {
    return (unsigned)__cvta_generic_to_shared(p);
}

__device__ __forceinline__ void ldsm4(unsigned* r, unsigned addr) {
    asm volatile("ldmatrix.sync.aligned.m8n8.x4.shared.b16 {%0,%1,%2,%3}, [%4];"
        : "=r"(r[0]), "=r"(r[1]), "=r"(r[2]), "=r"(r[3]) : "r"(addr));
}

__device__ __forceinline__ void mma16816(float* c, const unsigned* a, const unsigned* b) {
    asm volatile(
        "mma.sync.aligned.m16n8k16.row.col.f32.bf16.bf16.f32 "
        "{%0,%1,%2,%3}, {%4,%5,%6,%7}, {%8,%9}, {%0,%1,%2,%3};\n"
        : "+f"(c[0]), "+f"(c[1]), "+f"(c[2]), "+f"(c[3])
        : "r"(a[0]), "r"(a[1]), "r"(a[2]), "r"(a[3]), "r"(b[0]), "r"(b[1]));
}

// split 2 fp32 into packed bf16 hi pair + bf16 lo pair (lo = x - float(hi))
__device__ __forceinline__ void split2(float x0, float x1, unsigned& hi, unsigned& lo) {
    __nv_bfloat162 h = __floats2bfloat162_rn(x0, x1);
    float2 hf = __bfloat1622float2(h);
    __nv_bfloat162 l = __floats2bfloat162_rn(x0 - hf.x, x1 - hf.y);
    hi = *reinterpret_cast<unsigned*>(&h);
    lo = *reinterpret_cast<unsigned*>(&l);
}

// ---------------- tensor-core GEMM core: C = A @ W^T (fp32-in/out, bf16x3) ----
// Block tile 64(M) x 128(N), BK=16, DOUBLE-BUFFERED smem, 256 threads = 8 warps
// (2M x 4N), warp tile 32x32. A: [mrows, lda] fp32 row-major (optional gather).
// W: [N, K] fp32 row-major (rows K-major = col-major B => "row.col" mma).
__device__ __forceinline__ void mma_gemm_core(
    const float* __restrict__ Abase, int lda,
    const int* __restrict__ rowmap, int mrows, int mTile,
    const float* __restrict__ W, int nTile, int K,
    float (&acc)[2][4][4])
{
    // [stage][part hi/lo][row][16k + pad8] ; row stride 48B (conflict-free LDSM)
    __shared__ __align__(16) __nv_bfloat16 As[2][2][64][24];    // 12 KB
    __shared__ __align__(16) __nv_bfloat16 Bs[2][2][128][24];   // 24 KB

    const int tx = threadIdx.x;
    const int warp = tx >> 5, lane = tx & 31;
    const int wm = (warp >> 2) * 32;   // warp M offset
    const int wn = (warp & 3) * 32;    // warp N offset

    // --- staging assignments ---
    const int ar = tx >> 2;            // A row 0..63
    const int ak = (tx & 3) << 2;      // k offset {0,4,8,12}
    const int grow = mTile * 64 + ar;
    const float* aptr = nullptr;
    if (grow < mrows) {
        int src = rowmap ? rowmap[grow] : grow;
        aptr = Abase + (size_t)src * lda + ak;
    }
    const int br = tx >> 1;            // B row 0..127
    const int bk = (tx & 1) << 3;      // k offset {0,8}
    const float* bptr = W + (size_t)(nTile * 128 + br) * K + bk;

    // --- ldmatrix lane base addresses (stage 0, part hi) ---
    const unsigned aBase = su32(&As[0][0][wm + (lane & 15)][(lane >> 4) * 8]);
    const int bn = wn + (lane & 7) + ((lane >> 1) & 8);
    const unsigned bBase = su32(&Bs[0][0][bn][lane & 8]);
    // strides (bytes): A stage 6144, part 3072; B stage 12288, part 6144; +16rows = 768

    const int nt = K >> 4;

    // prologue: tile 0 regs -> stage into buf 0; prefetch tile 1 regs
    float4 av  = aptr ? *(const float4*)aptr : make_float4(0.f, 0.f, 0.f, 0.f);
    float4 bv0 = *(const float4*)bptr;
    float4 bv1 = *(const float4*)(bptr + 4);
    {
        unsigned h0, l0, h1, l1;
        split2(av.x, av.y, h0, l0); split2(av.z, av.w, h1, l1);
        *(uint2*)&As[0][0][ar][ak] = make_uint2(h0, h1);
        *(uint2*)&As[0][1][ar][ak] = make_uint2(l0, l1);
        unsigned p0h, p0l, p1h, p1l, p2h, p2l, p3h, p3l;
        split2(bv0.x, bv0.y, p0h, p0l); split2(bv0.z, bv0.w, p1h, p1l);
        split2(bv1.x, bv1.y, p2h, p2l); split2(bv1.z, bv1.w, p3h, p3l);
        *(uint4*)&Bs[0][0][br][bk] = make_uint4(p0h, p1h, p2h, p3h);
        *(uint4*)&Bs[0][1][br][bk] = make_uint4(p0l, p1l, p2l, p3l);
    }
    if (nt > 1) {
        av  = aptr ? *(const float4*)(aptr + 16) : make_float4(0.f, 0.f, 0.f, 0.f);
        bv0 = *(const float4*)(bptr + 16);
        bv1 = *(const float4*)(bptr + 20);
    }
    __syncthreads();

    for (int t = 0; t < nt; t++) {
        const int p = t & 1;
        const unsigned aHi = aBase + p * 6144;
        const unsigned bHi = bBase + p * 12288;
        unsigned Ah[2][4], Al[2][4], Bh[2][4], Bl[2][4];
        ldsm4(Ah[0], aHi);          ldsm4(Ah[1], aHi + 768);
        ldsm4(Al[0], aHi + 3072);   ldsm4(Al[1], aHi + 3072 + 768);
        ldsm4(Bh[0], bHi);          ldsm4(Bh[1], bHi + 768);
        ldsm4(Bl[0], bHi + 6144);   ldsm4(Bl[1], bHi + 6144 + 768);

        // stage tile t+1 into the other buffer (independent of this tile's MMA;
        // ptxas interleaves this ALU/STS stream into HMMA gaps)
        if (t + 1 < nt) {
            const int q = p ^ 1;
            unsigned h0, l0, h1, l1;
            split2(av.x, av.y, h0, l0); split2(av.z, av.w, h1, l1);
            *(uint2*)&As[q][0][ar][ak] = make_uint2(h0, h1);
            *(uint2*)&As[q][1][ar][ak] = make_uint2(l0, l1);
            unsigned p0h, p0l, p1h, p1l, p2h, p2l, p3h, p3l;
            split2(bv0.x, bv0.y, p0h, p0l); split2(bv0.z, bv0.w, p1h, p1l);
            split2(bv1.x, bv1.y, p2h, p2l); split2(bv1.z, bv1.w, p3h, p3l);
            *(uint4*)&Bs[q][0][br][bk] = make_uint4(p0h, p1h, p2h, p3h);
            *(uint4*)&Bs[q][1][br][bk] = make_uint4(p0l, p1l, p2l, p3l);
            if (t + 2 < nt) {  // prefetch tile t+2 into regs (2-tile LDG distance)
                const int ko = (t + 2) * 16;
                av  = aptr ? *(const float4*)(aptr + ko) : make_float4(0.f, 0.f, 0.f, 0.f);
                bv0 = *(const float4*)(bptr + ko);
                bv1 = *(const float4*)(bptr + ko + 4);
            }
        }

#pragma unroll
        for (int i = 0; i < 2; i++)
#pragma unroll
            for (int j = 0; j < 4; j++) {
                const unsigned* bh = &Bh[j >> 1][(j & 1) * 2];
                const unsigned* bl = &Bl[j >> 1][(j & 1) * 2];
                mma16816(acc[i][j], Ah[i], bh);   // hi*hi
                mma16816(acc[i][j], Ah[i], bl);   // hi*lo
                mma16816(acc[i][j], Al[i], bh);   // lo*hi
            }
        __syncthreads();
    }
}

// ---------------- fused QKV: grid (6, 8, 3) -----------------------------------
__global__ __launch_bounds__(256) void qkv_mma(
    const float* __restrict__ wq, const float* __restrict__ wk,
    const float* __restrict__ wv)
{
    const float* W = (blockIdx.z == 0) ? wq : (blockIdx.z == 1) ? wk : wv;
    float* out = (blockIdx.z == 0) ? g_q : (blockIdx.z == 1) ? g_k : g_v;
    float acc[2][4][4] = {};
    mma_gemm_core(g_x, NE, nullptr, NTOK, blockIdx.y, W, blockIdx.x, NE, acc);
    const int lane = threadIdx.x & 31, warp = threadIdx.x >> 5;
    const int m0 = blockIdx.y * 64 + (warp >> 2) * 32 + (lane >> 2);
    const int n0 = blockIdx.x * 128 + (warp & 3) * 32 + (lane & 3) * 2;
#pragma unroll
    for (int i = 0; i < 2; i++)
#pragma unroll
        for (int j = 0; j < 4; j++) {
            int m = m0 + i * 16, n = n0 + j * 8;
            *(float2*)&out[m * NE + n]       = make_float2(acc[i][j][0], acc[i][j][1]);
            *(float2*)&out[(m + 8) * NE + n] = make_float2(acc[i][j][2], acc[i][j][3]);
        }
}

// ---------------- output projection: grid (6, 8) -----------------------------
__global__ __launch_bounds__(256) void proj_mma(
    const float* __restrict__ wp, const float* __restrict__ bp)
{
    float acc[2][4][4] = {};
    mma_gemm_core(g_o, NE, nullptr, NTOK, blockIdx.y, wp, blockIdx.x, NE, acc);
    const int lane = threadIdx.x & 31, warp = threadIdx.x >> 5;
    const int m0 = blockIdx.y * 64 + (warp >> 2) * 32 + (lane >> 2);
    const int n0 = blockIdx.x * 128 + (warp & 3) * 32 + (lane & 3) * 2;
#pragma unroll
    for (int i = 0; i < 2; i++)
#pragma unroll
        for (int j = 0; j < 4; j++) {
            int m = m0 + i * 16, n = n0 + j * 8;
            float b0 = bp[n], b1 = bp[n + 1];
            *(float2*)&g_y[m * NE + n]       = make_float2(acc[i][j][0] + b0, acc[i][j][1] + b1);
            *(float2*)&g_y[(m + 8) * NE + n] = make_float2(acc[i][j][2] + b0, acc[i][j][3] + b1);
        }
}

// ---------------- expert GEMM1: h = gelu(x_gather @ w1^T + b1); grid(24,8,8) --
__global__ __launch_bounds__(256) void moe_g1_mma(
    const float* __restrict__ w1l, const float* __restrict__ b1l)
{
    const int e = blockIdx.z;
    const int ne = g_cnt[e];
    if ((int)(blockIdx.y * 64) >= ne) return;
    float acc[2][4][4] = {};
    mma_gemm_core(g_x, NE, g_tok + e * NTOK, ne, blockIdx.y,
                  w1l + (size_t)e * DFF * NE, blockIdx.x, NE, acc);
    const int lane = threadIdx.x & 31, warp = threadIdx.x >> 5;
    const int m0 = blockIdx.y * 64 + (warp >> 2) * 32 + (lane >> 2);
    const int n0 = blockIdx.x * 128 + (warp & 3) * 32 + (lane & 3) * 2;
    float* hb = g_h + (size_t)e * NTOK * DFF;
#pragma unroll
    for (int i = 0; i < 2; i++)
#pragma unroll
        for (int j = 0; j < 4; j++) {
            int n = n0 + j * 8;
            float b0 = b1l[e * DFF + n], b1 = b1l[e * DFF + n + 1];
#pragma unroll
            for (int half = 0; half < 2; half++) {
                int m = m0 + i * 16 + half * 8;
                if (m < ne) {
                    float v0 = acc[i][j][half * 2 + 0] + b0;
                    float v1 = acc[i][j][half * 2 + 1] + b1;
                    v0 = 0.5f * v0 * (1.f + erff(v0 * 0.70710678118654752f));
                    v1 = 0.5f * v1 * (1.f + erff(v1 * 0.70710678118654752f));
                    *(float2*)&hb[(size_t)m * DFF + n] = make_float2(v0, v1);
                }
            }
        }
}

// ---------------- expert GEMM2: y_slot = p*(h @ w2^T + b2); grid(6,8,8) -------
__global__ __launch_bounds__(256) void moe_g2_mma(
    const float* __restrict__ w2l, const float* __restrict__ b2l)
{
    const int e = blockIdx.z;
    const int ne = g_cnt[e];
    if ((int)(blockIdx.y * 64) >= ne) return;
    float acc[2][4][4] = {};
    mma_gemm_core(g_h + (size_t)e * NTOK * DFF, DFF, nullptr, ne, blockIdx.y,
                  w2l + (size_t)e * NE * DFF, blockIdx.x, DFF, acc);
    const int lane = threadIdx.x & 31, warp = threadIdx.x >> 5;
    const int m0 = blockIdx.y * 64 + (warp >> 2) * 32 + (lane >> 2);
    const int n0 = blockIdx.x * 128 + (warp & 3) * 32 + (lane & 3) * 2;
#pragma unroll
    for (int i = 0; i < 2; i++)
#pragma unroll
        for (int j = 0; j < 4; j++) {
            int n = n0 + j * 8;
            float b0 = b2l[e * NE + n], b1 = b2l[e * NE + n + 1];
#pragma unroll
            for (int half = 0; half < 2; half++) {
                int m = m0 + i * 16 + half * 8;
                if (m < ne) {
                    int tok = g_tok[e * NTOK + m];
                    int sl  = g_slot[e * NTOK + m];
                    float p = g_pw[e * NTOK + m];
                    float* dst = g_yslot + (size_t)sl * NTOK * NE + (size_t)tok * NE;
                    *(float2*)&dst[n] = make_float2(p * (acc[i][j][half * 2 + 0] + b0),
                                                    p * (acc[i][j][half * 2 + 1] + b1));
                }
            }
        }
}

// ---------------- embed ------------------------------------------------------
__global__ void embed_kernel(const int* __restrict__ idx,
                             const float* __restrict__ te,
                             const float* __restrict__ pe) {
    int t = blockIdx.x;
    int id = idx[t];
    int pp = t & (TT - 1);
    for (int c = threadIdx.x; c < NE; c += blockDim.x)
        g_x[t * NE + c] = te[id * NE + c] + pe[pp * NE + c];
}

// ---------------- attention core: grid (B*H=64, 2), 256 thr, dyn smem --------
__global__ __launch_bounds__(256) void attn_kernel() {
    extern __shared__ float sm[];
    float* sq = sm;                 // 32*96
    float* sk = sq + 32 * HD;       // 64*96
    float* sv = sk + 64 * HD;       // 64*96
    float* ss = sv + 64 * HD;       // 32*64
    const int b = blockIdx.x >> 3, h = blockIdx.x & 7;
    const int t0 = blockIdx.y * 32;
    const int base = b * TT;
    const int tid = threadIdx.x;
    const int col0 = h * HD;

    for (int i = tid; i < 64 * HD; i += 256) {
        int t = i / HD, d = i - t * HD;
        sk[i] = g_k[(base + t) * NE + col0 + d];
        sv[i] = g_v[(base + t) * NE + col0 + d];
    }
    for (int i = tid; i < 32 * HD; i += 256) {
        int t = i / HD, d = i - t * HD;
        sq[i] = g_q[(base + t0 + t) * NE + col0 + d];
    }
    __syncthreads();

    const float scale = 0.10206207261596575f;  // 96^-0.5
    for (int e = tid; e < 32 * 64; e += 256) {
        int t = e >> 6, s = e & 63;
        float a = 0.f;
        if (s <= t0 + t) {
            const float* qp = sq + t * HD;
            const float* kp = sk + s * HD;
#pragma unroll 8
            for (int d = 0; d < HD; d++) a += qp[d] * kp[d];
            a *= scale;
        }
        ss[e] = a;
    }
    __syncthreads();

    if (tid < 32) {
        int lim = t0 + tid;
        float m = -1e30f;
        for (int s = 0; s <= lim; s++) m = fmaxf(m, ss[tid * 64 + s]);
        float sum = 0.f;
        for (int s = 0; s < 64; s++) {
            float v = (s <= lim) ? expf(ss[tid * 64 + s] - m) : 0.f;
            ss[tid * 64 + s] = v;
            sum += v;
        }
        float inv = 1.f / sum;
        for (int s = 0; s < 64; s++) ss[tid * 64 + s] *= inv;
    }
    __syncthreads();

    for (int i = tid; i < 32 * HD; i += 256) {
        int t = i / HD, d = i - t * HD;
        const float* ps = ss + t * 64;
        float a = 0.f;
#pragma unroll 8
        for (int s = 0; s < 64; s++) a += ps[s] * sv[s * HD + d];
        g_o[(base + t0 + t) * NE + col0 + d] = a;
    }
}

// ------ residual add + layernorm (+ fused MoE gate logits when mode==1) ------
// mode: 0 none, 1 +g_y then gate, 2 +yslots
__global__ __launch_bounds__(256) void addln_kernel(
    const float* __restrict__ w, const float* __restrict__ bb, int mode,
    const float* __restrict__ gw, const float* __restrict__ gb)
{
    __shared__ float xs[NE];
    const int t = blockIdx.x, tid = threadIdx.x;
    float v[3];
    float s = 0.f, s2 = 0.f;
#pragma unroll
    for (int j = 0; j < 3; j++) {
        int c = tid + j * 256;
        float x = g_x[t * NE + c];
        if (mode == 1) x += g_y[t * NE + c];
        else if (mode == 2) x += g_yslot[t * NE + c] + g_yslot[NTOK * NE + t * NE + c];
        v[j] = x; s += x; s2 += x * x;
    }
#pragma unroll
    for (int o = 16; o; o >>= 1) {
        s  += __shfl_down_sync(0xffffffffu, s,  o);
        s2 += __shfl_down_sync(0xffffffffu, s2, o);
    }
    __shared__ float rs[8], rs2[8], smv[2];
    const int wp = tid >> 5, lane = tid & 31;
    if (lane == 0) { rs[wp] = s; rs2[wp] = s2; }
    __syncthreads();
    if (tid == 0) {
        float a = 0.f, b2 = 0.f;
#pragma unroll
        for (int i = 0; i < 8; i++) { a += rs[i]; b2 += rs2[i]; }
        float mean = a * (1.f / NE);
        float var = b2 * (1.f / NE) - mean * mean;
        smv[0] = mean;
        smv[1] = rsqrtf(var + 1e-5f);
    }
    __syncthreads();
    const float mean = smv[0], r = smv[1];
#pragma unroll
    for (int j = 0; j < 3; j++) {
        int c = tid + j * 256;
        float val = (v[j] - mean) * r * w[c] + bb[c];
        g_x[t * NE + c] = val;
        xs[c] = val;
    }
    if (mode == 1) {   // fused gate logits: warp wp -> expert wp
        __syncthreads();
        const float* gr = gw + wp * NE;
        float a = 0.f;
        for (int c = lane; c < NE; c += 32) a += xs[c] * gr[c];
#pragma unroll
        for (int o = 16; o; o >>= 1) a += __shfl_down_sync(0xffffffffu, a, o);
        if (lane == 0) g_logits[t * NEXP + wp] = a + gb[wp];
    }
}

// ---- top-2 + renorm + per-expert token lists. single block, 512 threads ----
__global__ __launch_bounds__(512) void route_b() {
    __shared__ int scnt[NEXP];
    const int tid = threadIdx.x;
    if (tid < NEXP) scnt[tid] = 0;
    __syncthreads();

    float lg[NEXP];
    float m = -1e30f;
#pragma unroll
    for (int e = 0; e < NEXP; e++) { lg[e] = g_logits[tid * NEXP + e]; m = fmaxf(m, lg[e]); }
#pragma unroll
    for (int e = 0; e < NEXP; e++) lg[e] = expf(lg[e] - m);

    int i0 = 0;
#pragma unroll
    for (int e = 1; e < NEXP; e++) if (lg[e] > lg[i0]) i0 = e;
    int i1 = (i0 == 0) ? 1 : 0;
#pragma unroll
    for (int e = 0; e < NEXP; e++) if (e != i0 && lg[e] > lg[i1]) i1 = e;

    const float inv = 1.f / (lg[i0] + lg[i1]);
    const float p0 = lg[i0] * inv, p1 = lg[i1] * inv;

    int pos0 = atomicAdd(&scnt[i0], 1);
    g_tok[i0 * NTOK + pos0] = tid; g_slot[i0 * NTOK + pos0] = 0; g_pw[i0 * NTOK + pos0] = p0;
    int pos1 = atomicAdd(&scnt[i1], 1);
    g_tok[i1 * NTOK + pos1] = tid; g_slot[i1 * NTOK + pos1] = 1; g_pw[i1 * NTOK + pos1] = p1;

    __syncthreads();
    if (tid < NEXP) g_cnt[tid] = scnt[tid];
}

// ---------------- LM head: logits = x @ lm_w^T + lm_b ------------------------
__global__ __launch_bounds__(128) void lm_kernel(
    const float* __restrict__ lw, const float* __restrict__ lb,
    float* __restrict__ out)
{
    __shared__ float xr[NE];
    const int t = blockIdx.x, tid = threadIdx.x;
    for (int c = tid; c < NE; c += 128) xr[c] = g_x[t * NE + c];
    __syncthreads();
    if (tid < NVOCAB) {
        const float* wr = lw + (size_t)tid * NE;
        float a = lb[tid];
#pragma unroll 8
        for (int c = 0; c < NE; c++) a += xr[c] * wr[c];
        out[t * NVOCAB + tid] = a;
    }
}

// ---------------- launch -----------------------------------------------------
extern "C" void kernel_launch(void* const* d_in, const int* in_sizes, int n_in,
                              void* d_out, int out_size) {
    (void)in_sizes; (void)n_in; (void)out_size;
    const int*   idx     = (const int*)  d_in[0];
    const float* tok_emb = (const float*)d_in[1];
    const float* pos_emb = (const float*)d_in[2];
    const float* wq      = (const float*)d_in[3];
    const float* wk      = (const float*)d_in[4];
    const float* wv      = (const float*)d_in[5];
    const float* wproj   = (const float*)d_in[6];
    const float* bproj   = (const float*)d_in[7];
    const float* gate_w  = (const float*)d_in[8];
    const float* gate_b  = (const float*)d_in[9];
    const float* w1      = (const float*)d_in[10];
    const float* b1      = (const float*)d_in[11];
    const float* w2      = (const float*)d_in[12];
    const float* b2      = (const float*)d_in[13];
    const float* ln1_w   = (const float*)d_in[14];
    const float* ln1_b   = (const float*)d_in[15];
    const float* ln2_w   = (const float*)d_in[16];
    const float* ln2_b   = (const float*)d_in[17];
    const float* lnf_w   = (const float*)d_in[18];
    const float* lnf_b   = (const float*)d_in[19];
    const float* lm_w    = (const float*)d_in[20];
    const float* lm_b    = (const float*)d_in[21];
    float* out = (float*)d_out;

    const int ATTN_SMEM = (32 * HD + 64 * HD + 64 * HD + 32 * 64) * 4;  // 69632 B
    cudaFuncSetAttribute(attn_kernel, cudaFuncAttributeMaxDynamicSharedMemorySize, ATTN_SMEM);

    embed_kernel<<<NTOK, 256>>>(idx, tok_emb, pos_emb);

    for (int l = 0; l < NLAYER; l++) {
        const size_t offW  = (size_t)l * NH * HD * NE;      // 589824
        const size_t offM1 = (size_t)l * NEXP * DFF * NE;   // w1/w2 per layer
        qkv_mma<<<dim3(6, 8, 3), 256>>>(wq + offW, wk + offW, wv + offW);
        attn_kernel<<<dim3(64, 2), 256, ATTN_SMEM>>>();
        proj_mma<<<dim3(6, 8), 256>>>(wproj + offW, bproj + (size_t)l * NE);
        // post-norm + fused gate logits
        addln_kernel<<<NTOK, 256>>>(ln1_w + (size_t)l * NE, ln1_b + (size_t)l * NE, 1,
                                    gate_w + (size_t)l * NEXP * NE,
                                    gate_b + (size_t)l * NEXP);
        route_b<<<1, 512>>>();
        moe_g1_mma<<<dim3(24, 8, NEXP), 256>>>(w1 + offM1, b1 + (size_t)l * NEXP * DFF);
        moe_g2_mma<<<dim3(6, 8, NEXP), 256>>>(w2 + offM1, b2 + (size_t)l * NEXP * NE);
        addln_kernel<<<NTOK, 256>>>(ln2_w + (size_t)l * NE, ln2_b + (size_t)l * NE, 2,
                                    nullptr, nullptr);
    }

    addln_kernel<<<NTOK, 256>>>(lnf_w, lnf_b, 0, nullptr, nullptr);
    lm_kernel<<<NTOK, 128>>>(lm_w, lm_b, out);
}

// round 8
// speedup vs baseline: 2.0490x; 1.0008x over previous
#include <cuda_runtime.h>
#include <cuda_bf16.h>
#include <math.h>

#define NTOK   512          // B*T = 8*64
#define NE     768          // n_embd
#define NH     8            // heads
#define HD     96           // head dim
#define DFF    3072
#define NEXP   8
#define NLAYER 12
#define NVOCAB 99
#define TT     64           // seq len

// ---------------- scratch (static device globals; no allocation) -------------
__device__ float g_x[NTOK * NE];
__device__ float g_q[NTOK * NE];
__device__ float g_k[NTOK * NE];
__device__ float g_v[NTOK * NE];
__device__ float g_o[NTOK * NE];
__device__ float g_y[NTOK * NE];
__device__ float g_h[(size_t)NEXP * NTOK * DFF];   // ~50 MB expert hidden
__device__ float g_yslot[2 * NTOK * NE];           // per-slot MoE outputs
__device__ float g_logits[NTOK * NEXP];
__device__ int   g_cnt[NEXP];
__device__ int   g_tok[NEXP * NTOK];
__device__ int   g_slot[NEXP * NTOK];
__device__ float g_pw[NEXP * NTOK];

// ---------------- small helpers ----------------------------------------------
__device__ __forceinline__ unsigned su32(const void* p) {
    return (unsigned)__cvta_generic_to_shared(p);
}

__device__ __forceinline__ void ldsm4(unsigned* r, unsigned addr) {
    asm volatile("ldmatrix.sync.aligned.m8n8.x4.shared.b16 {%0,%1,%2,%3}, [%4];"
        : "=r"(r[0]), "=r"(r[1]), "=r"(r[2]), "=r"(r[3]) : "r"(addr));
}

__device__ __forceinline__ void mma16816(float* c, const unsigned* a, const unsigned* b) {
    asm volatile(
        "mma.sync.aligned.m16n8k16.row.col.f32.bf16.bf16.f32 "
        "{%0,%1,%2,%3}, {%4,%5,%6,%7}, {%8,%9}, {%0,%1,%2,%3};\n"
        : "+f"(c[0]), "+f"(c[1]), "+f"(c[2]), "+f"(c[3])
        : "r"(a[0]), "r"(a[1]), "r"(a[2]), "r"(a[3]), "r"(b[0]), "r"(b[1]));
}

// split 2 fp32 into packed bf16 hi pair + bf16 lo pair (lo = x - float(hi))
__device__ __forceinline__ void split2(float x0, float x1, unsigned& hi, unsigned& lo) {
    __nv_bfloat162 h = __floats2bfloat162_rn(x0, x1);
    float2 hf = __bfloat1622float2(h);
    __nv_bfloat162 l = __floats2bfloat162_rn(x0 - hf.x, x1 - hf.y);
    hi = *reinterpret_cast<unsigned*>(&h);
    lo = *reinterpret_cast<unsigned*>(&l);
}

// ---------------- tensor-core GEMM core: C = A @ W^T (fp32-in/out, bf16x3) ----
// Block tile 64(M) x 128(N), BK=16, DOUBLE-BUFFERED smem, 256 threads = 8 warps
// (2M x 4N), warp tile 32x32. A: [mrows, lda] fp32 row-major (optional gather).
// W: [N, K] fp32 row-major (rows K-major = col-major B => "row.col" mma).
__device__ __forceinline__ void mma_gemm_core(
    const float* __restrict__ Abase, int lda,
    const int* __restrict__ rowmap, int mrows, int mTile,
    const float* __restrict__ W, int nTile, int K,
    float (&acc)[2][4][4])
{
    // [stage][part hi/lo][row][16k + pad8] ; row stride 48B (conflict-free LDSM)
    __shared__ __align__(16) __nv_bfloat16 As[2][2][64][24];    // 12 KB
    __shared__ __align__(16) __nv_bfloat16 Bs[2][2][128][24];   // 24 KB

    const int tx = threadIdx.x;
    const int warp = tx >> 5, lane = tx & 31;
    const int wm = (warp >> 2) * 32;   // warp M offset
    const int wn = (warp & 3) * 32;    // warp N offset

    // --- staging assignments ---
    const int ar = tx >> 2;            // A row 0..63
    const int ak = (tx & 3) << 2;      // k offset {0,4,8,12}
    const int grow = mTile * 64 + ar;
    const float* aptr = nullptr;
    if (grow < mrows) {
        int src = rowmap ? rowmap[grow] : grow;
        aptr = Abase + (size_t)src * lda + ak;
    }
    const int br = tx >> 1;            // B row 0..127
    const int bk = (tx & 1) << 3;      // k offset {0,8}
    const float* bptr = W + (size_t)(nTile * 128 + br) * K + bk;

    // --- ldmatrix lane base addresses (stage 0, part hi) ---
    const unsigned aBase = su32(&As[0][0][wm + (lane & 15)][(lane >> 4) * 8]);
    const int bn = wn + (lane & 7) + ((lane >> 1) & 8);
    const unsigned bBase = su32(&Bs[0][0][bn][lane & 8]);
    // strides (bytes): A stage 6144, part 3072; B stage 12288, part 6144; +16rows = 768

    const int nt = K >> 4;

    // prologue: tile 0 regs -> stage into buf 0; prefetch tile 1 regs
    float4 av  = aptr ? *(const float4*)aptr : make_float4(0.f, 0.f, 0.f, 0.f);
    float4 bv0 = *(const float4*)bptr;
    float4 bv1 = *(const float4*)(bptr + 4);
    {
        unsigned h0, l0, h1, l1;
        split2(av.x, av.y, h0, l0); split2(av.z, av.w, h1, l1);
        *(uint2*)&As[0][0][ar][ak] = make_uint2(h0, h1);
        *(uint2*)&As[0][1][ar][ak] = make_uint2(l0, l1);
        unsigned p0h, p0l, p1h, p1l, p2h, p2l, p3h, p3l;
        split2(bv0.x, bv0.y, p0h, p0l); split2(bv0.z, bv0.w, p1h, p1l);
        split2(bv1.x, bv1.y, p2h, p2l); split2(bv1.z, bv1.w, p3h, p3l);
        *(uint4*)&Bs[0][0][br][bk] = make_uint4(p0h, p1h, p2h, p3h);
        *(uint4*)&Bs[0][1][br][bk] = make_uint4(p0l, p1l, p2l, p3l);
    }
    if (nt > 1) {
        av  = aptr ? *(const float4*)(aptr + 16) : make_float4(0.f, 0.f, 0.f, 0.f);
        bv0 = *(const float4*)(bptr + 16);
        bv1 = *(const float4*)(bptr + 20);
    }
    __syncthreads();

    for (int t = 0; t < nt; t++) {
        const int p = t & 1;
        const unsigned aHi = aBase + p * 6144;
        const unsigned bHi = bBase + p * 12288;
        unsigned Ah[2][4], Al[2][4], Bh[2][4], Bl[2][4];
        ldsm4(Ah[0], aHi);          ldsm4(Ah[1], aHi + 768);
        ldsm4(Al[0], aHi + 3072);   ldsm4(Al[1], aHi + 3072 + 768);
        ldsm4(Bh[0], bHi);          ldsm4(Bh[1], bHi + 768);
        ldsm4(Bl[0], bHi + 6144);   ldsm4(Bl[1], bHi + 6144 + 768);

        // stage tile t+1 into the other buffer (independent of this tile's MMA;
        // ptxas interleaves this ALU/STS stream into HMMA gaps)
        if (t + 1 < nt) {
            const int q = p ^ 1;
            unsigned h0, l0, h1, l1;
            split2(av.x, av.y, h0, l0); split2(av.z, av.w, h1, l1);
            *(uint2*)&As[q][0][ar][ak] = make_uint2(h0, h1);
            *(uint2*)&As[q][1][ar][ak] = make_uint2(l0, l1);
            unsigned p0h, p0l, p1h, p1l, p2h, p2l, p3h, p3l;
            split2(bv0.x, bv0.y, p0h, p0l); split2(bv0.z, bv0.w, p1h, p1l);
            split2(bv1.x, bv1.y, p2h, p2l); split2(bv1.z, bv1.w, p3h, p3l);
            *(uint4*)&Bs[q][0][br][bk] = make_uint4(p0h, p1h, p2h, p3h);
            *(uint4*)&Bs[q][1][br][bk] = make_uint4(p0l, p1l, p2l, p3l);
            if (t + 2 < nt) {  // prefetch tile t+2 into regs (2-tile LDG distance)
                const int ko = (t + 2) * 16;
                av  = aptr ? *(const float4*)(aptr + ko) : make_float4(0.f, 0.f, 0.f, 0.f);
                bv0 = *(const float4*)(bptr + ko);
                bv1 = *(const float4*)(bptr + ko + 4);
            }
        }

#pragma unroll
        for (int i = 0; i < 2; i++)
#pragma unroll
            for (int j = 0; j < 4; j++) {
                const unsigned* bh = &Bh[j >> 1][(j & 1) * 2];
                const unsigned* bl = &Bl[j >> 1][(j & 1) * 2];
                mma16816(acc[i][j], Ah[i], bh);   // hi*hi
                mma16816(acc[i][j], Ah[i], bl);   // hi*lo
                mma16816(acc[i][j], Al[i], bh);   // lo*hi
            }
        __syncthreads();
    }
}

// ---------------- fused QKV: grid (6, 8, 3) -----------------------------------
__global__ __launch_bounds__(256) void qkv_mma(
    const float* __restrict__ wq, const float* __restrict__ wk,
    const float* __restrict__ wv)
{
    const float* W = (blockIdx.z == 0) ? wq : (blockIdx.z == 1) ? wk : wv;
    float* out = (blockIdx.z == 0) ? g_q : (blockIdx.z == 1) ? g_k : g_v;
    float acc[2][4][4] = {};
    mma_gemm_core(g_x, NE, nullptr, NTOK, blockIdx.y, W, blockIdx.x, NE, acc);
    const int lane = threadIdx.x & 31, warp = threadIdx.x >> 5;
    const int m0 = blockIdx.y * 64 + (warp >> 2) * 32 + (lane >> 2);
    const int n0 = blockIdx.x * 128 + (warp & 3) * 32 + (lane & 3) * 2;
#pragma unroll
    for (int i = 0; i < 2; i++)
#pragma unroll
        for (int j = 0; j < 4; j++) {
            int m = m0 + i * 16, n = n0 + j * 8;
            *(float2*)&out[m * NE + n]       = make_float2(acc[i][j][0], acc[i][j][1]);
            *(float2*)&out[(m + 8) * NE + n] = make_float2(acc[i][j][2], acc[i][j][3]);
        }
}

// ---------------- output projection: grid (6, 8) -----------------------------
__global__ __launch_bounds__(256) void proj_mma(
    const float* __restrict__ wp, const float* __restrict__ bp)
{
    float acc[2][4][4] = {};
    mma_gemm_core(g_o, NE, nullptr, NTOK, blockIdx.y, wp, blockIdx.x, NE, acc);
    const int lane = threadIdx.x & 31, warp = threadIdx.x >> 5;
    const int m0 = blockIdx.y * 64 + (warp >> 2) * 32 + (lane >> 2);
    const int n0 = blockIdx.x * 128 + (warp & 3) * 32 + (lane & 3) * 2;
#pragma unroll
    for (int i = 0; i < 2; i++)
#pragma unroll
        for (int j = 0; j < 4; j++) {
            int m = m0 + i * 16, n = n0 + j * 8;
            float b0 = bp[n], b1 = bp[n + 1];
            *(float2*)&g_y[m * NE + n]       = make_float2(acc[i][j][0] + b0, acc[i][j][1] + b1);
            *(float2*)&g_y[(m + 8) * NE + n] = make_float2(acc[i][j][2] + b0, acc[i][j][3] + b1);
        }
}

// ---------------- expert GEMM1: h = gelu(x_gather @ w1^T + b1); grid(24,8,8) --
__global__ __launch_bounds__(256) void moe_g1_mma(
    const float* __restrict__ w1l, const float* __restrict__ b1l)
{
    const int e = blockIdx.z;
    const int ne = g_cnt[e];
    if ((int)(blockIdx.y * 64) >= ne) return;
    float acc[2][4][4] = {};
    mma_gemm_core(g_x, NE, g_tok + e * NTOK, ne, blockIdx.y,
                  w1l + (size_t)e * DFF * NE, blockIdx.x, NE, acc);
    const int lane = threadIdx.x & 31, warp = threadIdx.x >> 5;
    const int m0 = blockIdx.y * 64 + (warp >> 2) * 32 + (lane >> 2);
    const int n0 = blockIdx.x * 128 + (warp & 3) * 32 + (lane & 3) * 2;
    float* hb = g_h + (size_t)e * NTOK * DFF;
#pragma unroll
    for (int i = 0; i < 2; i++)
#pragma unroll
        for (int j = 0; j < 4; j++) {
            int n = n0 + j * 8;
            float b0 = b1l[e * DFF + n], b1 = b1l[e * DFF + n + 1];
#pragma unroll
            for (int half = 0; half < 2; half++) {
                int m = m0 + i * 16 + half * 8;
                if (m < ne) {
                    float v0 = acc[i][j][half * 2 + 0] + b0;
                    float v1 = acc[i][j][half * 2 + 1] + b1;
                    v0 = 0.5f * v0 * (1.f + erff(v0 * 0.70710678118654752f));
                    v1 = 0.5f * v1 * (1.f + erff(v1 * 0.70710678118654752f));
                    *(float2*)&hb[(size_t)m * DFF + n] = make_float2(v0, v1);
                }
            }
        }
}

// ---------------- expert GEMM2: y_slot = p*(h @ w2^T + b2); grid(6,8,8) -------
__global__ __launch_bounds__(256) void moe_g2_mma(
    const float* __restrict__ w2l, const float* __restrict__ b2l)
{
    const int e = blockIdx.z;
    const int ne = g_cnt[e];
    if ((int)(blockIdx.y * 64) >= ne) return;
    float acc[2][4][4] = {};
    mma_gemm_core(g_h + (size_t)e * NTOK * DFF, DFF, nullptr, ne, blockIdx.y,
                  w2l + (size_t)e * NE * DFF, blockIdx.x, DFF, acc);
    const int lane = threadIdx.x & 31, warp = threadIdx.x >> 5;
    const int m0 = blockIdx.y * 64 + (warp >> 2) * 32 + (lane >> 2);
    const int n0 = blockIdx.x * 128 + (warp & 3) * 32 + (lane & 3) * 2;
#pragma unroll
    for (int i = 0; i < 2; i++)
#pragma unroll
        for (int j = 0; j < 4; j++) {
            int n = n0 + j * 8;
            float b0 = b2l[e * NE + n], b1 = b2l[e * NE + n + 1];
#pragma unroll
            for (int half = 0; half < 2; half++) {
                int m = m0 + i * 16 + half * 8;
                if (m < ne) {
                    int tok = g_tok[e * NTOK + m];
                    int sl  = g_slot[e * NTOK + m];
                    float p = g_pw[e * NTOK + m];
                    float* dst = g_yslot + (size_t)sl * NTOK * NE + (size_t)tok * NE;
                    *(float2*)&dst[n] = make_float2(p * (acc[i][j][half * 2 + 0] + b0),
                                                    p * (acc[i][j][half * 2 + 1] + b1));
                }
            }
        }
}

// ---------------- embed ------------------------------------------------------
__global__ void embed_kernel(const int* __restrict__ idx,
                             const float* __restrict__ te,
                             const float* __restrict__ pe) {
    int t = blockIdx.x;
    int id = idx[t];
    int pp = t & (TT - 1);
    for (int c = threadIdx.x; c < NE; c += blockDim.x)
        g_x[t * NE + c] = te[id * NE + c] + pe[pp * NE + c];
}

// ---------------- attention core: grid (B*H=64, 2), 256 thr, dyn smem --------
__global__ __launch_bounds__(256) void attn_kernel() {
    extern __shared__ float sm[];
    float* sq = sm;                 // 32*96
    float* sk = sq + 32 * HD;       // 64*96
    float* sv = sk + 64 * HD;       // 64*96
    float* ss = sv + 64 * HD;       // 32*64
    const int b = blockIdx.x >> 3, h = blockIdx.x & 7;
    const int t0 = blockIdx.y * 32;
    const int base = b * TT;
    const int tid = threadIdx.x;
    const int col0 = h * HD;

    for (int i = tid; i < 64 * HD; i += 256) {
        int t = i / HD, d = i - t * HD;
        sk[i] = g_k[(base + t) * NE + col0 + d];
        sv[i] = g_v[(base + t) * NE + col0 + d];
    }
    for (int i = tid; i < 32 * HD; i += 256) {
        int t = i / HD, d = i - t * HD;
        sq[i] = g_q[(base + t0 + t) * NE + col0 + d];
    }
    __syncthreads();

    const float scale = 0.10206207261596575f;  // 96^-0.5
    for (int e = tid; e < 32 * 64; e += 256) {
        int t = e >> 6, s = e & 63;
        float a = 0.f;
        if (s <= t0 + t) {
            const float* qp = sq + t * HD;
            const float* kp = sk + s * HD;
#pragma unroll 8
            for (int d = 0; d < HD; d++) a += qp[d] * kp[d];
            a *= scale;
        }
        ss[e] = a;
    }
    __syncthreads();

    if (tid < 32) {
        int lim = t0 + tid;
        float m = -1e30f;
        for (int s = 0; s <= lim; s++) m = fmaxf(m, ss[tid * 64 + s]);
        float sum = 0.f;
        for (int s = 0; s < 64; s++) {
            float v = (s <= lim) ? expf(ss[tid * 64 + s] - m) : 0.f;
            ss[tid * 64 + s] = v;
            sum += v;
        }
        float inv = 1.f / sum;
        for (int s = 0; s < 64; s++) ss[tid * 64 + s] *= inv;
    }
    __syncthreads();

    for (int i = tid; i < 32 * HD; i += 256) {
        int t = i / HD, d = i - t * HD;
        const float* ps = ss + t * 64;
        float a = 0.f;
#pragma unroll 8
        for (int s = 0; s < 64; s++) a += ps[s] * sv[s * HD + d];
        g_o[(base + t0 + t) * NE + col0 + d] = a;
    }
}

// ------ residual add + layernorm (+ fused MoE gate logits when mode==1) ------
// mode: 0 none, 1 +g_y then gate, 2 +yslots
__global__ __launch_bounds__(256) void addln_kernel(
    const float* __restrict__ w, const float* __restrict__ bb, int mode,
    const float* __restrict__ gw, const float* __restrict__ gb)
{
    __shared__ float xs[NE];
    const int t = blockIdx.x, tid = threadIdx.x;
    float v[3];
    float s = 0.f, s2 = 0.f;
#pragma unroll
    for (int j = 0; j < 3; j++) {
        int c = tid + j * 256;
        float x = g_x[t * NE + c];
        if (mode == 1) x += g_y[t * NE + c];
        else if (mode == 2) x += g_yslot[t * NE + c] + g_yslot[NTOK * NE + t * NE + c];
        v[j] = x; s += x; s2 += x * x;
    }
#pragma unroll
    for (int o = 16; o; o >>= 1) {
        s  += __shfl_down_sync(0xffffffffu, s,  o);
        s2 += __shfl_down_sync(0xffffffffu, s2, o);
    }
    __shared__ float rs[8], rs2[8], smv[2];
    const int wp = tid >> 5, lane = tid & 31;
    if (lane == 0) { rs[wp] = s; rs2[wp] = s2; }
    __syncthreads();
    if (tid == 0) {
        float a = 0.f, b2 = 0.f;
#pragma unroll
        for (int i = 0; i < 8; i++) { a += rs[i]; b2 += rs2[i]; }
        float mean = a * (1.f / NE);
        float var = b2 * (1.f / NE) - mean * mean;
        smv[0] = mean;
        smv[1] = rsqrtf(var + 1e-5f);
    }
    __syncthreads();
    const float mean = smv[0], r = smv[1];
#pragma unroll
    for (int j = 0; j < 3; j++) {
        int c = tid + j * 256;
        float val = (v[j] - mean) * r * w[c] + bb[c];
        g_x[t * NE + c] = val;
        xs[c] = val;
    }
    if (mode == 1) {   // fused gate logits: warp wp -> expert wp
        __syncthreads();
        const float* gr = gw + wp * NE;
        float a = 0.f;
        for (int c = lane; c < NE; c += 32) a += xs[c] * gr[c];
#pragma unroll
        for (int o = 16; o; o >>= 1) a += __shfl_down_sync(0xffffffffu, a, o);
        if (lane == 0) g_logits[t * NEXP + wp] = a + gb[wp];
    }
}

// ---- top-2 + renorm + per-expert token lists. single block, 512 threads ----
__global__ __launch_bounds__(512) void route_b() {
    __shared__ int scnt[NEXP];
    const int tid = threadIdx.x;
    if (tid < NEXP) scnt[tid] = 0;
    __syncthreads();

    float lg[NEXP];
    float m = -1e30f;
#pragma unroll
    for (int e = 0; e < NEXP; e++) { lg[e] = g_logits[tid * NEXP + e]; m = fmaxf(m, lg[e]); }
#pragma unroll
    for (int e = 0; e < NEXP; e++) lg[e] = expf(lg[e] - m);

    int i0 = 0;
#pragma unroll
    for (int e = 1; e < NEXP; e++) if (lg[e] > lg[i0]) i0 = e;
    int i1 = (i0 == 0) ? 1 : 0;
#pragma unroll
    for (int e = 0; e < NEXP; e++) if (e != i0 && lg[e] > lg[i1]) i1 = e;

    const float inv = 1.f / (lg[i0] + lg[i1]);
    const float p0 = lg[i0] * inv, p1 = lg[i1] * inv;

    int pos0 = atomicAdd(&scnt[i0], 1);
    g_tok[i0 * NTOK + pos0] = tid; g_slot[i0 * NTOK + pos0] = 0; g_pw[i0 * NTOK + pos0] = p0;
    int pos1 = atomicAdd(&scnt[i1], 1);
    g_tok[i1 * NTOK + pos1] = tid; g_slot[i1 * NTOK + pos1] = 1; g_pw[i1 * NTOK + pos1] = p1;

    __syncthreads();
    if (tid < NEXP) g_cnt[tid] = scnt[tid];
}

// ---------------- LM head: logits = x @ lm_w^T + lm_b ------------------------
__global__ __launch_bounds__(128) void lm_kernel(
    const float* __restrict__ lw, const float* __restrict__ lb,
    float* __restrict__ out)
{
    __shared__ float xr[NE];
    const int t = blockIdx.x, tid = threadIdx.x;
    for (int c = tid; c < NE; c += 128) xr[c] = g_x[t * NE + c];
    __syncthreads();
    if (tid < NVOCAB) {
        const float* wr = lw + (size_t)tid * NE;
        float a = lb[tid];
#pragma unroll 8
        for (int c = 0; c < NE; c++) a += xr[c] * wr[c];
        out[t * NVOCAB + tid] = a;
    }
}

// ---------------- launch -----------------------------------------------------
extern "C" void kernel_launch(void* const* d_in, const int* in_sizes, int n_in,
                              void* d_out, int out_size) {
    (void)in_sizes; (void)n_in; (void)out_size;
    const int*   idx     = (const int*)  d_in[0];
    const float* tok_emb = (const float*)d_in[1];
    const float* pos_emb = (const float*)d_in[2];
    const float* wq      = (const float*)d_in[3];
    const float* wk      = (const float*)d_in[4];
    const float* wv      = (const float*)d_in[5];
    const float* wproj   = (const float*)d_in[6];
    const float* bproj   = (const float*)d_in[7];
    const float* gate_w  = (const float*)d_in[8];
    const float* gate_b  = (const float*)d_in[9];
    const float* w1      = (const float*)d_in[10];
    const float* b1      = (const float*)d_in[11];
    const float* w2      = (const float*)d_in[12];
    const float* b2      = (const float*)d_in[13];
    const float* ln1_w   = (const float*)d_in[14];
    const float* ln1_b   = (const float*)d_in[15];
    const float* ln2_w   = (const float*)d_in[16];
    const float* ln2_b   = (const float*)d_in[17];
    const float* lnf_w   = (const float*)d_in[18];
    const float* lnf_b   = (const float*)d_in[19];
    const float* lm_w    = (const float*)d_in[20];
    const float* lm_b    = (const float*)d_in[21];
    float* out = (float*)d_out;

    const int ATTN_SMEM = (32 * HD + 64 * HD + 64 * HD + 32 * 64) * 4;  // 69632 B
    cudaFuncSetAttribute(attn_kernel, cudaFuncAttributeMaxDynamicSharedMemorySize, ATTN_SMEM);

    embed_kernel<<<NTOK, 256>>>(idx, tok_emb, pos_emb);

    for (int l = 0; l < NLAYER; l++) {
        const size_t offW  = (size_t)l * NH * HD * NE;      // 589824
        const size_t offM1 = (size_t)l * NEXP * DFF * NE;   // w1/w2 per layer
        qkv_mma<<<dim3(6, 8, 3), 256>>>(wq + offW, wk + offW, wv + offW);
        attn_kernel<<<dim3(64, 2), 256, ATTN_SMEM>>>();
        proj_mma<<<dim3(6, 8), 256>>>(wproj + offW, bproj + (size_t)l * NE);
        // post-norm + fused gate logits
        addln_kernel<<<NTOK, 256>>>(ln1_w + (size_t)l * NE, ln1_b + (size_t)l * NE, 1,
                                    gate_w + (size_t)l * NEXP * NE,
                                    gate_b + (size_t)l * NEXP);
        route_b<<<1, 512>>>();
        moe_g1_mma<<<dim3(24, 8, NEXP), 256>>>(w1 + offM1, b1 + (size_t)l * NEXP * DFF);
        moe_g2_mma<<<dim3(6, 8, NEXP), 256>>>(w2 + offM1, b2 + (size_t)l * NEXP * NE);
        addln_kernel<<<NTOK, 256>>>(ln2_w + (size_t)l * NE, ln2_b + (size_t)l * NE, 2,
                                    nullptr, nullptr);
    }

    addln_kernel<<<NTOK, 256>>>(lnf_w, lnf_b, 0, nullptr, nullptr);
    lm_kernel<<<NTOK, 128>>>(lm_w, lm_b, out);
}

// round 9
// speedup vs baseline: 2.0501x; 1.0006x over previous
#include <cuda_runtime.h>
#include <cuda_bf16.h>
#include <math.h>

#define NTOK   512          // B*T = 8*64
#define NE     768          // n_embd
#define NH     8            // heads
#define HD     96           // head dim
#define DFF    3072
#define NEXP   8
#define NLAYER 12
#define NVOCAB 99
#define TT     64           // seq len

// ---------------- scratch (static device globals; no allocation) -------------
__device__ float g_x[NTOK * NE];
__device__ float g_q[NTOK * NE];
__device__ float g_k[NTOK * NE];
__device__ float g_v[NTOK * NE];
__device__ float g_o[NTOK * NE];
__device__ float g_y[NTOK * NE];
__device__ float g_h[(size_t)NEXP * NTOK * DFF];   // ~50 MB expert hidden
__device__ float g_yslot[2 * NTOK * NE];           // per-slot MoE outputs
__device__ float g_logits[NTOK * NEXP];
__device__ int   g_cnt[NEXP];
__device__ int   g_tok[NEXP * NTOK];
__device__ int   g_slot[NEXP * NTOK];
__device__ float g_pw[NEXP * NTOK];

// ---------------- small helpers ----------------------------------------------
__device__ __forceinline__ unsigned su32(const void* p) {
    return (unsigned)__cvta_generic_to_shared(p);
}

__device__ __forceinline__ void ldsm4(unsigned* r, unsigned addr) {
    asm volatile("ldmatrix.sync.aligned.m8n8.x4.shared.b16 {%0,%1,%2,%3}, [%4];"
        : "=r"(r[0]), "=r"(r[1]), "=r"(r[2]), "=r"(r[3]) : "r"(addr));
}

__device__ __forceinline__ void mma16816(float* c, const unsigned* a, const unsigned* b) {
    asm volatile(
        "mma.sync.aligned.m16n8k16.row.col.f32.bf16.bf16.f32 "
        "{%0,%1,%2,%3}, {%4,%5,%6,%7}, {%8,%9}, {%0,%1,%2,%3};\n"
        : "+f"(c[0]), "+f"(c[1]), "+f"(c[2]), "+f"(c[3])
        : "r"(a[0]), "r"(a[1]), "r"(a[2]), "r"(a[3]), "r"(b[0]), "r"(b[1]));
}

// split 2 fp32 into packed bf16 hi pair + bf16 lo pair (lo = x - float(hi))
__device__ __forceinline__ void split2(float x0, float x1, unsigned& hi, unsigned& lo) {
    __nv_bfloat162 h = __floats2bfloat162_rn(x0, x1);
    float2 hf = __bfloat1622float2(h);
    __nv_bfloat162 l = __floats2bfloat162_rn(x0 - hf.x, x1 - hf.y);
    hi = *reinterpret_cast<unsigned*>(&h);
    lo = *reinterpret_cast<unsigned*>(&l);
}

// ---------------- tensor-core GEMM core: C = A @ W^T (fp32-in/out, bf16x3) ----
// Block tile 64(M) x 128(N), BK=16, DOUBLE-BUFFERED smem, 256 threads = 8 warps
// (2M x 4N), warp tile 32x32. A: [mrows, lda] fp32 row-major (optional gather).
// W: [N, K] fp32 row-major (rows K-major = col-major B => "row.col" mma).
__device__ __forceinline__ void mma_gemm_core(
    const float* __restrict__ Abase, int lda,
    const int* __restrict__ rowmap, int mrows, int mTile,
    const float* __restrict__ W, int nTile, int K,
    float (&acc)[2][4][4])
{
    // [stage][part hi/lo][row][16k + pad8] ; row stride 48B (conflict-free LDSM)
    __shared__ __align__(16) __nv_bfloat16 As[2][2][64][24];    // 12 KB
    __shared__ __align__(16) __nv_bfloat16 Bs[2][2][128][24];   // 24 KB

    const int tx = threadIdx.x;
    const int warp = tx >> 5, lane = tx & 31;
    const int wm = (warp >> 2) * 32;   // warp M offset
    const int wn = (warp & 3) * 32;    // warp N offset

    // --- staging assignments ---
    const int ar = tx >> 2;            // A row 0..63
    const int ak = (tx & 3) << 2;      // k offset {0,4,8,12}
    const int grow = mTile * 64 + ar;
    const float* aptr = nullptr;
    if (grow < mrows) {
        int src = rowmap ? rowmap[grow] : grow;
        aptr = Abase + (size_t)src * lda + ak;
    }
    const int br = tx >> 1;            // B row 0..127
    const int bk = (tx & 1) << 3;      // k offset {0,8}
    const float* bptr = W + (size_t)(nTile * 128 + br) * K + bk;

    // --- ldmatrix lane base addresses (stage 0, part hi) ---
    const unsigned aBase = su32(&As[0][0][wm + (lane & 15)][(lane >> 4) * 8]);
    const int bn = wn + (lane & 7) + ((lane >> 1) & 8);
    const unsigned bBase = su32(&Bs[0][0][bn][lane & 8]);
    // strides (bytes): A stage 6144, part 3072; B stage 12288, part 6144; +16rows = 768

    const int nt = K >> 4;

    // prologue: tile 0 regs -> stage into buf 0; prefetch tile 1 regs
    float4 av  = aptr ? *(const float4*)aptr : make_float4(0.f, 0.f, 0.f, 0.f);
    float4 bv0 = *(const float4*)bptr;
    float4 bv1 = *(const float4*)(bptr + 4);
    {
        unsigned h0, l0, h1, l1;
        split2(av.x, av.y, h0, l0); split2(av.z, av.w, h1, l1);
        *(uint2*)&As[0][0][ar][ak] = make_uint2(h0, h1);
        *(uint2*)&As[0][1][ar][ak] = make_uint2(l0, l1);
        unsigned p0h, p0l, p1h, p1l, p2h, p2l, p3h, p3l;
        split2(bv0.x, bv0.y, p0h, p0l); split2(bv0.z, bv0.w, p1h, p1l);
        split2(bv1.x, bv1.y, p2h, p2l); split2(bv1.z, bv1.w, p3h, p3l);
        *(uint4*)&Bs[0][0][br][bk] = make_uint4(p0h, p1h, p2h, p3h);
        *(uint4*)&Bs[0][1][br][bk] = make_uint4(p0l, p1l, p2l, p3l);
    }
    if (nt > 1) {
        av  = aptr ? *(const float4*)(aptr + 16) : make_float4(0.f, 0.f, 0.f, 0.f);
        bv0 = *(const float4*)(bptr + 16);
        bv1 = *(const float4*)(bptr + 20);
    }
    __syncthreads();

    for (int t = 0; t < nt; t++) {
        const int p = t & 1;
        const unsigned aHi = aBase + p * 6144;
        const unsigned bHi = bBase + p * 12288;
        unsigned Ah[2][4], Al[2][4], Bh[2][4], Bl[2][4];
        ldsm4(Ah[0], aHi);          ldsm4(Ah[1], aHi + 768);
        ldsm4(Al[0], aHi + 3072);   ldsm4(Al[1], aHi + 3072 + 768);
        ldsm4(Bh[0], bHi);          ldsm4(Bh[1], bHi + 768);
        ldsm4(Bl[0], bHi + 6144);   ldsm4(Bl[1], bHi + 6144 + 768);

        // stage tile t+1 into the other buffer (independent of this tile's MMA;
        // ptxas interleaves this ALU/STS stream into HMMA gaps)
        if (t + 1 < nt) {
            const int q = p ^ 1;
            unsigned h0, l0, h1, l1;
            split2(av.x, av.y, h0, l0); split2(av.z, av.w, h1, l1);
            *(uint2*)&As[q][0][ar][ak] = make_uint2(h0, h1);
            *(uint2*)&As[q][1][ar][ak] = make_uint2(l0, l1);
            unsigned p0h, p0l, p1h, p1l, p2h, p2l, p3h, p3l;
            split2(bv0.x, bv0.y, p0h, p0l); split2(bv0.z, bv0.w, p1h, p1l);
            split2(bv1.x, bv1.y, p2h, p2l); split2(bv1.z, bv1.w, p3h, p3l);
            *(uint4*)&Bs[q][0][br][bk] = make_uint4(p0h, p1h, p2h, p3h);
            *(uint4*)&Bs[q][1][br][bk] = make_uint4(p0l, p1l, p2l, p3l);
            if (t + 2 < nt) {  // prefetch tile t+2 into regs (2-tile LDG distance)
                const int ko = (t + 2) * 16;
                av  = aptr ? *(const float4*)(aptr + ko) : make_float4(0.f, 0.f, 0.f, 0.f);
                bv0 = *(const float4*)(bptr + ko);
                bv1 = *(const float4*)(bptr + ko + 4);
            }
        }

#pragma unroll
        for (int i = 0; i < 2; i++)
#pragma unroll
            for (int j = 0; j < 4; j++) {
                const unsigned* bh = &Bh[j >> 1][(j & 1) * 2];
                const unsigned* bl = &Bl[j >> 1][(j & 1) * 2];
                mma16816(acc[i][j], Ah[i], bh);   // hi*hi
                mma16816(acc[i][j], Ah[i], bl);   // hi*lo
                mma16816(acc[i][j], Al[i], bh);   // lo*hi
            }
        __syncthreads();
    }
}

// ---------------- fused QKV: grid (6, 8, 3) -----------------------------------
__global__ __launch_bounds__(256) void qkv_mma(
    const float* __restrict__ wq, const float* __restrict__ wk,
    const float* __restrict__ wv)
{
    const float* W = (blockIdx.z == 0) ? wq : (blockIdx.z == 1) ? wk : wv;
    float* out = (blockIdx.z == 0) ? g_q : (blockIdx.z == 1) ? g_k : g_v;
    float acc[2][4][4] = {};
    mma_gemm_core(g_x, NE, nullptr, NTOK, blockIdx.y, W, blockIdx.x, NE, acc);
    const int lane = threadIdx.x & 31, warp = threadIdx.x >> 5;
    const int m0 = blockIdx.y * 64 + (warp >> 2) * 32 + (lane >> 2);
    const int n0 = blockIdx.x * 128 + (warp & 3) * 32 + (lane & 3) * 2;
#pragma unroll
    for (int i = 0; i < 2; i++)
#pragma unroll
        for (int j = 0; j < 4; j++) {
            int m = m0 + i * 16, n = n0 + j * 8;
            *(float2*)&out[m * NE + n]       = make_float2(acc[i][j][0], acc[i][j][1]);
            *(float2*)&out[(m + 8) * NE + n] = make_float2(acc[i][j][2], acc[i][j][3]);
        }
}

// ---------------- output projection: grid (6, 8) -----------------------------
__global__ __launch_bounds__(256) void proj_mma(
    const float* __restrict__ wp, const float* __restrict__ bp)
{
    float acc[2][4][4] = {};
    mma_gemm_core(g_o, NE, nullptr, NTOK, blockIdx.y, wp, blockIdx.x, NE, acc);
    const int lane = threadIdx.x & 31, warp = threadIdx.x >> 5;
    const int m0 = blockIdx.y * 64 + (warp >> 2) * 32 + (lane >> 2);
    const int n0 = blockIdx.x * 128 + (warp & 3) * 32 + (lane & 3) * 2;
#pragma unroll
    for (int i = 0; i < 2; i++)
#pragma unroll
        for (int j = 0; j < 4; j++) {
            int m = m0 + i * 16, n = n0 + j * 8;
            float b0 = bp[n], b1 = bp[n + 1];
            *(float2*)&g_y[m * NE + n]       = make_float2(acc[i][j][0] + b0, acc[i][j][1] + b1);
            *(float2*)&g_y[(m + 8) * NE + n] = make_float2(acc[i][j][2] + b0, acc[i][j][3] + b1);
        }
}

// ---------------- expert GEMM1: h = gelu(x_gather @ w1^T + b1); grid(24,8,8) --
__global__ __launch_bounds__(256) void moe_g1_mma(
    const float* __restrict__ w1l, const float* __restrict__ b1l)
{
    const int e = blockIdx.z;
    const int ne = g_cnt[e];
    if ((int)(blockIdx.y * 64) >= ne) return;
    float acc[2][4][4] = {};
    mma_gemm_core(g_x, NE, g_tok + e * NTOK, ne, blockIdx.y,
                  w1l + (size_t)e * DFF * NE, blockIdx.x, NE, acc);
    const int lane = threadIdx.x & 31, warp = threadIdx.x >> 5;
    const int m0 = blockIdx.y * 64 + (warp >> 2) * 32 + (lane >> 2);
    const int n0 = blockIdx.x * 128 + (warp & 3) * 32 + (lane & 3) * 2;
    float* hb = g_h + (size_t)e * NTOK * DFF;
#pragma unroll
    for (int i = 0; i < 2; i++)
#pragma unroll
        for (int j = 0; j < 4; j++) {
            int n = n0 + j * 8;
            float b0 = b1l[e * DFF + n], b1 = b1l[e * DFF + n + 1];
#pragma unroll
            for (int half = 0; half < 2; half++) {
                int m = m0 + i * 16 + half * 8;
                if (m < ne) {
                    float v0 = acc[i][j][half * 2 + 0] + b0;
                    float v1 = acc[i][j][half * 2 + 1] + b1;
                    v0 = 0.5f * v0 * (1.f + erff(v0 * 0.70710678118654752f));
                    v1 = 0.5f * v1 * (1.f + erff(v1 * 0.70710678118654752f));
                    *(float2*)&hb[(size_t)m * DFF + n] = make_float2(v0, v1);
                }
            }
        }
}

// ---------------- expert GEMM2: y_slot = p*(h @ w2^T + b2); grid(6,8,8) -------
__global__ __launch_bounds__(256) void moe_g2_mma(
    const float* __restrict__ w2l, const float* __restrict__ b2l)
{
    const int e = blockIdx.z;
    const int ne = g_cnt[e];
    if ((int)(blockIdx.y * 64) >= ne) return;
    float acc[2][4][4] = {};
    mma_gemm_core(g_h + (size_t)e * NTOK * DFF, DFF, nullptr, ne, blockIdx.y,
                  w2l + (size_t)e * NE * DFF, blockIdx.x, DFF, acc);
    const int lane = threadIdx.x & 31, warp = threadIdx.x >> 5;
    const int m0 = blockIdx.y * 64 + (warp >> 2) * 32 + (lane >> 2);
    const int n0 = blockIdx.x * 128 + (warp & 3) * 32 + (lane & 3) * 2;
#pragma unroll
    for (int i = 0; i < 2; i++)
#pragma unroll
        for (int j = 0; j < 4; j++) {
            int n = n0 + j * 8;
            float b0 = b2l[e * NE + n], b1 = b2l[e * NE + n + 1];
#pragma unroll
            for (int half = 0; half < 2; half++) {
                int m = m0 + i * 16 + half * 8;
                if (m < ne) {
                    int tok = g_tok[e * NTOK + m];
                    int sl  = g_slot[e * NTOK + m];
                    float p = g_pw[e * NTOK + m];
                    float* dst = g_yslot + (size_t)sl * NTOK * NE + (size_t)tok * NE;
                    *(float2*)&dst[n] = make_float2(p * (acc[i][j][half * 2 + 0] + b0),
                                                    p * (acc[i][j][half * 2 + 1] + b1));
                }
            }
        }
}

// ---------------- embed ------------------------------------------------------
__global__ void embed_kernel(const int* __restrict__ idx,
                             const float* __restrict__ te,
                             const float* __restrict__ pe) {
    int t = blockIdx.x;
    int id = idx[t];
    int pp = t & (TT - 1);
    for (int c = threadIdx.x; c < NE; c += blockDim.x)
        g_x[t * NE + c] = te[id * NE + c] + pe[pp * NE + c];
}

// ---------------- attention core: grid (B*H=64, 2), 256 thr, dyn smem --------
__global__ __launch_bounds__(256) void attn_kernel() {
    extern __shared__ float sm[];
    float* sq = sm;                 // 32*96
    float* sk = sq + 32 * HD;       // 64*96
    float* sv = sk + 64 * HD;       // 64*96
    float* ss = sv + 64 * HD;       // 32*64
    const int b = blockIdx.x >> 3, h = blockIdx.x & 7;
    const int t0 = blockIdx.y * 32;
    const int base = b * TT;
    const int tid = threadIdx.x;
    const int col0 = h * HD;

    for (int i = tid; i < 64 * HD; i += 256) {
        int t = i / HD, d = i - t * HD;
        sk[i] = g_k[(base + t) * NE + col0 + d];
        sv[i] = g_v[(base + t) * NE + col0 + d];
    }
    for (int i = tid; i < 32 * HD; i += 256) {
        int t = i / HD, d = i - t * HD;
        sq[i] = g_q[(base + t0 + t) * NE + col0 + d];
    }
    __syncthreads();

    const float scale = 0.10206207261596575f;  // 96^-0.5
    for (int e = tid; e < 32 * 64; e += 256) {
        int t = e >> 6, s = e & 63;
        float a = 0.f;
        if (s <= t0 + t) {
            const float* qp = sq + t * HD;
            const float* kp = sk + s * HD;
#pragma unroll 8
            for (int d = 0; d < HD; d++) a += qp[d] * kp[d];
            a *= scale;
        }
        ss[e] = a;
    }
    __syncthreads();

    if (tid < 32) {
        int lim = t0 + tid;
        float m = -1e30f;
        for (int s = 0; s <= lim; s++) m = fmaxf(m, ss[tid * 64 + s]);
        float sum = 0.f;
        for (int s = 0; s < 64; s++) {
            float v = (s <= lim) ? expf(ss[tid * 64 + s] - m) : 0.f;
            ss[tid * 64 + s] = v;
            sum += v;
        }
        float inv = 1.f / sum;
        for (int s = 0; s < 64; s++) ss[tid * 64 + s] *= inv;
    }
    __syncthreads();

    for (int i = tid; i < 32 * HD; i += 256) {
        int t = i / HD, d = i - t * HD;
        const float* ps = ss + t * 64;
        float a = 0.f;
#pragma unroll 8
        for (int s = 0; s < 64; s++) a += ps[s] * sv[s * HD + d];
        g_o[(base + t0 + t) * NE + col0 + d] = a;
    }
}

// ------ residual add + layernorm (+ fused MoE gate logits when mode==1) ------
// mode: 0 none, 1 +g_y then gate, 2 +yslots
__global__ __launch_bounds__(256) void addln_kernel(
    const float* __restrict__ w, const float* __restrict__ bb, int mode,
    const float* __restrict__ gw, const float* __restrict__ gb)
{
    __shared__ float xs[NE];
    const int t = blockIdx.x, tid = threadIdx.x;
    float v[3];
    float s = 0.f, s2 = 0.f;
#pragma unroll
    for (int j = 0; j < 3; j++) {
        int c = tid + j * 256;
        float x = g_x[t * NE + c];
        if (mode == 1) x += g_y[t * NE + c];
        else if (mode == 2) x += g_yslot[t * NE + c] + g_yslot[NTOK * NE + t * NE + c];
        v[j] = x; s += x; s2 += x * x;
    }
#pragma unroll
    for (int o = 16; o; o >>= 1) {
        s  += __shfl_down_sync(0xffffffffu, s,  o);
        s2 += __shfl_down_sync(0xffffffffu, s2, o);
    }
    __shared__ float rs[8], rs2[8], smv[2];
    const int wp = tid >> 5, lane = tid & 31;
    if (lane == 0) { rs[wp] = s; rs2[wp] = s2; }
    __syncthreads();
    if (tid == 0) {
        float a = 0.f, b2 = 0.f;
#pragma unroll
        for (int i = 0; i < 8; i++) { a += rs[i]; b2 += rs2[i]; }
        float mean = a * (1.f / NE);
        float var = b2 * (1.f / NE) - mean * mean;
        smv[0] = mean;
        smv[1] = rsqrtf(var + 1e-5f);
    }
    __syncthreads();
    const float mean = smv[0], r = smv[1];
#pragma unroll
    for (int j = 0; j < 3; j++) {
        int c = tid + j * 256;
        float val = (v[j] - mean) * r * w[c] + bb[c];
        g_x[t * NE + c] = val;
        xs[c] = val;
    }
    if (mode == 1) {   // fused gate logits: warp wp -> expert wp
        __syncthreads();
        const float* gr = gw + wp * NE;
        float a = 0.f;
        for (int c = lane; c < NE; c += 32) a += xs[c] * gr[c];
#pragma unroll
        for (int o = 16; o; o >>= 1) a += __shfl_down_sync(0xffffffffu, a, o);
        if (lane == 0) g_logits[t * NEXP + wp] = a + gb[wp];
    }
}

// ---- top-2 + renorm + per-expert token lists. single block, 512 threads ----
__global__ __launch_bounds__(512) void route_b() {
    __shared__ int scnt[NEXP];
    const int tid = threadIdx.x;
    if (tid < NEXP) scnt[tid] = 0;
    __syncthreads();

    float lg[NEXP];
    float m = -1e30f;
#pragma unroll
    for (int e = 0; e < NEXP; e++) { lg[e] = g_logits[tid * NEXP + e]; m = fmaxf(m, lg[e]); }
#pragma unroll
    for (int e = 0; e < NEXP; e++) lg[e] = expf(lg[e] - m);

    int i0 = 0;
#pragma unroll
    for (int e = 1; e < NEXP; e++) if (lg[e] > lg[i0]) i0 = e;
    int i1 = (i0 == 0) ? 1 : 0;
#pragma unroll
    for (int e = 0; e < NEXP; e++) if (e != i0 && lg[e] > lg[i1]) i1 = e;

    const float inv = 1.f / (lg[i0] + lg[i1]);
    const float p0 = lg[i0] * inv, p1 = lg[i1] * inv;

    int pos0 = atomicAdd(&scnt[i0], 1);
    g_tok[i0 * NTOK + pos0] = tid; g_slot[i0 * NTOK + pos0] = 0; g_pw[i0 * NTOK + pos0] = p0;
    int pos1 = atomicAdd(&scnt[i1], 1);
    g_tok[i1 * NTOK + pos1] = tid; g_slot[i1 * NTOK + pos1] = 1; g_pw[i1 * NTOK + pos1] = p1;

    __syncthreads();
    if (tid < NEXP) g_cnt[tid] = scnt[tid];
}

// ---------------- LM head: logits = x @ lm_w^T + lm_b ------------------------
__global__ __launch_bounds__(128) void lm_kernel(
    const float* __restrict__ lw, const float* __restrict__ lb,
    float* __restrict__ out)
{
    __shared__ float xr[NE];
    const int t = blockIdx.x, tid = threadIdx.x;
    for (int c = tid; c < NE; c += 128) xr[c] = g_x[t * NE + c];
    __syncthreads();
    if (tid < NVOCAB) {
        const float* wr = lw + (size_t)tid * NE;
        float a = lb[tid];
#pragma unroll 8
        for (int c = 0; c < NE; c++) a += xr[c] * wr[c];
        out[t * NVOCAB + tid] = a;
    }
}

// ---------------- launch -----------------------------------------------------
extern "C" void kernel_launch(void* const* d_in, const int* in_sizes, int n_in,
                              void* d_out, int out_size) {
    (void)in_sizes; (void)n_in; (void)out_size;
    const int*   idx     = (const int*)  d_in[0];
    const float* tok_emb = (const float*)d_in[1];
    const float* pos_emb = (const float*)d_in[2];
    const float* wq      = (const float*)d_in[3];
    const float* wk      = (const float*)d_in[4];
    const float* wv      = (const float*)d_in[5];
    const float* wproj   = (const float*)d_in[6];
    const float* bproj   = (const float*)d_in[7];
    const float* gate_w  = (const float*)d_in[8];
    const float* gate_b  = (const float*)d_in[9];
    const float* w1      = (const float*)d_in[10];
    const float* b1      = (const float*)d_in[11];
    const float* w2      = (const float*)d_in[12];
    const float* b2      = (const float*)d_in[13];
    const float* ln1_w   = (const float*)d_in[14];
    const float* ln1_b   = (const float*)d_in[15];
    const float* ln2_w   = (const float*)d_in[16];
    const float* ln2_b   = (const float*)d_in[17];
    const float* lnf_w   = (const float*)d_in[18];
    const float* lnf_b   = (const float*)d_in[19];
    const float* lm_w    = (const float*)d_in[20];
    const float* lm_b    = (const float*)d_in[21];
    float* out = (float*)d_out;

    const int ATTN_SMEM = (32 * HD + 64 * HD + 64 * HD + 32 * 64) * 4;  // 69632 B
    cudaFuncSetAttribute(attn_kernel, cudaFuncAttributeMaxDynamicSharedMemorySize, ATTN_SMEM);

    embed_kernel<<<NTOK, 256>>>(idx, tok_emb, pos_emb);

    for (int l = 0; l < NLAYER; l++) {
        const size_t offW  = (size_t)l * NH * HD * NE;      // 589824
        const size_t offM1 = (size_t)l * NEXP * DFF * NE;   // w1/w2 per layer
        qkv_mma<<<dim3(6, 8, 3), 256>>>(wq + offW, wk + offW, wv + offW);
        attn_kernel<<<dim3(64, 2), 256, ATTN_SMEM>>>();
        proj_mma<<<dim3(6, 8), 256>>>(wproj + offW, bproj + (size_t)l * NE);
        // post-norm + fused gate logits
        addln_kernel<<<NTOK, 256>>>(ln1_w + (size_t)l * NE, ln1_b + (size_t)l * NE, 1,
                                    gate_w + (size_t)l * NEXP * NE,
                                    gate_b + (size_t)l * NEXP);
        route_b<<<1, 512>>>();
        moe_g1_mma<<<dim3(24, 8, NEXP), 256>>>(w1 + offM1, b1 + (size_t)l * NEXP * DFF);
        moe_g2_mma<<<dim3(6, 8, NEXP), 256>>>(w2 + offM1, b2 + (size_t)l * NEXP * NE);
        addln_kernel<<<NTOK, 256>>>(ln2_w + (size_t)l * NE, ln2_b + (size_t)l * NE, 2,
                                    nullptr, nullptr);
    }

    addln_kernel<<<NTOK, 256>>>(lnf_w, lnf_b, 0, nullptr, nullptr);
    lm_kernel<<<NTOK, 128>>>(lm_w, lm_b, out);
}

// round 10
// speedup vs baseline: 2.0507x; 1.0003x over previous
#include <cuda_runtime.h>
#include <cuda_bf16.h>
#include <math.h>

#define NTOK   512          // B*T = 8*64
#define NE     768          // n_embd
#define NH     8            // heads
#define HD     96           // head dim
#define DFF    3072
#define NEXP   8
#define NLAYER 12
#define NVOCAB 99
#define TT     64           // seq len

// ---------------- scratch (static device globals; no allocation) -------------
__device__ float g_x[NTOK * NE];
__device__ float g_q[NTOK * NE];
__device__ float g_k[NTOK * NE];
__device__ float g_v[NTOK * NE];
__device__ float g_o[NTOK * NE];
__device__ float g_y[NTOK * NE];
__device__ float g_h[(size_t)NEXP * NTOK * DFF];   // ~50 MB expert hidden
__device__ float g_yslot[2 * NTOK * NE];           // per-slot MoE outputs
__device__ float g_logits[NTOK * NEXP];
__device__ int   g_cnt[NEXP];
__device__ int   g_tok[NEXP * NTOK];
__device__ int   g_slot[NEXP * NTOK];
__device__ float g_pw[NEXP * NTOK];

// ---------------- small helpers ----------------------------------------------
__device__ __forceinline__ unsigned su32(const void* p) {
    return (unsigned)__cvta_generic_to_shared(p);
}

__device__ __forceinline__ void ldsm4(unsigned* r, unsigned addr) {
    asm volatile("ldmatrix.sync.aligned.m8n8.x4.shared.b16 {%0,%1,%2,%3}, [%4];"
        : "=r"(r[0]), "=r"(r[1]), "=r"(r[2]), "=r"(r[3]) : "r"(addr));
}

__device__ __forceinline__ void mma16816(float* c, const unsigned* a, const unsigned* b) {
    asm volatile(
        "mma.sync.aligned.m16n8k16.row.col.f32.bf16.bf16.f32 "
        "{%0,%1,%2,%3}, {%4,%5,%6,%7}, {%8,%9}, {%0,%1,%2,%3};\n"
        : "+f"(c[0]), "+f"(c[1]), "+f"(c[2]), "+f"(c[3])
        : "r"(a[0]), "r"(a[1]), "r"(a[2]), "r"(a[3]), "r"(b[0]), "r"(b[1]));
}

// split 2 fp32 into packed bf16 hi pair + bf16 lo pair (lo = x - float(hi))
__device__ __forceinline__ void split2(float x0, float x1, unsigned& hi, unsigned& lo) {
    __nv_bfloat162 h = __floats2bfloat162_rn(x0, x1);
    float2 hf = __bfloat1622float2(h);
    __nv_bfloat162 l = __floats2bfloat162_rn(x0 - hf.x, x1 - hf.y);
    hi = *reinterpret_cast<unsigned*>(&h);
    lo = *reinterpret_cast<unsigned*>(&l);
}

// ---------------- tensor-core GEMM core: C = A @ W^T (fp32-in/out, bf16x3) ----
// Block tile 64(M) x 128(N), BK=16, DOUBLE-BUFFERED smem, 256 threads = 8 warps
// (2M x 4N), warp tile 32x32. A: [mrows, lda] fp32 row-major (optional gather).
// W: [N, K] fp32 row-major (rows K-major = col-major B => "row.col" mma).
__device__ __forceinline__ void mma_gemm_core(
    const float* __restrict__ Abase, int lda,
    const int* __restrict__ rowmap, int mrows, int mTile,
    const float* __restrict__ W, int nTile, int K,
    float (&acc)[2][4][4])
{
    // [stage][part hi/lo][row][16k + pad8] ; row stride 48B (conflict-free LDSM)
    __shared__ __align__(16) __nv_bfloat16 As[2][2][64][24];    // 12 KB
    __shared__ __align__(16) __nv_bfloat16 Bs[2][2][128][24];   // 24 KB

    const int tx = threadIdx.x;
    const int warp = tx >> 5, lane = tx & 31;
    const int wm = (warp >> 2) * 32;   // warp M offset
    const int wn = (warp & 3) * 32;    // warp N offset

    // --- staging assignments ---
    const int ar = tx >> 2;            // A row 0..63
    const int ak = (tx & 3) << 2;      // k offset {0,4,8,12}
    const int grow = mTile * 64 + ar;
    const float* aptr = nullptr;
    if (grow < mrows) {
        int src = rowmap ? rowmap[grow] : grow;
        aptr = Abase + (size_t)src * lda + ak;
    }
    const int br = tx >> 1;            // B row 0..127
    const int bk = (tx & 1) << 3;      // k offset {0,8}
    const float* bptr = W + (size_t)(nTile * 128 + br) * K + bk;

    // --- ldmatrix lane base addresses (stage 0, part hi) ---
    const unsigned aBase = su32(&As[0][0][wm + (lane & 15)][(lane >> 4) * 8]);
    const int bn = wn + (lane & 7) + ((lane >> 1) & 8);
    const unsigned bBase = su32(&Bs[0][0][bn][lane & 8]);
    // strides (bytes): A stage 6144, part 3072; B stage 12288, part 6144; +16rows = 768

    const int nt = K >> 4;

    // prologue: tile 0 regs -> stage into buf 0; prefetch tile 1 regs
    float4 av  = aptr ? *(const float4*)aptr : make_float4(0.f, 0.f, 0.f, 0.f);
    float4 bv0 = *(const float4*)bptr;
    float4 bv1 = *(const float4*)(bptr + 4);
    {
        unsigned h0, l0, h1, l1;
        split2(av.x, av.y, h0, l0); split2(av.z, av.w, h1, l1);
        *(uint2*)&As[0][0][ar][ak] = make_uint2(h0, h1);
        *(uint2*)&As[0][1][ar][ak] = make_uint2(l0, l1);
        unsigned p0h, p0l, p1h, p1l, p2h, p2l, p3h, p3l;
        split2(bv0.x, bv0.y, p0h, p0l); split2(bv0.z, bv0.w, p1h, p1l);
        split2(bv1.x, bv1.y, p2h, p2l); split2(bv1.z, bv1.w, p3h, p3l);
        *(uint4*)&Bs[0][0][br][bk] = make_uint4(p0h, p1h, p2h, p3h);
        *(uint4*)&Bs[0][1][br][bk] = make_uint4(p0l, p1l, p2l, p3l);
    }
    if (nt > 1) {
        av  = aptr ? *(const float4*)(aptr + 16) : make_float4(0.f, 0.f, 0.f, 0.f);
        bv0 = *(const float4*)(bptr + 16);
        bv1 = *(const float4*)(bptr + 20);
    }
    __syncthreads();

    for (int t = 0; t < nt; t++) {
        const int p = t & 1;
        const unsigned aHi = aBase + p * 6144;
        const unsigned bHi = bBase + p * 12288;
        unsigned Ah[2][4], Al[2][4], Bh[2][4], Bl[2][4];
        ldsm4(Ah[0], aHi);          ldsm4(Ah[1], aHi + 768);
        ldsm4(Al[0], aHi + 3072);   ldsm4(Al[1], aHi + 3072 + 768);
        ldsm4(Bh[0], bHi);          ldsm4(Bh[1], bHi + 768);
        ldsm4(Bl[0], bHi + 6144);   ldsm4(Bl[1], bHi + 6144 + 768);

        // stage tile t+1 into the other buffer (independent of this tile's MMA;
        // ptxas interleaves this ALU/STS stream into HMMA gaps)
        if (t + 1 < nt) {
            const int q = p ^ 1;
            unsigned h0, l0, h1, l1;
            split2(av.x, av.y, h0, l0); split2(av.z, av.w, h1, l1);
            *(uint2*)&As[q][0][ar][ak] = make_uint2(h0, h1);
            *(uint2*)&As[q][1][ar][ak] = make_uint2(l0, l1);
            unsigned p0h, p0l, p1h, p1l, p2h, p2l, p3h, p3l;
            split2(bv0.x, bv0.y, p0h, p0l); split2(bv0.z, bv0.w, p1h, p1l);
            split2(bv1.x, bv1.y, p2h, p2l); split2(bv1.z, bv1.w, p3h, p3l);
            *(uint4*)&Bs[q][0][br][bk] = make_uint4(p0h, p1h, p2h, p3h);
            *(uint4*)&Bs[q][1][br][bk] = make_uint4(p0l, p1l, p2l, p3l);
            if (t + 2 < nt) {  // prefetch tile t+2 into regs (2-tile LDG distance)
                const int ko = (t + 2) * 16;
                av  = aptr ? *(const float4*)(aptr + ko) : make_float4(0.f, 0.f, 0.f, 0.f);
                bv0 = *(const float4*)(bptr + ko);
                bv1 = *(const float4*)(bptr + ko + 4);
            }
        }

#pragma unroll
        for (int i = 0; i < 2; i++)
#pragma unroll
            for (int j = 0; j < 4; j++) {
                const unsigned* bh = &Bh[j >> 1][(j & 1) * 2];
                const unsigned* bl = &Bl[j >> 1][(j & 1) * 2];
                mma16816(acc[i][j], Ah[i], bh);   // hi*hi
                mma16816(acc[i][j], Ah[i], bl);   // hi*lo
                mma16816(acc[i][j], Al[i], bh);   // lo*hi
            }
        __syncthreads();
    }
}

// ---------------- fused QKV: grid (6, 8, 3) -----------------------------------
__global__ __launch_bounds__(256) void qkv_mma(
    const float* __restrict__ wq, const float* __restrict__ wk,
    const float* __restrict__ wv)
{
    const float* W = (blockIdx.z == 0) ? wq : (blockIdx.z == 1) ? wk : wv;
    float* out = (blockIdx.z == 0) ? g_q : (blockIdx.z == 1) ? g_k : g_v;
    float acc[2][4][4] = {};
    mma_gemm_core(g_x, NE, nullptr, NTOK, blockIdx.y, W, blockIdx.x, NE, acc);
    const int lane = threadIdx.x & 31, warp = threadIdx.x >> 5;
    const int m0 = blockIdx.y * 64 + (warp >> 2) * 32 + (lane >> 2);
    const int n0 = blockIdx.x * 128 + (warp & 3) * 32 + (lane & 3) * 2;
#pragma unroll
    for (int i = 0; i < 2; i++)
#pragma unroll
        for (int j = 0; j < 4; j++) {
            int m = m0 + i * 16, n = n0 + j * 8;
            *(float2*)&out[m * NE + n]       = make_float2(acc[i][j][0], acc[i][j][1]);
            *(float2*)&out[(m + 8) * NE + n] = make_float2(acc[i][j][2], acc[i][j][3]);
        }
}

// ---------------- output projection: grid (6, 8) -----------------------------
__global__ __launch_bounds__(256) void proj_mma(
    const float* __restrict__ wp, const float* __restrict__ bp)
{
    float acc[2][4][4] = {};
    mma_gemm_core(g_o, NE, nullptr, NTOK, blockIdx.y, wp, blockIdx.x, NE, acc);
    const int lane = threadIdx.x & 31, warp = threadIdx.x >> 5;
    const int m0 = blockIdx.y * 64 + (warp >> 2) * 32 + (lane >> 2);
    const int n0 = blockIdx.x * 128 + (warp & 3) * 32 + (lane & 3) * 2;
#pragma unroll
    for (int i = 0; i < 2; i++)
#pragma unroll
        for (int j = 0; j < 4; j++) {
            int m = m0 + i * 16, n = n0 + j * 8;
            float b0 = bp[n], b1 = bp[n + 1];
            *(float2*)&g_y[m * NE + n]       = make_float2(acc[i][j][0] + b0, acc[i][j][1] + b1);
            *(float2*)&g_y[(m + 8) * NE + n] = make_float2(acc[i][j][2] + b0, acc[i][j][3] + b1);
        }
}

// ---------------- expert GEMM1: h = gelu(x_gather @ w1^T + b1); grid(24,8,8) --
__global__ __launch_bounds__(256) void moe_g1_mma(
    const float* __restrict__ w1l, const float* __restrict__ b1l)
{
    const int e = blockIdx.z;
    const int ne = g_cnt[e];
    if ((int)(blockIdx.y * 64) >= ne) return;
    float acc[2][4][4] = {};
    mma_gemm_core(g_x, NE, g_tok + e * NTOK, ne, blockIdx.y,
                  w1l + (size_t)e * DFF * NE, blockIdx.x, NE, acc);
    const int lane = threadIdx.x & 31, warp = threadIdx.x >> 5;
    const int m0 = blockIdx.y * 64 + (warp >> 2) * 32 + (lane >> 2);
    const int n0 = blockIdx.x * 128 + (warp & 3) * 32 + (lane & 3) * 2;
    float* hb = g_h + (size_t)e * NTOK * DFF;
#pragma unroll
    for (int i = 0; i < 2; i++)
#pragma unroll
        for (int j = 0; j < 4; j++) {
            int n = n0 + j * 8;
            float b0 = b1l[e * DFF + n], b1 = b1l[e * DFF + n + 1];
#pragma unroll
            for (int half = 0; half < 2; half++) {
                int m = m0 + i * 16 + half * 8;
                if (m < ne) {
                    float v0 = acc[i][j][half * 2 + 0] + b0;
                    float v1 = acc[i][j][half * 2 + 1] + b1;
                    v0 = 0.5f * v0 * (1.f + erff(v0 * 0.70710678118654752f));
                    v1 = 0.5f * v1 * (1.f + erff(v1 * 0.70710678118654752f));
                    *(float2*)&hb[(size_t)m * DFF + n] = make_float2(v0, v1);
                }
            }
        }
}

// ---------------- expert GEMM2: y_slot = p*(h @ w2^T + b2); grid(6,8,8) -------
__global__ __launch_bounds__(256) void moe_g2_mma(
    const float* __restrict__ w2l, const float* __restrict__ b2l)
{
    const int e = blockIdx.z;
    const int ne = g_cnt[e];
    if ((int)(blockIdx.y * 64) >= ne) return;
    float acc[2][4][4] = {};
    mma_gemm_core(g_h + (size_t)e * NTOK * DFF, DFF, nullptr, ne, blockIdx.y,
                  w2l + (size_t)e * NE * DFF, blockIdx.x, DFF, acc);
    const int lane = threadIdx.x & 31, warp = threadIdx.x >> 5;
    const int m0 = blockIdx.y * 64 + (warp >> 2) * 32 + (lane >> 2);
    const int n0 = blockIdx.x * 128 + (warp & 3) * 32 + (lane & 3) * 2;
#pragma unroll
    for (int i = 0; i < 2; i++)
#pragma unroll
        for (int j = 0; j < 4; j++) {
            int n = n0 + j * 8;
            float b0 = b2l[e * NE + n], b1 = b2l[e * NE + n + 1];
#pragma unroll
            for (int half = 0; half < 2; half++) {
                int m = m0 + i * 16 + half * 8;
                if (m < ne) {
                    int tok = g_tok[e * NTOK + m];
                    int sl  = g_slot[e * NTOK + m];
                    float p = g_pw[e * NTOK + m];
                    float* dst = g_yslot + (size_t)sl * NTOK * NE + (size_t)tok * NE;
                    *(float2*)&dst[n] = make_float2(p * (acc[i][j][half * 2 + 0] + b0),
                                                    p * (acc[i][j][half * 2 + 1] + b1));
                }
            }
        }
}

// ---------------- embed ------------------------------------------------------
__global__ void embed_kernel(const int* __restrict__ idx,
                             const float* __restrict__ te,
                             const float* __restrict__ pe) {
    int t = blockIdx.x;
    int id = idx[t];
    int pp = t & (TT - 1);
    for (int c = threadIdx.x; c < NE; c += blockDim.x)
        g_x[t * NE + c] = te[id * NE + c] + pe[pp * NE + c];
}

// ---------------- attention core: grid (B*H=64, 2), 256 thr, dyn smem --------
__global__ __launch_bounds__(256) void attn_kernel() {
    extern __shared__ float sm[];
    float* sq = sm;                 // 32*96
    float* sk = sq + 32 * HD;       // 64*96
    float* sv = sk + 64 * HD;       // 64*96
    float* ss = sv + 64 * HD;       // 32*64
    const int b = blockIdx.x >> 3, h = blockIdx.x & 7;
    const int t0 = blockIdx.y * 32;
    const int base = b * TT;
    const int tid = threadIdx.x;
    const int col0 = h * HD;

    for (int i = tid; i < 64 * HD; i += 256) {
        int t = i / HD, d = i - t * HD;
        sk[i] = g_k[(base + t) * NE + col0 + d];
        sv[i] = g_v[(base + t) * NE + col0 + d];
    }
    for (int i = tid; i < 32 * HD; i += 256) {
        int t = i / HD, d = i - t * HD;
        sq[i] = g_q[(base + t0 + t) * NE + col0 + d];
    }
    __syncthreads();

    const float scale = 0.10206207261596575f;  // 96^-0.5
    for (int e = tid; e < 32 * 64; e += 256) {
        int t = e >> 6, s = e & 63;
        float a = 0.f;
        if (s <= t0 + t) {
            const float* qp = sq + t * HD;
            const float* kp = sk + s * HD;
#pragma unroll 8
            for (int d = 0; d < HD; d++) a += qp[d] * kp[d];
            a *= scale;
        }
        ss[e] = a;
    }
    __syncthreads();

    if (tid < 32) {
        int lim = t0 + tid;
        float m = -1e30f;
        for (int s = 0; s <= lim; s++) m = fmaxf(m, ss[tid * 64 + s]);
        float sum = 0.f;
        for (int s = 0; s < 64; s++) {
            float v = (s <= lim) ? expf(ss[tid * 64 + s] - m) : 0.f;
            ss[tid * 64 + s] = v;
            sum += v;
        }
        float inv = 1.f / sum;
        for (int s = 0; s < 64; s++) ss[tid * 64 + s] *= inv;
    }
    __syncthreads();

    for (int i = tid; i < 32 * HD; i += 256) {
        int t = i / HD, d = i - t * HD;
        const float* ps = ss + t * 64;
        float a = 0.f;
#pragma unroll 8
        for (int s = 0; s < 64; s++) a += ps[s] * sv[s * HD + d];
        g_o[(base + t0 + t) * NE + col0 + d] = a;
    }
}

// ------ residual add + layernorm (+ fused MoE gate logits when mode==1) ------
// mode: 0 none, 1 +g_y then gate, 2 +yslots
__global__ __launch_bounds__(256) void addln_kernel(
    const float* __restrict__ w, const float* __restrict__ bb, int mode,
    const float* __restrict__ gw, const float* __restrict__ gb)
{
    __shared__ float xs[NE];
    const int t = blockIdx.x, tid = threadIdx.x;
    float v[3];
    float s = 0.f, s2 = 0.f;
#pragma unroll
    for (int j = 0; j < 3; j++) {
        int c = tid + j * 256;
        float x = g_x[t * NE + c];
        if (mode == 1) x += g_y[t * NE + c];
        else if (mode == 2) x += g_yslot[t * NE + c] + g_yslot[NTOK * NE + t * NE + c];
        v[j] = x; s += x; s2 += x * x;
    }
#pragma unroll
    for (int o = 16; o; o >>= 1) {
        s  += __shfl_down_sync(0xffffffffu, s,  o);
        s2 += __shfl_down_sync(0xffffffffu, s2, o);
    }
    __shared__ float rs[8], rs2[8], smv[2];
    const int wp = tid >> 5, lane = tid & 31;
    if (lane == 0) { rs[wp] = s; rs2[wp] = s2; }
    __syncthreads();
    if (tid == 0) {
        float a = 0.f, b2 = 0.f;
#pragma unroll
        for (int i = 0; i < 8; i++) { a += rs[i]; b2 += rs2[i]; }
        float mean = a * (1.f / NE);
        float var = b2 * (1.f / NE) - mean * mean;
        smv[0] = mean;
        smv[1] = rsqrtf(var + 1e-5f);
    }
    __syncthreads();
    const float mean = smv[0], r = smv[1];
#pragma unroll
    for (int j = 0; j < 3; j++) {
        int c = tid + j * 256;
        float val = (v[j] - mean) * r * w[c] + bb[c];
        g_x[t * NE + c] = val;
        xs[c] = val;
    }
    if (mode == 1) {   // fused gate logits: warp wp -> expert wp
        __syncthreads();
        const float* gr = gw + wp * NE;
        float a = 0.f;
        for (int c = lane; c < NE; c += 32) a += xs[c] * gr[c];
#pragma unroll
        for (int o = 16; o; o >>= 1) a += __shfl_down_sync(0xffffffffu, a, o);
        if (lane == 0) g_logits[t * NEXP + wp] = a + gb[wp];
    }
}

// ---- top-2 + renorm + per-expert token lists. single block, 512 threads ----
__global__ __launch_bounds__(512) void route_b() {
    __shared__ int scnt[NEXP];
    const int tid = threadIdx.x;
    if (tid < NEXP) scnt[tid] = 0;
    __syncthreads();

    float lg[NEXP];
    float m = -1e30f;
#pragma unroll
    for (int e = 0; e < NEXP; e++) { lg[e] = g_logits[tid * NEXP + e]; m = fmaxf(m, lg[e]); }
#pragma unroll
    for (int e = 0; e < NEXP; e++) lg[e] = expf(lg[e] - m);

    int i0 = 0;
#pragma unroll
    for (int e = 1; e < NEXP; e++) if (lg[e] > lg[i0]) i0 = e;
    int i1 = (i0 == 0) ? 1 : 0;
#pragma unroll
    for (int e = 0; e < NEXP; e++) if (e != i0 && lg[e] > lg[i1]) i1 = e;

    const float inv = 1.f / (lg[i0] + lg[i1]);
    const float p0 = lg[i0] * inv, p1 = lg[i1] * inv;

    int pos0 = atomicAdd(&scnt[i0], 1);
    g_tok[i0 * NTOK + pos0] = tid; g_slot[i0 * NTOK + pos0] = 0; g_pw[i0 * NTOK + pos0] = p0;
    int pos1 = atomicAdd(&scnt[i1], 1);
    g_tok[i1 * NTOK + pos1] = tid; g_slot[i1 * NTOK + pos1] = 1; g_pw[i1 * NTOK + pos1] = p1;

    __syncthreads();
    if (tid < NEXP) g_cnt[tid] = scnt[tid];
}

// ---------------- LM head: logits = x @ lm_w^T + lm_b ------------------------
__global__ __launch_bounds__(128) void lm_kernel(
    const float* __restrict__ lw, const float* __restrict__ lb,
    float* __restrict__ out)
{
    __shared__ float xr[NE];
    const int t = blockIdx.x, tid = threadIdx.x;
    for (int c = tid; c < NE; c += 128) xr[c] = g_x[t * NE + c];
    __syncthreads();
    if (tid < NVOCAB) {
        const float* wr = lw + (size_t)tid * NE;
        float a = lb[tid];
#pragma unroll 8
        for (int c = 0; c < NE; c++) a += xr[c] * wr[c];
        out[t * NVOCAB + tid] = a;
    }
}

// ---------------- launch -----------------------------------------------------
extern "C" void kernel_launch(void* const* d_in, const int* in_sizes, int n_in,
                              void* d_out, int out_size) {
    (void)in_sizes; (void)n_in; (void)out_size;
    const int*   idx     = (const int*)  d_in[0];
    const float* tok_emb = (const float*)d_in[1];
    const float* pos_emb = (const float*)d_in[2];
    const float* wq      = (const float*)d_in[3];
    const float* wk      = (const float*)d_in[4];
    const float* wv      = (const float*)d_in[5];
    const float* wproj   = (const float*)d_in[6];
    const float* bproj   = (const float*)d_in[7];
    const float* gate_w  = (const float*)d_in[8];
    const float* gate_b  = (const float*)d_in[9];
    const float* w1      = (const float*)d_in[10];
    const float* b1      = (const float*)d_in[11];
    const float* w2      = (const float*)d_in[12];
    const float* b2      = (const float*)d_in[13];
    const float* ln1_w   = (const float*)d_in[14];
    const float* ln1_b   = (const float*)d_in[15];
    const float* ln2_w   = (const float*)d_in[16];
    const float* ln2_b   = (const float*)d_in[17];
    const float* lnf_w   = (const float*)d_in[18];
    const float* lnf_b   = (const float*)d_in[19];
    const float* lm_w    = (const float*)d_in[20];
    const float* lm_b    = (const float*)d_in[21];
    float* out = (float*)d_out;

    const int ATTN_SMEM = (32 * HD + 64 * HD + 64 * HD + 32 * 64) * 4;  // 69632 B
    cudaFuncSetAttribute(attn_kernel, cudaFuncAttributeMaxDynamicSharedMemorySize, ATTN_SMEM);

    embed_kernel<<<NTOK, 256>>>(idx, tok_emb, pos_emb);

    for (int l = 0; l < NLAYER; l++) {
        const size_t offW  = (size_t)l * NH * HD * NE;      // 589824
        const size_t offM1 = (size_t)l * NEXP * DFF * NE;   // w1/w2 per layer
        qkv_mma<<<dim3(6, 8, 3), 256>>>(wq + offW, wk + offW, wv + offW);
        attn_kernel<<<dim3(64, 2), 256, ATTN_SMEM>>>();
        proj_mma<<<dim3(6, 8), 256>>>(wproj + offW, bproj + (size_t)l * NE);
        // post-norm + fused gate logits
        addln_kernel<<<NTOK, 256>>>(ln1_w + (size_t)l * NE, ln1_b + (size_t)l * NE, 1,
                                    gate_w + (size_t)l * NEXP * NE,
                                    gate_b + (size_t)l * NEXP);
        route_b<<<1, 512>>>();
        moe_g1_mma<<<dim3(24, 8, NEXP), 256>>>(w1 + offM1, b1 + (size_t)l * NEXP * DFF);
        moe_g2_mma<<<dim3(6, 8, NEXP), 256>>>(w2 + offM1, b2 + (size_t)l * NEXP * NE);
        addln_kernel<<<NTOK, 256>>>(ln2_w + (size_t)l * NE, ln2_b + (size_t)l * NE, 2,
                                    nullptr, nullptr);
    }

    addln_kernel<<<NTOK, 256>>>(lnf_w, lnf_b, 0, nullptr, nullptr);
    lm_kernel<<<NTOK, 128>>>(lm_w, lm_b, out);
}

// round 11
// speedup vs baseline: 2.5674x; 1.2520x over previous
#include <cuda_runtime.h>
#include <cuda_bf16.h>
#include <math.h>

#define NTOK   512          // B*T = 8*64
#define NE     768          // n_embd
#define NH     8            // heads
#define HD     96           // head dim
#define DFF    3072
#define NEXP   8
#define NLAYER 12
#define NVOCAB 99
#define TT     64           // seq len

#define GEMM_SMEM 73728     // 4-slot ring: A 4*6144B + B 4*12288B

// ---------------- scratch (static device globals; no allocation) -------------
__device__ float g_x[NTOK * NE];
__device__ float g_q[NTOK * NE];
__device__ float g_k[NTOK * NE];
__device__ float g_v[NTOK * NE];
__device__ float g_o[NTOK * NE];
__device__ float g_y[NTOK * NE];
__device__ float g_y2[NTOK * NE];                  // proj split-K partial
__device__ float g_h[(size_t)NEXP * NTOK * DFF];   // ~50 MB expert hidden
__device__ float g_yslot[4 * NTOK * NE];           // [slot*2 + ksplit]
__device__ float g_logits[NTOK * NEXP];
__device__ int   g_cnt[NEXP];
__device__ int   g_tok[NEXP * NTOK];
__device__ int   g_slot[NEXP * NTOK];
__device__ float g_pw[NEXP * NTOK];

// ---------------- small helpers ----------------------------------------------
__device__ __forceinline__ unsigned su32(const void* p) {
    return (unsigned)__cvta_generic_to_shared(p);
}

__device__ __forceinline__ void ldsm4(unsigned* r, unsigned addr) {
    asm volatile("ldmatrix.sync.aligned.m8n8.x4.shared.b16 {%0,%1,%2,%3}, [%4];"
        : "=r"(r[0]), "=r"(r[1]), "=r"(r[2]), "=r"(r[3]) : "r"(addr));
}

__device__ __forceinline__ void mma16816(float* c, const unsigned* a, const unsigned* b) {
    asm volatile(
        "mma.sync.aligned.m16n8k16.row.col.f32.bf16.bf16.f32 "
        "{%0,%1,%2,%3}, {%4,%5,%6,%7}, {%8,%9}, {%0,%1,%2,%3};\n"
        : "+f"(c[0]), "+f"(c[1]), "+f"(c[2]), "+f"(c[3])
        : "r"(a[0]), "r"(a[1]), "r"(a[2]), "r"(a[3]), "r"(b[0]), "r"(b[1]));
}

// split 2 fp32 into packed bf16 hi pair + bf16 lo pair (lo = x - float(hi))
__device__ __forceinline__ void split2(float x0, float x1, unsigned& hi, unsigned& lo) {
    __nv_bfloat162 h = __floats2bfloat162_rn(x0, x1);
    float2 hf = __bfloat1622float2(h);
    __nv_bfloat162 l = __floats2bfloat162_rn(x0 - hf.x, x1 - hf.y);
    hi = *reinterpret_cast<unsigned*>(&h);
    lo = *reinterpret_cast<unsigned*>(&l);
}

// stage one 16-k tile (regs -> smem slice). Layout per slice (bf16 elems):
//   A: slice*3072 + part*1536 + row*24 + k      (rows 0..63)
//   B: 12288 + slice*6144 + part*3072 + row*24 + k  (rows 0..127)
__device__ __forceinline__ void stage_tile(
    __nv_bfloat16* sm_bf, int slice, int ar, int ak, int br, int bk,
    float4 av, float4 bv0, float4 bv1)
{
    unsigned h0, l0, h1, l1;
    split2(av.x, av.y, h0, l0); split2(av.z, av.w, h1, l1);
    __nv_bfloat16* A0 = sm_bf + slice * 3072 + ar * 24 + ak;
    *(uint2*)A0          = make_uint2(h0, h1);
    *(uint2*)(A0 + 1536) = make_uint2(l0, l1);
    unsigned p0h, p0l, p1h, p1l, p2h, p2l, p3h, p3l;
    split2(bv0.x, bv0.y, p0h, p0l); split2(bv0.z, bv0.w, p1h, p1l);
    split2(bv1.x, bv1.y, p2h, p2l); split2(bv1.z, bv1.w, p3h, p3l);
    __nv_bfloat16* B0 = sm_bf + 12288 + slice * 6144 + br * 24 + bk;
    *(uint4*)B0          = make_uint4(p0h, p1h, p2h, p3h);
    *(uint4*)(B0 + 3072) = make_uint4(p0l, p1l, p2l, p3l);
}

// ---------------- tensor-core GEMM core: C = A @ W^T (fp32-in/out, bf16x3) ----
// Block tile 64(M) x 128(N), BK=16, 4-slot smem ring (barrier every 2 tiles),
// 256 threads = 8 warps (2M x 4N), warp tile 32x32.
// A: [mrows, lda] fp32 row-major (optional row gather). W rows: ldw stride.
// Computes over K range [koff, koff + nt*16). Requires nt >= 4.
__device__ __forceinline__ void mma_gemm_core(
    const float* __restrict__ Abase, int lda,
    const int* __restrict__ rowmap, int mrows, int mTile,
    const float* __restrict__ W, int ldw, int nTile, int koff, int nt,
    float (&acc)[2][4][4])
{
    extern __shared__ __align__(16) __nv_bfloat16 sm_bf[];

    const int tx = threadIdx.x;
    const int warp = tx >> 5, lane = tx & 31;
    const int wm = (warp >> 2) * 32;   // warp M offset
    const int wn = (warp & 3) * 32;    // warp N offset

    // staging assignments
    const int ar = tx >> 2;            // A row 0..63
    const int ak = (tx & 3) << 2;      // k offset {0,4,8,12}
    const int grow = mTile * 64 + ar;
    const float* aptr = nullptr;
    if (grow < mrows) {
        int src = rowmap ? rowmap[grow] : grow;
        aptr = Abase + (size_t)src * lda + koff + ak;
    }
    const int br = tx >> 1;            // B row 0..127
    const int bk = (tx & 1) << 3;      // k offset {0,8}
    const float* bptr = W + (size_t)(nTile * 128 + br) * ldw + koff + bk;

    // ldmatrix lane base addresses (slice 0, part hi)
    const unsigned aB = su32(sm_bf + (wm + (lane & 15)) * 24 + (lane >> 4) * 8);
    const int bn = wn + (lane & 7) + ((lane >> 1) & 8);
    const unsigned bB = su32(sm_bf + 12288 + bn * 24 + (lane & 8));
    // byte strides: A slice 6144, part 3072; B slice 12288, part 6144; +16 rows = 768

    const float4 zf4 = make_float4(0.f, 0.f, 0.f, 0.f);

    // prologue: stage tiles 0,1 into slices 0,1; prefetch tiles 2,3 into regs
    float4 avA, bv0A, bv1A, avB, bv0B, bv1B;
    avA  = aptr ? *(const float4*)aptr : zf4;
    bv0A = *(const float4*)bptr;  bv1A = *(const float4*)(bptr + 4);
    avB  = aptr ? *(const float4*)(aptr + 16) : zf4;
    bv0B = *(const float4*)(bptr + 16); bv1B = *(const float4*)(bptr + 20);
    stage_tile(sm_bf, 0, ar, ak, br, bk, avA, bv0A, bv1A);
    stage_tile(sm_bf, 1, ar, ak, br, bk, avB, bv0B, bv1B);
    avA  = aptr ? *(const float4*)(aptr + 32) : zf4;
    bv0A = *(const float4*)(bptr + 32); bv1A = *(const float4*)(bptr + 36);
    avB  = aptr ? *(const float4*)(aptr + 48) : zf4;
    bv0B = *(const float4*)(bptr + 48); bv1B = *(const float4*)(bptr + 52);
    __syncthreads();

    for (int t = 0; t < nt; t++) {
        const int s = t & 3;
        const unsigned aHi = aB + s * 6144;
        const unsigned bHi = bB + s * 12288;
        unsigned Ah[2][4], Al[2][4], Bh[2][4], Bl[2][4];
        ldsm4(Ah[0], aHi);          ldsm4(Ah[1], aHi + 768);
        ldsm4(Al[0], aHi + 3072);   ldsm4(Al[1], aHi + 3072 + 768);
        ldsm4(Bh[0], bHi);          ldsm4(Bh[1], bHi + 768);
        ldsm4(Bl[0], bHi + 6144);   ldsm4(Bl[1], bHi + 6144 + 768);

        // stage tile t+2 into slice (t+2)&3 (not in use this pair); prefetch t+4
        if (t + 2 < nt) {
            if (t & 1) {
                stage_tile(sm_bf, (t + 2) & 3, ar, ak, br, bk, avB, bv0B, bv1B);
                if (t + 4 < nt) {
                    const int ko = (t + 4) * 16;
                    avB  = aptr ? *(const float4*)(aptr + ko) : zf4;
                    bv0B = *(const float4*)(bptr + ko);
                    bv1B = *(const float4*)(bptr + ko + 4);
                }
            } else {
                stage_tile(sm_bf, (t + 2) & 3, ar, ak, br, bk, avA, bv0A, bv1A);
                if (t + 4 < nt) {
                    const int ko = (t + 4) * 16;
                    avA  = aptr ? *(const float4*)(aptr + ko) : zf4;
                    bv0A = *(const float4*)(bptr + ko);
                    bv1A = *(const float4*)(bptr + ko + 4);
                }
            }
        }

#pragma unroll
        for (int i = 0; i < 2; i++)
#pragma unroll
            for (int j = 0; j < 4; j++) {
                const unsigned* bh = &Bh[j >> 1][(j & 1) * 2];
                const unsigned* bl = &Bl[j >> 1][(j & 1) * 2];
                mma16816(acc[i][j], Ah[i], bh);   // hi*hi
                mma16816(acc[i][j], Ah[i], bl);   // hi*lo
                mma16816(acc[i][j], Al[i], bh);   // lo*hi
            }
        if (t & 1) __syncthreads();   // barrier every 2 tiles
    }
}

// ---------------- fused QKV: grid (6, 8, 3) -----------------------------------
__global__ __launch_bounds__(256) void qkv_mma(
    const float* __restrict__ wq, const float* __restrict__ wk,
    const float* __restrict__ wv)
{
    const float* W = (blockIdx.z == 0) ? wq : (blockIdx.z == 1) ? wk : wv;
    float* out = (blockIdx.z == 0) ? g_q : (blockIdx.z == 1) ? g_k : g_v;
    float acc[2][4][4] = {};
    mma_gemm_core(g_x, NE, nullptr, NTOK, blockIdx.y, W, NE, blockIdx.x, 0, NE / 16, acc);
    const int lane = threadIdx.x & 31, warp = threadIdx.x >> 5;
    const int m0 = blockIdx.y * 64 + (warp >> 2) * 32 + (lane >> 2);
    const int n0 = blockIdx.x * 128 + (warp & 3) * 32 + (lane & 3) * 2;
#pragma unroll
    for (int i = 0; i < 2; i++)
#pragma unroll
        for (int j = 0; j < 4; j++) {
            int m = m0 + i * 16, n = n0 + j * 8;
            *(float2*)&out[m * NE + n]       = make_float2(acc[i][j][0], acc[i][j][1]);
            *(float2*)&out[(m + 8) * NE + n] = make_float2(acc[i][j][2], acc[i][j][3]);
        }
}

// ---------------- output projection, split-K x2: grid (6, 8, 2) ---------------
__global__ __launch_bounds__(256) void proj_mma(
    const float* __restrict__ wp, const float* __restrict__ bp)
{
    const int ks = blockIdx.z;
    float acc[2][4][4] = {};
    mma_gemm_core(g_o, NE, nullptr, NTOK, blockIdx.y, wp, NE, blockIdx.x,
                  ks * (NE / 2), NE / 32, acc);
    float* out = ks ? g_y2 : g_y;
    const int lane = threadIdx.x & 31, warp = threadIdx.x >> 5;
    const int m0 = blockIdx.y * 64 + (warp >> 2) * 32 + (lane >> 2);
    const int n0 = blockIdx.x * 128 + (warp & 3) * 32 + (lane & 3) * 2;
#pragma unroll
    for (int i = 0; i < 2; i++)
#pragma unroll
        for (int j = 0; j < 4; j++) {
            int m = m0 + i * 16, n = n0 + j * 8;
            float b0 = ks ? 0.f : bp[n], b1 = ks ? 0.f : bp[n + 1];
            *(float2*)&out[m * NE + n]       = make_float2(acc[i][j][0] + b0, acc[i][j][1] + b1);
            *(float2*)&out[(m + 8) * NE + n] = make_float2(acc[i][j][2] + b0, acc[i][j][3] + b1);
        }
}

// ---------------- expert GEMM1: h = gelu(x_gather @ w1^T + b1); grid(24,8,8) --
__global__ __launch_bounds__(256) void moe_g1_mma(
    const float* __restrict__ w1l, const float* __restrict__ b1l)
{
    const int e = blockIdx.z;
    const int ne = g_cnt[e];
    if ((int)(blockIdx.y * 64) >= ne) return;
    float acc[2][4][4] = {};
    mma_gemm_core(g_x, NE, g_tok + e * NTOK, ne, blockIdx.y,
                  w1l + (size_t)e * DFF * NE, NE, blockIdx.x, 0, NE / 16, acc);
    const int lane = threadIdx.x & 31, warp = threadIdx.x >> 5;
    const int m0 = blockIdx.y * 64 + (warp >> 2) * 32 + (lane >> 2);
    const int n0 = blockIdx.x * 128 + (warp & 3) * 32 + (lane & 3) * 2;
    float* hb = g_h + (size_t)e * NTOK * DFF;
#pragma unroll
    for (int i = 0; i < 2; i++)
#pragma unroll
        for (int j = 0; j < 4; j++) {
            int n = n0 + j * 8;
            float b0 = b1l[e * DFF + n], b1 = b1l[e * DFF + n + 1];
#pragma unroll
            for (int half = 0; half < 2; half++) {
                int m = m0 + i * 16 + half * 8;
                if (m < ne) {
                    float v0 = acc[i][j][half * 2 + 0] + b0;
                    float v1 = acc[i][j][half * 2 + 1] + b1;
                    v0 = 0.5f * v0 * (1.f + erff(v0 * 0.70710678118654752f));
                    v1 = 0.5f * v1 * (1.f + erff(v1 * 0.70710678118654752f));
                    *(float2*)&hb[(size_t)m * DFF + n] = make_float2(v0, v1);
                }
            }
        }
}

// ------ expert GEMM2, split-K x2: y_slot = p*(h @ w2^T + b2); grid(6,8,16) ----
__global__ __launch_bounds__(256) void moe_g2_mma(
    const float* __restrict__ w2l, const float* __restrict__ b2l)
{
    const int e  = blockIdx.z >> 1;
    const int ks = blockIdx.z & 1;
    const int ne = g_cnt[e];
    if ((int)(blockIdx.y * 64) >= ne) return;
    float acc[2][4][4] = {};
    mma_gemm_core(g_h + (size_t)e * NTOK * DFF, DFF, nullptr, ne, blockIdx.y,
                  w2l + (size_t)e * NE * DFF, DFF, blockIdx.x,
                  ks * (DFF / 2), DFF / 32, acc);
    const int lane = threadIdx.x & 31, warp = threadIdx.x >> 5;
    const int m0 = blockIdx.y * 64 + (warp >> 2) * 32 + (lane >> 2);
    const int n0 = blockIdx.x * 128 + (warp & 3) * 32 + (lane & 3) * 2;
#pragma unroll
    for (int i = 0; i < 2; i++)
#pragma unroll
        for (int j = 0; j < 4; j++) {
            int n = n0 + j * 8;
            float b0 = ks ? 0.f : b2l[e * NE + n];
            float b1 = ks ? 0.f : b2l[e * NE + n + 1];
#pragma unroll
            for (int half = 0; half < 2; half++) {
                int m = m0 + i * 16 + half * 8;
                if (m < ne) {
                    int tok = g_tok[e * NTOK + m];
                    int sl  = g_slot[e * NTOK + m];
                    float p = g_pw[e * NTOK + m];
                    float* dst = g_yslot + (size_t)(sl * 2 + ks) * NTOK * NE + (size_t)tok * NE;
                    *(float2*)&dst[n] = make_float2(p * (acc[i][j][half * 2 + 0] + b0),
                                                    p * (acc[i][j][half * 2 + 1] + b1));
                }
            }
        }
}

// ---------------- embed ------------------------------------------------------
__global__ void embed_kernel(const int* __restrict__ idx,
                             const float* __restrict__ te,
                             const float* __restrict__ pe) {
    int t = blockIdx.x;
    int id = idx[t];
    int pp = t & (TT - 1);
    for (int c = threadIdx.x; c < NE; c += blockDim.x)
        g_x[t * NE + c] = te[id * NE + c] + pe[pp * NE + c];
}

// ---------------- attention core: grid (B*H=64, 2), 256 thr, dyn smem --------
__global__ __launch_bounds__(256) void attn_kernel() {
    extern __shared__ float sm[];
    float* sq = sm;                 // 32*96
    float* sk = sq + 32 * HD;       // 64*96
    float* sv = sk + 64 * HD;       // 64*96
    float* ss = sv + 64 * HD;       // 32*64
    const int b = blockIdx.x >> 3, h = blockIdx.x & 7;
    const int t0 = blockIdx.y * 32;
    const int base = b * TT;
    const int tid = threadIdx.x;
    const int col0 = h * HD;

    for (int i = tid; i < 64 * HD; i += 256) {
        int t = i / HD, d = i - t * HD;
        sk[i] = g_k[(base + t) * NE + col0 + d];
        sv[i] = g_v[(base + t) * NE + col0 + d];
    }
    for (int i = tid; i < 32 * HD; i += 256) {
        int t = i / HD, d = i - t * HD;
        sq[i] = g_q[(base + t0 + t) * NE + col0 + d];
    }
    __syncthreads();

    const float scale = 0.10206207261596575f;  // 96^-0.5
    for (int e = tid; e < 32 * 64; e += 256) {
        int t = e >> 6, s = e & 63;
        float a = 0.f;
        if (s <= t0 + t) {
            const float* qp = sq + t * HD;
            const float* kp = sk + s * HD;
#pragma unroll 8
            for (int d = 0; d < HD; d++) a += qp[d] * kp[d];
            a *= scale;
        }
        ss[e] = a;
    }
    __syncthreads();

    if (tid < 32) {
        int lim = t0 + tid;
        float m = -1e30f;
        for (int s = 0; s <= lim; s++) m = fmaxf(m, ss[tid * 64 + s]);
        float sum = 0.f;
        for (int s = 0; s < 64; s++) {
            float v = (s <= lim) ? expf(ss[tid * 64 + s] - m) : 0.f;
            ss[tid * 64 + s] = v;
            sum += v;
        }
        float inv = 1.f / sum;
        for (int s = 0; s < 64; s++) ss[tid * 64 + s] *= inv;
    }
    __syncthreads();

    for (int i = tid; i < 32 * HD; i += 256) {
        int t = i / HD, d = i - t * HD;
        const float* ps = ss + t * 64;
        float a = 0.f;
#pragma unroll 8
        for (int s = 0; s < 64; s++) a += ps[s] * sv[s * HD + d];
        g_o[(base + t0 + t) * NE + col0 + d] = a;
    }
}

// ------ residual add + layernorm (+ fused MoE gate logits when mode==1) ------
// mode: 0 none, 1 += g_y + g_y2 then gate, 2 += 4 yslot buffers
__global__ __launch_bounds__(256) void addln_kernel(
    const float* __restrict__ w, const float* __restrict__ bb, int mode,
    const float* __restrict__ gw, const float* __restrict__ gb)
{
    __shared__ float xs[NE];
    const int t = blockIdx.x, tid = threadIdx.x;
    float v[3];
    float s = 0.f, s2 = 0.f;
#pragma unroll
    for (int j = 0; j < 3; j++) {
        int c = tid + j * 256;
        float x = g_x[t * NE + c];
        if (mode == 1) x += g_y[t * NE + c] + g_y2[t * NE + c];
        else if (mode == 2) {
            x += g_yslot[t * NE + c]
               + g_yslot[1 * NTOK * NE + t * NE + c]
               + g_yslot[2 * NTOK * NE + t * NE + c]
               + g_yslot[3 * NTOK * NE + t * NE + c];
        }
        v[j] = x; s += x; s2 += x * x;
    }
#pragma unroll
    for (int o = 16; o; o >>= 1) {
        s  += __shfl_down_sync(0xffffffffu, s,  o);
        s2 += __shfl_down_sync(0xffffffffu, s2, o);
    }
    __shared__ float rs[8], rs2[8], smv[2];
    const int wp = tid >> 5, lane = tid & 31;
    if (lane == 0) { rs[wp] = s; rs2[wp] = s2; }
    __syncthreads();
    if (tid == 0) {
        float a = 0.f, b2 = 0.f;
#pragma unroll
        for (int i = 0; i < 8; i++) { a += rs[i]; b2 += rs2[i]; }
        float mean = a * (1.f / NE);
        float var = b2 * (1.f / NE) - mean * mean;
        smv[0] = mean;
        smv[1] = rsqrtf(var + 1e-5f);
    }
    __syncthreads();
    const float mean = smv[0], r = smv[1];
#pragma unroll
    for (int j = 0; j < 3; j++) {
        int c = tid + j * 256;
        float val = (v[j] - mean) * r * w[c] + bb[c];
        g_x[t * NE + c] = val;
        xs[c] = val;
    }
    if (mode == 1) {   // fused gate logits: warp wp -> expert wp
        __syncthreads();
        const float* gr = gw + wp * NE;
        float a = 0.f;
        for (int c = lane; c < NE; c += 32) a += xs[c] * gr[c];
#pragma unroll
        for (int o = 16; o; o >>= 1) a += __shfl_down_sync(0xffffffffu, a, o);
        if (lane == 0) g_logits[t * NEXP + wp] = a + gb[wp];
    }
}

// ---- top-2 + renorm + per-expert token lists. single block, 512 threads ----
__global__ __launch_bounds__(512) void route_b() {
    __shared__ int scnt[NEXP];
    const int tid = threadIdx.x;
    if (tid < NEXP) scnt[tid] = 0;
    __syncthreads();

    float lg[NEXP];
    float m = -1e30f;
#pragma unroll
    for (int e = 0; e < NEXP; e++) { lg[e] = g_logits[tid * NEXP + e]; m = fmaxf(m, lg[e]); }
#pragma unroll
    for (int e = 0; e < NEXP; e++) lg[e] = expf(lg[e] - m);

    int i0 = 0;
#pragma unroll
    for (int e = 1; e < NEXP; e++) if (lg[e] > lg[i0]) i0 = e;
    int i1 = (i0 == 0) ? 1 : 0;
#pragma unroll
    for (int e = 0; e < NEXP; e++) if (e != i0 && lg[e] > lg[i1]) i1 = e;

    const float inv = 1.f / (lg[i0] + lg[i1]);
    const float p0 = lg[i0] * inv, p1 = lg[i1] * inv;

    int pos0 = atomicAdd(&scnt[i0], 1);
    g_tok[i0 * NTOK + pos0] = tid; g_slot[i0 * NTOK + pos0] = 0; g_pw[i0 * NTOK + pos0] = p0;
    int pos1 = atomicAdd(&scnt[i1], 1);
    g_tok[i1 * NTOK + pos1] = tid; g_slot[i1 * NTOK + pos1] = 1; g_pw[i1 * NTOK + pos1] = p1;

    __syncthreads();
    if (tid < NEXP) g_cnt[tid] = scnt[tid];
}

// ---------------- LM head: logits = x @ lm_w^T + lm_b ------------------------
__global__ __launch_bounds__(128) void lm_kernel(
    const float* __restrict__ lw, const float* __restrict__ lb,
    float* __restrict__ out)
{
    __shared__ float xr[NE];
    const int t = blockIdx.x, tid = threadIdx.x;
    for (int c = tid; c < NE; c += 128) xr[c] = g_x[t * NE + c];
    __syncthreads();
    if (tid < NVOCAB) {
        const float* wr = lw + (size_t)tid * NE;
        float a = lb[tid];
#pragma unroll 8
        for (int c = 0; c < NE; c++) a += xr[c] * wr[c];
        out[t * NVOCAB + tid] = a;
    }
}

// ---------------- launch -----------------------------------------------------
extern "C" void kernel_launch(void* const* d_in, const int* in_sizes, int n_in,
                              void* d_out, int out_size) {
    (void)in_sizes; (void)n_in; (void)out_size;
    const int*   idx     = (const int*)  d_in[0];
    const float* tok_emb = (const float*)d_in[1];
    const float* pos_emb = (const float*)d_in[2];
    const float* wq      = (const float*)d_in[3];
    const float* wk      = (const float*)d_in[4];
    const float* wv      = (const float*)d_in[5];
    const float* wproj   = (const float*)d_in[6];
    const float* bproj   = (const float*)d_in[7];
    const float* gate_w  = (const float*)d_in[8];
    const float* gate_b  = (const float*)d_in[9];
    const float* w1      = (const float*)d_in[10];
    const float* b1      = (const float*)d_in[11];
    const float* w2      = (const float*)d_in[12];
    const float* b2      = (const float*)d_in[13];
    const float* ln1_w   = (const float*)d_in[14];
    const float* ln1_b   = (const float*)d_in[15];
    const float* ln2_w   = (const float*)d_in[16];
    const float* ln2_b   = (const float*)d_in[17];
    const float* lnf_w   = (const float*)d_in[18];
    const float* lnf_b   = (const float*)d_in[19];
    const float* lm_w    = (const float*)d_in[20];
    const float* lm_b    = (const float*)d_in[21];
    float* out = (float*)d_out;

    const int ATTN_SMEM = (32 * HD + 64 * HD + 64 * HD + 32 * 64) * 4;  // 69632 B
    cudaFuncSetAttribute(attn_kernel, cudaFuncAttributeMaxDynamicSharedMemorySize, ATTN_SMEM);
    cudaFuncSetAttribute(qkv_mma,    cudaFuncAttributeMaxDynamicSharedMemorySize, GEMM_SMEM);
    cudaFuncSetAttribute(proj_mma,   cudaFuncAttributeMaxDynamicSharedMemorySize, GEMM_SMEM);
    cudaFuncSetAttribute(moe_g1_mma, cudaFuncAttributeMaxDynamicSharedMemorySize, GEMM_SMEM);
    cudaFuncSetAttribute(moe_g2_mma, cudaFuncAttributeMaxDynamicSharedMemorySize, GEMM_SMEM);

    embed_kernel<<<NTOK, 256>>>(idx, tok_emb, pos_emb);

    for (int l = 0; l < NLAYER; l++) {
        const size_t offW  = (size_t)l * NH * HD * NE;      // 589824
        const size_t offM1 = (size_t)l * NEXP * DFF * NE;   // w1/w2 per layer
        qkv_mma<<<dim3(6, 8, 3), 256, GEMM_SMEM>>>(wq + offW, wk + offW, wv + offW);
        attn_kernel<<<dim3(64, 2), 256, ATTN_SMEM>>>();
        proj_mma<<<dim3(6, 8, 2), 256, GEMM_SMEM>>>(wproj + offW, bproj + (size_t)l * NE);
        // post-norm + fused gate logits
        addln_kernel<<<NTOK, 256>>>(ln1_w + (size_t)l * NE, ln1_b + (size_t)l * NE, 1,
                                    gate_w + (size_t)l * NEXP * NE,
                                    gate_b + (size_t)l * NEXP);
        route_b<<<1, 512>>>();
        moe_g1_mma<<<dim3(24, 8, NEXP), 256, GEMM_SMEM>>>(w1 + offM1, b1 + (size_t)l * NEXP * DFF);
        moe_g2_mma<<<dim3(6, 8, NEXP * 2), 256, GEMM_SMEM>>>(w2 + offM1, b2 + (size_t)l * NEXP * NE);
        addln_kernel<<<NTOK, 256>>>(ln2_w + (size_t)l * NE, ln2_b + (size_t)l * NE, 2,
                                    nullptr, nullptr);
    }

    addln_kernel<<<NTOK, 256>>>(lnf_w, lnf_b, 0, nullptr, nullptr);
    lm_kernel<<<NTOK, 128>>>(lm_w, lm_b, out);
}

// round 12
// speedup vs baseline: 2.5734x; 1.0023x over previous
#include <cuda_runtime.h>
#include <cuda_bf16.h>
#include <math.h>

#define NTOK   512          // B*T = 8*64
#define NE     768          // n_embd
#define NH     8            // heads
#define HD     96           // head dim
#define DFF    3072
#define NEXP   8
#define NLAYER 12
#define NVOCAB 99
#define TT     64           // seq len

#define GEMM_SMEM 73728     // 4-slot ring: A 4*6144B + B 4*12288B

// ---------------- scratch (static device globals; no allocation) -------------
__device__ float g_x[NTOK * NE];
__device__ float g_q[NTOK * NE];
__device__ float g_k[NTOK * NE];
__device__ float g_v[NTOK * NE];
__device__ float g_o[NTOK * NE];
__device__ float g_y[NTOK * NE];
__device__ float g_y2[NTOK * NE];                  // proj split-K partial
__device__ float g_h[(size_t)NEXP * NTOK * DFF];   // ~50 MB expert hidden
__device__ float g_yslot[4 * NTOK * NE];           // [slot*2 + ksplit]
__device__ float g_logits[NTOK * NEXP];
__device__ int   g_cnt[NEXP];
__device__ int   g_tok[NEXP * NTOK];
__device__ int   g_slot[NEXP * NTOK];
__device__ float g_pw[NEXP * NTOK];

// ---------------- small helpers ----------------------------------------------
__device__ __forceinline__ unsigned su32(const void* p) {
    return (unsigned)__cvta_generic_to_shared(p);
}

__device__ __forceinline__ void ldsm4(unsigned* r, unsigned addr) {
    asm volatile("ldmatrix.sync.aligned.m8n8.x4.shared.b16 {%0,%1,%2,%3}, [%4];"
        : "=r"(r[0]), "=r"(r[1]), "=r"(r[2]), "=r"(r[3]) : "r"(addr));
}

__device__ __forceinline__ void mma16816(float* c, const unsigned* a, const unsigned* b) {
    asm volatile(
        "mma.sync.aligned.m16n8k16.row.col.f32.bf16.bf16.f32 "
        "{%0,%1,%2,%3}, {%4,%5,%6,%7}, {%8,%9}, {%0,%1,%2,%3};\n"
        : "+f"(c[0]), "+f"(c[1]), "+f"(c[2]), "+f"(c[3])
        : "r"(a[0]), "r"(a[1]), "r"(a[2]), "r"(a[3]), "r"(b[0]), "r"(b[1]));
}

// split 2 fp32 into packed bf16 hi pair + bf16 lo pair (lo = x - float(hi))
__device__ __forceinline__ void split2(float x0, float x1, unsigned& hi, unsigned& lo) {
    __nv_bfloat162 h = __floats2bfloat162_rn(x0, x1);
    float2 hf = __bfloat1622float2(h);
    __nv_bfloat162 l = __floats2bfloat162_rn(x0 - hf.x, x1 - hf.y);
    hi = *reinterpret_cast<unsigned*>(&h);
    lo = *reinterpret_cast<unsigned*>(&l);
}

// stage one 16-k tile (regs -> smem slice). Layout per slice (bf16 elems):
//   A: slice*3072 + part*1536 + row*24 + k      (rows 0..63)
//   B: 12288 + slice*6144 + part*3072 + row*24 + k  (rows 0..127)
__device__ __forceinline__ void stage_tile(
    __nv_bfloat16* sm_bf, int slice, int ar, int ak, int br, int bk,
    float4 av, float4 bv0, float4 bv1)
{
    unsigned h0, l0, h1, l1;
    split2(av.x, av.y, h0, l0); split2(av.z, av.w, h1, l1);
    __nv_bfloat16* A0 = sm_bf + slice * 3072 + ar * 24 + ak;
    *(uint2*)A0          = make_uint2(h0, h1);
    *(uint2*)(A0 + 1536) = make_uint2(l0, l1);
    unsigned p0h, p0l, p1h, p1l, p2h, p2l, p3h, p3l;
    split2(bv0.x, bv0.y, p0h, p0l); split2(bv0.z, bv0.w, p1h, p1l);
    split2(bv1.x, bv1.y, p2h, p2l); split2(bv1.z, bv1.w, p3h, p3l);
    __nv_bfloat16* B0 = sm_bf + 12288 + slice * 6144 + br * 24 + bk;
    *(uint4*)B0          = make_uint4(p0h, p1h, p2h, p3h);
    *(uint4*)(B0 + 3072) = make_uint4(p0l, p1l, p2l, p3l);
}

// ---------------- tensor-core GEMM core: C = A @ W^T (fp32-in/out, bf16x3) ----
// Block tile 64(M) x 128(N), BK=16, 4-slot smem ring (barrier every 2 tiles),
// 256 threads = 8 warps (2M x 4N), warp tile 32x32.
// A: [mrows, lda] fp32 row-major (optional row gather). W rows: ldw stride.
// Computes over K range [koff, koff + nt*16). Requires nt >= 4.
__device__ __forceinline__ void mma_gemm_core(
    const float* __restrict__ Abase, int lda,
    const int* __restrict__ rowmap, int mrows, int mTile,
    const float* __restrict__ W, int ldw, int nTile, int koff, int nt,
    float (&acc)[2][4][4])
{
    extern __shared__ __align__(16) __nv_bfloat16 sm_bf[];

    const int tx = threadIdx.x;
    const int warp = tx >> 5, lane = tx & 31;
    const int wm = (warp >> 2) * 32;   // warp M offset
    const int wn = (warp & 3) * 32;    // warp N offset

    // staging assignments
    const int ar = tx >> 2;            // A row 0..63
    const int ak = (tx & 3) << 2;      // k offset {0,4,8,12}
    const int grow = mTile * 64 + ar;
    const float* aptr = nullptr;
    if (grow < mrows) {
        int src = rowmap ? rowmap[grow] : grow;
        aptr = Abase + (size_t)src * lda + koff + ak;
    }
    const int br = tx >> 1;            // B row 0..127
    const int bk = (tx & 1) << 3;      // k offset {0,8}
    const float* bptr = W + (size_t)(nTile * 128 + br) * ldw + koff + bk;

    // ldmatrix lane base addresses (slice 0, part hi)
    const unsigned aB = su32(sm_bf + (wm + (lane & 15)) * 24 + (lane >> 4) * 8);
    const int bn = wn + (lane & 7) + ((lane >> 1) & 8);
    const unsigned bB = su32(sm_bf + 12288 + bn * 24 + (lane & 8));
    // byte strides: A slice 6144, part 3072; B slice 12288, part 6144; +16 rows = 768

    const float4 zf4 = make_float4(0.f, 0.f, 0.f, 0.f);

    // prologue: stage tiles 0,1 into slices 0,1; prefetch tiles 2,3 into regs
    float4 avA, bv0A, bv1A, avB, bv0B, bv1B;
    avA  = aptr ? *(const float4*)aptr : zf4;
    bv0A = *(const float4*)bptr;  bv1A = *(const float4*)(bptr + 4);
    avB  = aptr ? *(const float4*)(aptr + 16) : zf4;
    bv0B = *(const float4*)(bptr + 16); bv1B = *(const float4*)(bptr + 20);
    stage_tile(sm_bf, 0, ar, ak, br, bk, avA, bv0A, bv1A);
    stage_tile(sm_bf, 1, ar, ak, br, bk, avB, bv0B, bv1B);
    avA  = aptr ? *(const float4*)(aptr + 32) : zf4;
    bv0A = *(const float4*)(bptr + 32); bv1A = *(const float4*)(bptr + 36);
    avB  = aptr ? *(const float4*)(aptr + 48) : zf4;
    bv0B = *(const float4*)(bptr + 48); bv1B = *(const float4*)(bptr + 52);
    __syncthreads();

    for (int t = 0; t < nt; t++) {
        const int s = t & 3;
        const unsigned aHi = aB + s * 6144;
        const unsigned bHi = bB + s * 12288;
        unsigned Ah[2][4], Al[2][4], Bh[2][4], Bl[2][4];
        ldsm4(Ah[0], aHi);          ldsm4(Ah[1], aHi + 768);
        ldsm4(Al[0], aHi + 3072);   ldsm4(Al[1], aHi + 3072 + 768);
        ldsm4(Bh[0], bHi);          ldsm4(Bh[1], bHi + 768);
        ldsm4(Bl[0], bHi + 6144);   ldsm4(Bl[1], bHi + 6144 + 768);

        // stage tile t+2 into slice (t+2)&3 (not in use this pair); prefetch t+4
        if (t + 2 < nt) {
            if (t & 1) {
                stage_tile(sm_bf, (t + 2) & 3, ar, ak, br, bk, avB, bv0B, bv1B);
                if (t + 4 < nt) {
                    const int ko = (t + 4) * 16;
                    avB  = aptr ? *(const float4*)(aptr + ko) : zf4;
                    bv0B = *(const float4*)(bptr + ko);
                    bv1B = *(const float4*)(bptr + ko + 4);
                }
            } else {
                stage_tile(sm_bf, (t + 2) & 3, ar, ak, br, bk, avA, bv0A, bv1A);
                if (t + 4 < nt) {
                    const int ko = (t + 4) * 16;
                    avA  = aptr ? *(const float4*)(aptr + ko) : zf4;
                    bv0A = *(const float4*)(bptr + ko);
                    bv1A = *(const float4*)(bptr + ko + 4);
                }
            }
        }

#pragma unroll
        for (int i = 0; i < 2; i++)
#pragma unroll
            for (int j = 0; j < 4; j++) {
                const unsigned* bh = &Bh[j >> 1][(j & 1) * 2];
                const unsigned* bl = &Bl[j >> 1][(j & 1) * 2];
                mma16816(acc[i][j], Ah[i], bh);   // hi*hi
                mma16816(acc[i][j], Ah[i], bl);   // hi*lo
                mma16816(acc[i][j], Al[i], bh);   // lo*hi
            }
        if (t & 1) __syncthreads();   // barrier every 2 tiles
    }
}

// ---------------- fused QKV: grid (6, 8, 3) -----------------------------------
__global__ __launch_bounds__(256) void qkv_mma(
    const float* __restrict__ wq, const float* __restrict__ wk,
    const float* __restrict__ wv)
{
    const float* W = (blockIdx.z == 0) ? wq : (blockIdx.z == 1) ? wk : wv;
    float* out = (blockIdx.z == 0) ? g_q : (blockIdx.z == 1) ? g_k : g_v;
    float acc[2][4][4] = {};
    mma_gemm_core(g_x, NE, nullptr, NTOK, blockIdx.y, W, NE, blockIdx.x, 0, NE / 16, acc);
    const int lane = threadIdx.x & 31, warp = threadIdx.x >> 5;
    const int m0 = blockIdx.y * 64 + (warp >> 2) * 32 + (lane >> 2);
    const int n0 = blockIdx.x * 128 + (warp & 3) * 32 + (lane & 3) * 2;
#pragma unroll
    for (int i = 0; i < 2; i++)
#pragma unroll
        for (int j = 0; j < 4; j++) {
            int m = m0 + i * 16, n = n0 + j * 8;
            *(float2*)&out[m * NE + n]       = make_float2(acc[i][j][0], acc[i][j][1]);
            *(float2*)&out[(m + 8) * NE + n] = make_float2(acc[i][j][2], acc[i][j][3]);
        }
}

// ---------------- output projection, split-K x2: grid (6, 8, 2) ---------------
__global__ __launch_bounds__(256) void proj_mma(
    const float* __restrict__ wp, const float* __restrict__ bp)
{
    const int ks = blockIdx.z;
    float acc[2][4][4] = {};
    mma_gemm_core(g_o, NE, nullptr, NTOK, blockIdx.y, wp, NE, blockIdx.x,
                  ks * (NE / 2), NE / 32, acc);
    float* out = ks ? g_y2 : g_y;
    const int lane = threadIdx.x & 31, warp = threadIdx.x >> 5;
    const int m0 = blockIdx.y * 64 + (warp >> 2) * 32 + (lane >> 2);
    const int n0 = blockIdx.x * 128 + (warp & 3) * 32 + (lane & 3) * 2;
#pragma unroll
    for (int i = 0; i < 2; i++)
#pragma unroll
        for (int j = 0; j < 4; j++) {
            int m = m0 + i * 16, n = n0 + j * 8;
            float b0 = ks ? 0.f : bp[n], b1 = ks ? 0.f : bp[n + 1];
            *(float2*)&out[m * NE + n]       = make_float2(acc[i][j][0] + b0, acc[i][j][1] + b1);
            *(float2*)&out[(m + 8) * NE + n] = make_float2(acc[i][j][2] + b0, acc[i][j][3] + b1);
        }
}

// ---------------- expert GEMM1: h = gelu(x_gather @ w1^T + b1); grid(24,8,8) --
__global__ __launch_bounds__(256) void moe_g1_mma(
    const float* __restrict__ w1l, const float* __restrict__ b1l)
{
    const int e = blockIdx.z;
    const int ne = g_cnt[e];
    if ((int)(blockIdx.y * 64) >= ne) return;
    float acc[2][4][4] = {};
    mma_gemm_core(g_x, NE, g_tok + e * NTOK, ne, blockIdx.y,
                  w1l + (size_t)e * DFF * NE, NE, blockIdx.x, 0, NE / 16, acc);
    const int lane = threadIdx.x & 31, warp = threadIdx.x >> 5;
    const int m0 = blockIdx.y * 64 + (warp >> 2) * 32 + (lane >> 2);
    const int n0 = blockIdx.x * 128 + (warp & 3) * 32 + (lane & 3) * 2;
    float* hb = g_h + (size_t)e * NTOK * DFF;
#pragma unroll
    for (int i = 0; i < 2; i++)
#pragma unroll
        for (int j = 0; j < 4; j++) {
            int n = n0 + j * 8;
            float b0 = b1l[e * DFF + n], b1 = b1l[e * DFF + n + 1];
#pragma unroll
            for (int half = 0; half < 2; half++) {
                int m = m0 + i * 16 + half * 8;
                if (m < ne) {
                    float v0 = acc[i][j][half * 2 + 0] + b0;
                    float v1 = acc[i][j][half * 2 + 1] + b1;
                    v0 = 0.5f * v0 * (1.f + erff(v0 * 0.70710678118654752f));
                    v1 = 0.5f * v1 * (1.f + erff(v1 * 0.70710678118654752f));
                    *(float2*)&hb[(size_t)m * DFF + n] = make_float2(v0, v1);
                }
            }
        }
}

// ------ expert GEMM2, split-K x2: y_slot = p*(h @ w2^T + b2); grid(6,8,16) ----
__global__ __launch_bounds__(256) void moe_g2_mma(
    const float* __restrict__ w2l, const float* __restrict__ b2l)
{
    const int e  = blockIdx.z >> 1;
    const int ks = blockIdx.z & 1;
    const int ne = g_cnt[e];
    if ((int)(blockIdx.y * 64) >= ne) return;
    float acc[2][4][4] = {};
    mma_gemm_core(g_h + (size_t)e * NTOK * DFF, DFF, nullptr, ne, blockIdx.y,
                  w2l + (size_t)e * NE * DFF, DFF, blockIdx.x,
                  ks * (DFF / 2), DFF / 32, acc);
    const int lane = threadIdx.x & 31, warp = threadIdx.x >> 5;
    const int m0 = blockIdx.y * 64 + (warp >> 2) * 32 + (lane >> 2);
    const int n0 = blockIdx.x * 128 + (warp & 3) * 32 + (lane & 3) * 2;
#pragma unroll
    for (int i = 0; i < 2; i++)
#pragma unroll
        for (int j = 0; j < 4; j++) {
            int n = n0 + j * 8;
            float b0 = ks ? 0.f : b2l[e * NE + n];
            float b1 = ks ? 0.f : b2l[e * NE + n + 1];
#pragma unroll
            for (int half = 0; half < 2; half++) {
                int m = m0 + i * 16 + half * 8;
                if (m < ne) {
                    int tok = g_tok[e * NTOK + m];
                    int sl  = g_slot[e * NTOK + m];
                    float p = g_pw[e * NTOK + m];
                    float* dst = g_yslot + (size_t)(sl * 2 + ks) * NTOK * NE + (size_t)tok * NE;
                    *(float2*)&dst[n] = make_float2(p * (acc[i][j][half * 2 + 0] + b0),
                                                    p * (acc[i][j][half * 2 + 1] + b1));
                }
            }
        }
}

// ---------------- embed ------------------------------------------------------
__global__ void embed_kernel(const int* __restrict__ idx,
                             const float* __restrict__ te,
                             const float* __restrict__ pe) {
    int t = blockIdx.x;
    int id = idx[t];
    int pp = t & (TT - 1);
    for (int c = threadIdx.x; c < NE; c += blockDim.x)
        g_x[t * NE + c] = te[id * NE + c] + pe[pp * NE + c];
}

// ---------------- attention core: grid (B*H=64, 2), 256 thr, dyn smem --------
__global__ __launch_bounds__(256) void attn_kernel() {
    extern __shared__ float sm[];
    float* sq = sm;                 // 32*96
    float* sk = sq + 32 * HD;       // 64*96
    float* sv = sk + 64 * HD;       // 64*96
    float* ss = sv + 64 * HD;       // 32*64
    const int b = blockIdx.x >> 3, h = blockIdx.x & 7;
    const int t0 = blockIdx.y * 32;
    const int base = b * TT;
    const int tid = threadIdx.x;
    const int col0 = h * HD;

    for (int i = tid; i < 64 * HD; i += 256) {
        int t = i / HD, d = i - t * HD;
        sk[i] = g_k[(base + t) * NE + col0 + d];
        sv[i] = g_v[(base + t) * NE + col0 + d];
    }
    for (int i = tid; i < 32 * HD; i += 256) {
        int t = i / HD, d = i - t * HD;
        sq[i] = g_q[(base + t0 + t) * NE + col0 + d];
    }
    __syncthreads();

    const float scale = 0.10206207261596575f;  // 96^-0.5
    for (int e = tid; e < 32 * 64; e += 256) {
        int t = e >> 6, s = e & 63;
        float a = 0.f;
        if (s <= t0 + t) {
            const float* qp = sq + t * HD;
            const float* kp = sk + s * HD;
#pragma unroll 8
            for (int d = 0; d < HD; d++) a += qp[d] * kp[d];
            a *= scale;
        }
        ss[e] = a;
    }
    __syncthreads();

    if (tid < 32) {
        int lim = t0 + tid;
        float m = -1e30f;
        for (int s = 0; s <= lim; s++) m = fmaxf(m, ss[tid * 64 + s]);
        float sum = 0.f;
        for (int s = 0; s < 64; s++) {
            float v = (s <= lim) ? expf(ss[tid * 64 + s] - m) : 0.f;
            ss[tid * 64 + s] = v;
            sum += v;
        }
        float inv = 1.f / sum;
        for (int s = 0; s < 64; s++) ss[tid * 64 + s] *= inv;
    }
    __syncthreads();

    for (int i = tid; i < 32 * HD; i += 256) {
        int t = i / HD, d = i - t * HD;
        const float* ps = ss + t * 64;
        float a = 0.f;
#pragma unroll 8
        for (int s = 0; s < 64; s++) a += ps[s] * sv[s * HD + d];
        g_o[(base + t0 + t) * NE + col0 + d] = a;
    }
}

// ------ residual add + layernorm (+ fused MoE gate logits when mode==1) ------
// mode: 0 none, 1 += g_y + g_y2 then gate, 2 += 4 yslot buffers
__global__ __launch_bounds__(256) void addln_kernel(
    const float* __restrict__ w, const float* __restrict__ bb, int mode,
    const float* __restrict__ gw, const float* __restrict__ gb)
{
    __shared__ float xs[NE];
    const int t = blockIdx.x, tid = threadIdx.x;
    float v[3];
    float s = 0.f, s2 = 0.f;
#pragma unroll
    for (int j = 0; j < 3; j++) {
        int c = tid + j * 256;
        float x = g_x[t * NE + c];
        if (mode == 1) x += g_y[t * NE + c] + g_y2[t * NE + c];
        else if (mode == 2) {
            x += g_yslot[t * NE + c]
               + g_yslot[1 * NTOK * NE + t * NE + c]
               + g_yslot[2 * NTOK * NE + t * NE + c]
               + g_yslot[3 * NTOK * NE + t * NE + c];
        }
        v[j] = x; s += x; s2 += x * x;
    }
#pragma unroll
    for (int o = 16; o; o >>= 1) {
        s  += __shfl_down_sync(0xffffffffu, s,  o);
        s2 += __shfl_down_sync(0xffffffffu, s2, o);
    }
    __shared__ float rs[8], rs2[8], smv[2];
    const int wp = tid >> 5, lane = tid & 31;
    if (lane == 0) { rs[wp] = s; rs2[wp] = s2; }
    __syncthreads();
    if (tid == 0) {
        float a = 0.f, b2 = 0.f;
#pragma unroll
        for (int i = 0; i < 8; i++) { a += rs[i]; b2 += rs2[i]; }
        float mean = a * (1.f / NE);
        float var = b2 * (1.f / NE) - mean * mean;
        smv[0] = mean;
        smv[1] = rsqrtf(var + 1e-5f);
    }
    __syncthreads();
    const float mean = smv[0], r = smv[1];
#pragma unroll
    for (int j = 0; j < 3; j++) {
        int c = tid + j * 256;
        float val = (v[j] - mean) * r * w[c] + bb[c];
        g_x[t * NE + c] = val;
        xs[c] = val;
    }
    if (mode == 1) {   // fused gate logits: warp wp -> expert wp
        __syncthreads();
        const float* gr = gw + wp * NE;
        float a = 0.f;
        for (int c = lane; c < NE; c += 32) a += xs[c] * gr[c];
#pragma unroll
        for (int o = 16; o; o >>= 1) a += __shfl_down_sync(0xffffffffu, a, o);
        if (lane == 0) g_logits[t * NEXP + wp] = a + gb[wp];
    }
}

// ---- top-2 + renorm + per-expert token lists. single block, 512 threads ----
__global__ __launch_bounds__(512) void route_b() {
    __shared__ int scnt[NEXP];
    const int tid = threadIdx.x;
    if (tid < NEXP) scnt[tid] = 0;
    __syncthreads();

    float lg[NEXP];
    float m = -1e30f;
#pragma unroll
    for (int e = 0; e < NEXP; e++) { lg[e] = g_logits[tid * NEXP + e]; m = fmaxf(m, lg[e]); }
#pragma unroll
    for (int e = 0; e < NEXP; e++) lg[e] = expf(lg[e] - m);

    int i0 = 0;
#pragma unroll
    for (int e = 1; e < NEXP; e++) if (lg[e] > lg[i0]) i0 = e;
    int i1 = (i0 == 0) ? 1 : 0;
#pragma unroll
    for (int e = 0; e < NEXP; e++) if (e != i0 && lg[e] > lg[i1]) i1 = e;

    const float inv = 1.f / (lg[i0] + lg[i1]);
    const float p0 = lg[i0] * inv, p1 = lg[i1] * inv;

    int pos0 = atomicAdd(&scnt[i0], 1);
    g_tok[i0 * NTOK + pos0] = tid; g_slot[i0 * NTOK + pos0] = 0; g_pw[i0 * NTOK + pos0] = p0;
    int pos1 = atomicAdd(&scnt[i1], 1);
    g_tok[i1 * NTOK + pos1] = tid; g_slot[i1 * NTOK + pos1] = 1; g_pw[i1 * NTOK + pos1] = p1;

    __syncthreads();
    if (tid < NEXP) g_cnt[tid] = scnt[tid];
}

// ---------------- LM head: logits = x @ lm_w^T + lm_b ------------------------
__global__ __launch_bounds__(128) void lm_kernel(
    const float* __restrict__ lw, const float* __restrict__ lb,
    float* __restrict__ out)
{
    __shared__ float xr[NE];
    const int t = blockIdx.x, tid = threadIdx.x;
    for (int c = tid; c < NE; c += 128) xr[c] = g_x[t * NE + c];
    __syncthreads();
    if (tid < NVOCAB) {
        const float* wr = lw + (size_t)tid * NE;
        float a = lb[tid];
#pragma unroll 8
        for (int c = 0; c < NE; c++) a += xr[c] * wr[c];
        out[t * NVOCAB + tid] = a;
    }
}

// ---------------- launch -----------------------------------------------------
extern "C" void kernel_launch(void* const* d_in, const int* in_sizes, int n_in,
                              void* d_out, int out_size) {
    (void)in_sizes; (void)n_in; (void)out_size;
    const int*   idx     = (const int*)  d_in[0];
    const float* tok_emb = (const float*)d_in[1];
    const float* pos_emb = (const float*)d_in[2];
    const float* wq      = (const float*)d_in[3];
    const float* wk      = (const float*)d_in[4];
    const float* wv      = (const float*)d_in[5];
    const float* wproj   = (const float*)d_in[6];
    const float* bproj   = (const float*)d_in[7];
    const float* gate_w  = (const float*)d_in[8];
    const float* gate_b  = (const float*)d_in[9];
    const float* w1      = (const float*)d_in[10];
    const float* b1      = (const float*)d_in[11];
    const float* w2      = (const float*)d_in[12];
    const float* b2      = (const float*)d_in[13];
    const float* ln1_w   = (const float*)d_in[14];
    const float* ln1_b   = (const float*)d_in[15];
    const float* ln2_w   = (const float*)d_in[16];
    const float* ln2_b   = (const float*)d_in[17];
    const float* lnf_w   = (const float*)d_in[18];
    const float* lnf_b   = (const float*)d_in[19];
    const float* lm_w    = (const float*)d_in[20];
    const float* lm_b    = (const float*)d_in[21];
    float* out = (float*)d_out;

    const int ATTN_SMEM = (32 * HD + 64 * HD + 64 * HD + 32 * 64) * 4;  // 69632 B
    cudaFuncSetAttribute(attn_kernel, cudaFuncAttributeMaxDynamicSharedMemorySize, ATTN_SMEM);
    cudaFuncSetAttribute(qkv_mma,    cudaFuncAttributeMaxDynamicSharedMemorySize, GEMM_SMEM);
    cudaFuncSetAttribute(proj_mma,   cudaFuncAttributeMaxDynamicSharedMemorySize, GEMM_SMEM);
    cudaFuncSetAttribute(moe_g1_mma, cudaFuncAttributeMaxDynamicSharedMemorySize, GEMM_SMEM);
    cudaFuncSetAttribute(moe_g2_mma, cudaFuncAttributeMaxDynamicSharedMemorySize, GEMM_SMEM);

    embed_kernel<<<NTOK, 256>>>(idx, tok_emb, pos_emb);

    for (int l = 0; l < NLAYER; l++) {
        const size_t offW  = (size_t)l * NH * HD * NE;      // 589824
        const size_t offM1 = (size_t)l * NEXP * DFF * NE;   // w1/w2 per layer
        qkv_mma<<<dim3(6, 8, 3), 256, GEMM_SMEM>>>(wq + offW, wk + offW, wv + offW);
        attn_kernel<<<dim3(64, 2), 256, ATTN_SMEM>>>();
        proj_mma<<<dim3(6, 8, 2), 256, GEMM_SMEM>>>(wproj + offW, bproj + (size_t)l * NE);
        // post-norm + fused gate logits
        addln_kernel<<<NTOK, 256>>>(ln1_w + (size_t)l * NE, ln1_b + (size_t)l * NE, 1,
                                    gate_w + (size_t)l * NEXP * NE,
                                    gate_b + (size_t)l * NEXP);
        route_b<<<1, 512>>>();
        moe_g1_mma<<<dim3(24, 8, NEXP), 256, GEMM_SMEM>>>(w1 + offM1, b1 + (size_t)l * NEXP * DFF);
        moe_g2_mma<<<dim3(6, 8, NEXP * 2), 256, GEMM_SMEM>>>(w2 + offM1, b2 + (size_t)l * NEXP * NE);
        addln_kernel<<<NTOK, 256>>>(ln2_w + (size_t)l * NE, ln2_b + (size_t)l * NE, 2,
                                    nullptr, nullptr);
    }

    addln_kernel<<<NTOK, 256>>>(lnf_w, lnf_b, 0, nullptr, nullptr);
    lm_kernel<<<NTOK, 128>>>(lm_w, lm_b, out);
}